// round 8
// baseline (speedup 1.0000x reference)
#include <cuda_runtime.h>
#include <cstdint>
#include <math.h>

#define B_ 2
#define S_ 2048
#define E_ 2048
#define H_ 32
#define D_ 64
#define M_ (B_*S_)
#define SCALE_ 0.125f

// ---------------- scratch ----------------
static __device__ __align__(128) int8_t g_x1[(size_t)M_ * E_];
static __device__ __align__(128) int8_t g_x2[(size_t)M_ * E_];
static __device__ __align__(128) float  g_sx[M_];
static __device__ __align__(128) int8_t g_a1[(size_t)M_ * E_];
static __device__ __align__(128) int8_t g_a2[(size_t)M_ * E_];
static __device__ __align__(128) float  g_sa[M_];
static __device__ __align__(128) float  g_attn[(size_t)M_ * E_];

static __device__ __align__(128) int8_t g_wq1[(size_t)E_ * E_];
static __device__ __align__(128) int8_t g_wq2[(size_t)E_ * E_];
static __device__ __align__(128) float  g_swq[E_];
static __device__ __align__(128) int8_t g_wk1[(size_t)E_ * E_];
static __device__ __align__(128) int8_t g_wk2[(size_t)E_ * E_];
static __device__ __align__(128) float  g_swk[E_];
static __device__ __align__(128) int8_t g_wv1[(size_t)E_ * E_];
static __device__ __align__(128) int8_t g_wv2[(size_t)E_ * E_];
static __device__ __align__(128) float  g_swv[E_];
static __device__ __align__(128) int8_t g_wo1[(size_t)E_ * E_];
static __device__ __align__(128) int8_t g_wo2[(size_t)E_ * E_];
static __device__ __align__(128) float  g_swo[E_];

static __device__ __align__(128) float g_qf[(size_t)M_ * E_];
static __device__ __align__(128) float g_kf[(size_t)M_ * E_];
static __device__ __align__(128) float g_vf[(size_t)M_ * E_];

static __device__ __align__(128) int8_t g_q1[(size_t)M_ * E_];
static __device__ __align__(128) int8_t g_q2[(size_t)M_ * E_];
static __device__ __align__(128) int8_t g_k1[(size_t)M_ * E_];
static __device__ __align__(128) int8_t g_k2[(size_t)M_ * E_];
static __device__ __align__(128) int8_t g_vt1[(size_t)M_ * E_];
static __device__ __align__(128) int8_t g_vt2[(size_t)M_ * E_];
static __device__ __align__(128) float  g_sq[(size_t)H_ * M_];
static __device__ __align__(128) float  g_sk[(size_t)H_ * M_];
static __device__ __align__(128) float  g_sv[(size_t)H_ * M_];

// ---------------- helpers ----------------
__device__ __forceinline__ uint32_t smem_u32(const void* p) {
    uint32_t a;
    asm("{ .reg .u64 t; cvta.to.shared.u64 t, %1; cvt.u32.u64 %0, t; }"
        : "=r"(a) : "l"(p));
    return a;
}
__device__ __forceinline__ void cp_async16(uint32_t saddr, const void* gaddr) {
    asm volatile("cp.async.cg.shared.global [%0], [%1], 16;\n"
                 :: "r"(saddr), "l"(gaddr));
}
#define CP_COMMIT() asm volatile("cp.async.commit_group;\n" ::: "memory")
#define CP_WAIT0()  asm volatile("cp.async.wait_group 0;\n" ::: "memory")
#define CP_WAIT1()  asm volatile("cp.async.wait_group 1;\n" ::: "memory")
#define CP_WAIT2()  asm volatile("cp.async.wait_group 2;\n" ::: "memory")

__device__ __forceinline__ void ldm_x4(uint32_t* r, uint32_t addr) {
    asm volatile("ldmatrix.sync.aligned.m8n8.x4.shared.b16 {%0,%1,%2,%3}, [%4];"
                 : "=r"(r[0]), "=r"(r[1]), "=r"(r[2]), "=r"(r[3]) : "r"(addr));
}
__device__ __forceinline__ void mma_s8(int* d, const uint32_t* a,
                                       uint32_t b0, uint32_t b1) {
    asm volatile(
        "mma.sync.aligned.m16n8k32.row.col.s32.s8.s8.s32 "
        "{%0,%1,%2,%3}, {%4,%5,%6,%7}, {%8,%9}, {%0,%1,%2,%3};"
        : "+r"(d[0]), "+r"(d[1]), "+r"(d[2]), "+r"(d[3])
        : "r"(a[0]), "r"(a[1]), "r"(a[2]), "r"(a[3]), "r"(b0), "r"(b1));
}
__device__ __forceinline__ void sts16(uint32_t addr, uint16_t v) {
    asm volatile("st.shared.u16 [%0], %1;" :: "r"(addr), "h"(v) : "memory");
}
__device__ __forceinline__ float ex2(float x) {
    float y; asm("ex2.approx.f32 %0, %1;" : "=f"(y) : "f"(x)); return y;
}

// ---------------------------------------------------------------------------
// Row-wise two-level int8 quantization over 2048-col rows.
// ---------------------------------------------------------------------------
__global__ __launch_bounds__(256) void rowquant(
    const float* __restrict__ x, int8_t* __restrict__ q1,
    int8_t* __restrict__ q2, float* __restrict__ s)
{
    __shared__ float wmax[8];
    const int row = blockIdx.x, t = threadIdx.x;
    const float* xr = x + (size_t)row * 2048 + t * 8;
    float4 v0 = ((const float4*)xr)[0];
    float4 v1 = ((const float4*)xr)[1];
    float vv[8] = {v0.x, v0.y, v0.z, v0.w, v1.x, v1.y, v1.z, v1.w};
    float m = 0.f;
#pragma unroll
    for (int j = 0; j < 8; j++) m = fmaxf(m, fabsf(vv[j]));
#pragma unroll
    for (int o = 16; o; o >>= 1) m = fmaxf(m, __shfl_xor_sync(~0u, m, o));
    if ((t & 31) == 0) wmax[t >> 5] = m;
    __syncthreads();
    float mm = wmax[0];
#pragma unroll
    for (int i = 1; i < 8; i++) mm = fmaxf(mm, wmax[i]);
    mm = fmaxf(mm, 1e-20f);
    if (t == 0) s[row] = mm * (1.f / 127.f);
    const float inv = 127.f / mm;

    uint32_t p1[2] = {0, 0}, p2[2] = {0, 0};
#pragma unroll
    for (int j = 0; j < 8; j++) {
        float xs = vv[j] * inv;
        float qf = rintf(xs);
        float rf = rintf((xs - qf) * 254.f);
        int iq = (int)qf, ir = (int)rf;
        p1[j >> 2] |= (uint32_t)(iq & 0xff) << ((j & 3) * 8);
        p2[j >> 2] |= (uint32_t)(ir & 0xff) << ((j & 3) * 8);
    }
    ((uint32_t*)q1)[row * 512 + t * 2]     = p1[0];
    ((uint32_t*)q1)[row * 512 + t * 2 + 1] = p1[1];
    ((uint32_t*)q2)[row * 512 + t * 2]     = p2[0];
    ((uint32_t*)q2)[row * 512 + t * 2 + 1] = p2[1];
}

// ---------------------------------------------------------------------------
// Per-(row, head) two-level quantization of Q/K (64-col head segments).
// grid (M_, 2): y=0 -> Q, y=1 -> K. Scale layout: s[h][row].
// ---------------------------------------------------------------------------
__global__ __launch_bounds__(256) void qkquant(
    const float* __restrict__ Qf, const float* __restrict__ Kf,
    int8_t* __restrict__ Q1, int8_t* __restrict__ Q2, float* __restrict__ SQ,
    int8_t* __restrict__ K1, int8_t* __restrict__ K2, float* __restrict__ SK)
{
    const int row = blockIdx.x, t = threadIdx.x;
    const float* src = (blockIdx.y == 0) ? Qf : Kf;
    int8_t* o1 = (blockIdx.y == 0) ? Q1 : K1;
    int8_t* o2 = (blockIdx.y == 0) ? Q2 : K2;
    float* ss  = (blockIdx.y == 0) ? SQ : SK;

    const float* xr = src + (size_t)row * 2048 + t * 8;
    float4 v0 = ((const float4*)xr)[0];
    float4 v1 = ((const float4*)xr)[1];
    float vv[8] = {v0.x, v0.y, v0.z, v0.w, v1.x, v1.y, v1.z, v1.w};
    float m = 0.f;
#pragma unroll
    for (int j = 0; j < 8; j++) m = fmaxf(m, fabsf(vv[j]));
    m = fmaxf(m, __shfl_xor_sync(~0u, m, 1));
    m = fmaxf(m, __shfl_xor_sync(~0u, m, 2));
    m = fmaxf(m, __shfl_xor_sync(~0u, m, 4));
    m = fmaxf(m, 1e-20f);
    const int h = t >> 3;
    if ((t & 7) == 0) ss[(size_t)h * M_ + row] = m * (1.f / 127.f);
    const float inv = 127.f / m;

    uint32_t p1[2] = {0, 0}, p2[2] = {0, 0};
#pragma unroll
    for (int j = 0; j < 8; j++) {
        float xs = vv[j] * inv;
        float qf = rintf(xs);
        float rf = rintf((xs - qf) * 254.f);
        int iq = (int)qf, ir = (int)rf;
        p1[j >> 2] |= (uint32_t)(iq & 0xff) << ((j & 3) * 8);
        p2[j >> 2] |= (uint32_t)(ir & 0xff) << ((j & 3) * 8);
    }
    ((uint32_t*)o1)[row * 512 + t * 2]     = p1[0];
    ((uint32_t*)o1)[row * 512 + t * 2 + 1] = p1[1];
    ((uint32_t*)o2)[row * 512 + t * 2]     = p2[0];
    ((uint32_t*)o2)[row * 512 + t * 2 + 1] = p2[1];
}

// ---------------------------------------------------------------------------
// V quantization + transpose: V[tok][h*64+d] -> Vt[(b*H+h)*64+d][tok].
// grid (S_/64, H_, B_). Per-(tok, head) scales in SV[h][row].
// ---------------------------------------------------------------------------
__global__ __launch_bounds__(256) void vquant(
    const float* __restrict__ Vf, int8_t* __restrict__ V1,
    int8_t* __restrict__ V2, float* __restrict__ SV)
{
    __shared__ float vs[64][65];
    __shared__ float inv_s[64];
    const int t = threadIdx.x;
    const int j0 = blockIdx.x * 64, h = blockIdx.y, b = blockIdx.z;

#pragma unroll
    for (int i = 0; i < 4; i++) {
        int idx = t + i * 256;
        int r = idx >> 4, c4 = idx & 15;
        float4 v = *(const float4*)(Vf + ((size_t)(b * 2048 + j0 + r)) * 2048
                                       + h * 64 + c4 * 4);
        vs[r][c4 * 4 + 0] = v.x; vs[r][c4 * 4 + 1] = v.y;
        vs[r][c4 * 4 + 2] = v.z; vs[r][c4 * 4 + 3] = v.w;
    }
    __syncthreads();
    {
        int r = t >> 2, seg = t & 3;
        float m = 0.f;
#pragma unroll
        for (int k = 0; k < 16; k++) m = fmaxf(m, fabsf(vs[r][seg * 16 + k]));
        m = fmaxf(m, __shfl_xor_sync(~0u, m, 1));
        m = fmaxf(m, __shfl_xor_sync(~0u, m, 2));
        m = fmaxf(m, 1e-20f);
        if (seg == 0) {
            inv_s[r] = 127.f / m;
            SV[(size_t)h * M_ + b * 2048 + j0 + r] = m * (1.f / 127.f);
        }
    }
    __syncthreads();
    {
        int d = t >> 2, seg = t & 3;
        uint32_t o1[4] = {0,0,0,0}, o2[4] = {0,0,0,0};
#pragma unroll
        for (int i = 0; i < 16; i++) {
            int tok = seg * 16 + i;
            float xs = vs[tok][d] * inv_s[tok];
            float qf = rintf(xs);
            float rf = rintf((xs - qf) * 254.f);
            int iq = (int)qf, ir = (int)rf;
            o1[i >> 2] |= (uint32_t)(iq & 0xff) << ((i & 3) * 8);
            o2[i >> 2] |= (uint32_t)(ir & 0xff) << ((i & 3) * 8);
        }
        size_t off = ((size_t)((b * 32 + h) * 64 + d)) * 2048 + j0 + seg * 16;
        *(uint4*)(V1 + off) = make_uint4(o1[0], o1[1], o1[2], o1[3]);
        *(uint4*)(V2 + off) = make_uint4(o2[0], o2[1], o2[2], o2[3]);
    }
}

// ---------------------------------------------------------------------------
// Two-level int8 GEMM (fp32 C): C = sA_i*sB_j*(A1B1 + (A1B2+A2B1)/254) + bias.
// ---------------------------------------------------------------------------
#define GK 2048
#define NCH8 32
#define SSTG 32768
#define GS8_SMEM (3 * SSTG)

struct GArgs {
    const int8_t *B1, *B2;
    const float* sB;
    const float* bias;
    float* C;
};

__device__ __forceinline__ void s8_load(
    const int8_t* __restrict__ A1, const int8_t* __restrict__ A2,
    const int8_t* __restrict__ B1, const int8_t* __restrict__ B2,
    int m0, int n0, int k0, uint32_t sb, int t)
{
#pragma unroll
    for (int i = 0; i < 2; i++) {
        int idx = t + i * 256, r = idx >> 2, c = idx & 3;
        uint32_t so = (uint32_t)(r * 64 + (((c ^ ((r >> 1) & 3))) << 4));
        size_t ga = (size_t)(m0 + r) * GK + k0 + c * 16;
        size_t gb = (size_t)(n0 + r) * GK + k0 + c * 16;
        cp_async16(sb +          so, A1 + ga);
        cp_async16(sb +  8192u + so, A2 + ga);
        cp_async16(sb + 16384u + so, B1 + gb);
        cp_async16(sb + 24576u + so, B2 + gb);
    }
}

__global__ __launch_bounds__(256, 1) void gemm_s8(
    const int8_t* __restrict__ A1, const int8_t* __restrict__ A2,
    const float* __restrict__ sA, GArgs a0, GArgs a1, GArgs a2)
{
    extern __shared__ char smem[];
    const uint32_t sbase = smem_u32(smem);
    const GArgs ga = (blockIdx.z == 0) ? a0 : (blockIdx.z == 1) ? a1 : a2;
    const int t = threadIdx.x, lane = t & 31, wid = t >> 5;
    const int warp_m = wid >> 2, warp_n = wid & 3;
    const int m0 = blockIdx.y * 128;
    const int n0 = blockIdx.x * 128;

    int a_row[4], b_row[2];
    uint32_t a_sw[4], b_sw[2];
#pragma unroll
    for (int mt = 0; mt < 4; mt++) {
        a_row[mt] = warp_m * 64 + mt * 16 + (lane & 15);
        a_sw[mt]  = (uint32_t)((a_row[mt] >> 1) & 3);
    }
#pragma unroll
    for (int pt = 0; pt < 2; pt++) {
        b_row[pt] = warp_n * 32 + pt * 16 + (lane & 7) + ((lane >> 4) & 1) * 8;
        b_sw[pt]  = (uint32_t)((b_row[pt] >> 1) & 3);
    }
    const uint32_t a_ch = (uint32_t)(lane >> 4);
    const uint32_t b_ch = (uint32_t)((lane >> 3) & 1);

    int acc1[4][4][4], acc2[4][4][4];
#pragma unroll
    for (int i = 0; i < 4; i++)
#pragma unroll
        for (int j = 0; j < 4; j++)
#pragma unroll
            for (int q = 0; q < 4; q++) { acc1[i][j][q] = 0; acc2[i][j][q] = 0; }

    s8_load(A1, A2, ga.B1, ga.B2, m0, n0, 0,   sbase,            t); CP_COMMIT();
    s8_load(A1, A2, ga.B1, ga.B2, m0, n0, 64,  sbase + SSTG,     t); CP_COMMIT();
    s8_load(A1, A2, ga.B1, ga.B2, m0, n0, 128, sbase + 2 * SSTG, t); CP_COMMIT();

    uint32_t stg = 0;
    for (int ch = 0; ch < NCH8; ch++) {
        CP_WAIT2();
        __syncthreads();
        const uint32_t sb = sbase + stg * SSTG;

#pragma unroll
        for (int s = 0; s < 2; s++) {
            uint32_t Af1[4][4], Af2[4][4];
            uint32_t Bf1[2][4], Bf2[2][4];
#pragma unroll
            for (int mt = 0; mt < 4; mt++) {
                uint32_t c = (uint32_t)(s * 2) + a_ch;
                uint32_t off = (uint32_t)(a_row[mt] * 64) + ((c ^ a_sw[mt]) << 4);
                ldm_x4(Af1[mt], sb + off);
                ldm_x4(Af2[mt], sb + 8192u + off);
            }
#pragma unroll
            for (int pt = 0; pt < 2; pt++) {
                uint32_t c = (uint32_t)(s * 2) + b_ch;
                uint32_t off = (uint32_t)(b_row[pt] * 64) + ((c ^ b_sw[pt]) << 4);
                ldm_x4(Bf1[pt], sb + 16384u + off);
                ldm_x4(Bf2[pt], sb + 24576u + off);
            }
#pragma unroll
            for (int mt = 0; mt < 4; mt++)
#pragma unroll
                for (int nt = 0; nt < 4; nt++) {
                    const int pt = nt >> 1, hl = (nt & 1) * 2;
                    mma_s8(acc1[mt][nt], Af1[mt], Bf1[pt][hl], Bf1[pt][hl+1]);
                    mma_s8(acc2[mt][nt], Af1[mt], Bf2[pt][hl], Bf2[pt][hl+1]);
                    mma_s8(acc2[mt][nt], Af2[mt], Bf1[pt][hl], Bf1[pt][hl+1]);
                }
        }
        __syncthreads();
        if (ch + 3 < NCH8)
            s8_load(A1, A2, ga.B1, ga.B2, m0, n0, (ch + 3) * 64,
                    sbase + stg * SSTG, t);
        CP_COMMIT();
        stg = (stg == 2) ? 0 : stg + 1;
    }

    const float R = 1.f / 254.f;
#pragma unroll
    for (int mt = 0; mt < 4; mt++) {
        const int r0 = m0 + warp_m * 64 + mt * 16 + (lane >> 2);
        const float sa0 = sA[r0], sa1 = sA[r0 + 8];
#pragma unroll
        for (int nt = 0; nt < 4; nt++) {
            const int cc = n0 + warp_n * 32 + nt * 8 + (lane & 3) * 2;
            const float sb0 = ga.sB[cc], sb1 = ga.sB[cc + 1];
            const float bx = ga.bias[cc], by = ga.bias[cc + 1];
            float v0 = ((float)acc1[mt][nt][0] + (float)acc2[mt][nt][0] * R) * (sa0 * sb0) + bx;
            float v1 = ((float)acc1[mt][nt][1] + (float)acc2[mt][nt][1] * R) * (sa0 * sb1) + by;
            float v2 = ((float)acc1[mt][nt][2] + (float)acc2[mt][nt][2] * R) * (sa1 * sb0) + bx;
            float v3 = ((float)acc1[mt][nt][3] + (float)acc2[mt][nt][3] * R) * (sa1 * sb1) + by;
            *(float2*)(ga.C + (size_t)r0 * GK + cc)       = make_float2(v0, v1);
            *(float2*)(ga.C + (size_t)(r0 + 8) * GK + cc) = make_float2(v2, v3);
        }
    }
}

// ---------------------------------------------------------------------------
// Flash attention (causal), full two-level int8 (Q,K,P,V), fp32 softmax.
// smem: [0,32K) two KV stages (k1,k2,v1,v2 4KB each); [32K,+1K) scales;
//       [33792,+32K) Q staging (prologue) then per-warp P tiles (mainloop).
// ---------------------------------------------------------------------------
#define FQT 256
#define FKT 64
#define KVST 16384u
#define SCOFF 32768u
#define POFF 33792u
#define FA_SMEM 66560

__global__ __launch_bounds__(256, 1) void flash_s8(
    const int8_t* __restrict__ q1g, const int8_t* __restrict__ q2g,
    const float* __restrict__ sqg,
    const int8_t* __restrict__ k1g, const int8_t* __restrict__ k2g,
    const float* __restrict__ skg,
    const int8_t* __restrict__ v1g, const int8_t* __restrict__ v2g,
    const float* __restrict__ svg,
    float* __restrict__ O)
{
    extern __shared__ char smem[];
    const uint32_t sb = smem_u32(smem);
    const int t = threadIdx.x, lane = t & 31, wid = t >> 5;
    const int qt = blockIdx.x, bh = blockIdx.y;
    const int b = bh >> 5, h = bh & 31;
    const int q0 = qt * FQT;
    const int qrow0 = b * S_ + q0;
    const int krow0 = b * S_;
    const int hoff = h * D_;
    const size_t vtbase = ((size_t)((b * H_ + h) * D_)) * S_;
    const float* skh = skg + (size_t)h * M_ + b * S_;
    const float* svh = svg + (size_t)h * M_ + b * S_;
    const float R254 = 1.f / 254.f;
    const float CEXP = SCALE_ * 1.4426950408889634f;

    // ---- stage Q (both levels) into P area, hoist fragments ----
#pragma unroll
    for (int i = 0; i < 4; i++) {
        int idx = t + i * 256, r = idx >> 2, c = idx & 3;
        uint32_t so = (uint32_t)(r * 64 + ((c ^ ((r >> 1) & 3)) << 4));
        size_t g = (size_t)(qrow0 + r) * 2048 + hoff + c * 16;
        cp_async16(sb + POFF +          so, q1g + g);
        cp_async16(sb + POFF + 16384u + so, q2g + g);
    }
    CP_COMMIT(); CP_WAIT0();
    __syncthreads();

    uint32_t fq1[2][2][4], fq2[2][2][4];
#pragma unroll
    for (int mt = 0; mt < 2; mt++)
#pragma unroll
        for (int kc = 0; kc < 2; kc++) {
            int row = wid * 32 + mt * 16 + (lane & 15);
            uint32_t c = (uint32_t)(kc * 2 + (lane >> 4));
            uint32_t off = (uint32_t)(row * 64) + ((c ^ (uint32_t)((row >> 1) & 3)) << 4);
            ldm_x4(fq1[mt][kc], sb + POFF + off);
            ldm_x4(fq2[mt][kc], sb + POFF + 16384u + off);
        }
    float sqv[2][2];
#pragma unroll
    for (int mt = 0; mt < 2; mt++)
#pragma unroll
        for (int rr = 0; rr < 2; rr++)
            sqv[mt][rr] = sqg[(size_t)h * M_ + qrow0 + wid * 32 + mt * 16
                              + (lane >> 2) + rr * 8];
    __syncthreads();   // Q area now reusable as P tiles

    const int jmax = 4 * (qt + 1);
    {   // KV tile 0 -> stage 0
        int r = t >> 2, c = t & 3;
        uint32_t so = (uint32_t)(r * 64 + ((c ^ ((r >> 1) & 3)) << 4));
        size_t gk = (size_t)(krow0 + r) * 2048 + hoff + c * 16;
        cp_async16(sb +          so, k1g + gk);
        cp_async16(sb +  4096u + so, k2g + gk);
        size_t gv = vtbase + (size_t)r * 2048 + c * 16;
        cp_async16(sb +  8192u + so, v1g + gv);
        cp_async16(sb + 12288u + so, v2g + gv);
        if (t < 16)      cp_async16(sb + SCOFF + t * 16u, skh + t * 4);
        else if (t < 32) cp_async16(sb + SCOFF + 256u + (t - 16) * 16u, svh + (t - 16) * 4);
    }
    CP_COMMIT();

    float Oacc[2][8][4];
#pragma unroll
    for (int i = 0; i < 2; i++)
#pragma unroll
        for (int j = 0; j < 8; j++)
#pragma unroll
            for (int q = 0; q < 4; q++) Oacc[i][j][q] = 0.f;
    float m_i[2][2] = {{-1e30f, -1e30f}, {-1e30f, -1e30f}};
    float l_i[2][2] = {{0.f, 0.f}, {0.f, 0.f}};

    for (int jt = 0; jt < jmax; jt++) {
        const int k0 = jt * FKT;
        __syncthreads();
        if (jt + 1 < jmax) {
            uint32_t st = (uint32_t)((jt + 1) & 1) * KVST;
            int r = t >> 2, c = t & 3;
            uint32_t so = (uint32_t)(r * 64 + ((c ^ ((r >> 1) & 3)) << 4));
            size_t gk = (size_t)(krow0 + k0 + FKT + r) * 2048 + hoff + c * 16;
            cp_async16(sb + st +          so, k1g + gk);
            cp_async16(sb + st +  4096u + so, k2g + gk);
            size_t gv = vtbase + (size_t)r * 2048 + k0 + FKT + c * 16;
            cp_async16(sb + st +  8192u + so, v1g + gv);
            cp_async16(sb + st + 12288u + so, v2g + gv);
            uint32_t sco = SCOFF + (uint32_t)((jt + 1) & 1) * 512u;
            if (t < 16)      cp_async16(sb + sco + t * 16u, skh + k0 + FKT + t * 4);
            else if (t < 32) cp_async16(sb + sco + 256u + (t - 16) * 16u,
                                        svh + k0 + FKT + (t - 16) * 4);
        }
        CP_COMMIT(); CP_WAIT1();
        __syncthreads();
        const uint32_t st = sb + (uint32_t)(jt & 1) * KVST;
        const float* sks = (const float*)(smem + SCOFF + (jt & 1) * 512);
        const float* svs = sks + 64;

        // ---- S = Q K^T, int8 two-level, in key halves ----
        float sacc[2][8][4];
#pragma unroll
        for (int kh = 0; kh < 2; kh++) {
            int i1[2][4][4], i2[2][4][4];
#pragma unroll
            for (int i = 0; i < 2; i++)
#pragma unroll
                for (int j = 0; j < 4; j++)
#pragma unroll
                    for (int q = 0; q < 4; q++) { i1[i][j][q] = 0; i2[i][j][q] = 0; }
#pragma unroll
            for (int kc = 0; kc < 2; kc++) {
                uint32_t bk1[2][4], bk2[2][4];
#pragma unroll
                for (int np2 = 0; np2 < 2; np2++) {
                    int row = (kh * 2 + np2) * 16 + (lane & 7) + ((lane >> 4) & 1) * 8;
                    uint32_t c = (uint32_t)(kc * 2 + ((lane >> 3) & 1));
                    uint32_t off = (uint32_t)(row * 64) + ((c ^ (uint32_t)((row >> 1) & 3)) << 4);
                    ldm_x4(bk1[np2], st + off);
                    ldm_x4(bk2[np2], st + 4096u + off);
                }
#pragma unroll
                for (int mt = 0; mt < 2; mt++)
#pragma unroll
                    for (int np2 = 0; np2 < 2; np2++)
#pragma unroll
                        for (int nt2 = 0; nt2 < 2; nt2++) {
                            const int sl = np2 * 2 + nt2, hl = nt2 * 2;
                            mma_s8(i1[mt][sl], fq1[mt][kc], bk1[np2][hl], bk1[np2][hl+1]);
                            mma_s8(i2[mt][sl], fq1[mt][kc], bk2[np2][hl], bk2[np2][hl+1]);
                            mma_s8(i2[mt][sl], fq2[mt][kc], bk1[np2][hl], bk1[np2][hl+1]);
                        }
            }
#pragma unroll
            for (int mt = 0; mt < 2; mt++)
#pragma unroll
                for (int sl = 0; sl < 4; sl++) {
                    const int nt = kh * 4 + sl;
                    const int c0 = nt * 8 + (lane & 3) * 2;
                    const float k0s = sks[c0], k1s = sks[c0 + 1];
#pragma unroll
                    for (int rr = 0; rr < 2; rr++) {
                        sacc[mt][nt][rr*2]   = sqv[mt][rr] * k0s *
                            ((float)i1[mt][sl][rr*2]   + (float)i2[mt][sl][rr*2]   * R254);
                        sacc[mt][nt][rr*2+1] = sqv[mt][rr] * k1s *
                            ((float)i1[mt][sl][rr*2+1] + (float)i2[mt][sl][rr*2+1] * R254);
                    }
                }
        }

        // ---- causal mask ----
        if (k0 + FKT - 1 > q0) {
#pragma unroll
            for (int mt = 0; mt < 2; mt++)
#pragma unroll
                for (int nt = 0; nt < 8; nt++)
#pragma unroll
                    for (int e = 0; e < 4; e++) {
                        int qrow = q0 + wid * 32 + mt * 16 + (lane >> 2) + (e >> 1) * 8;
                        int kcol = k0 + nt * 8 + (lane & 3) * 2 + (e & 1);
                        if (kcol > qrow) sacc[mt][nt][e] = -1e30f;
                    }
        }

        // ---- online softmax ----
#pragma unroll
        for (int mt = 0; mt < 2; mt++)
#pragma unroll
            for (int rr = 0; rr < 2; rr++) {
                float mx = -1e30f;
#pragma unroll
                for (int nt = 0; nt < 8; nt++)
                    mx = fmaxf(mx, fmaxf(sacc[mt][nt][rr*2], sacc[mt][nt][rr*2+1]));
                mx = fmaxf(mx, __shfl_xor_sync(0xffffffffu, mx, 1));
                mx = fmaxf(mx, __shfl_xor_sync(0xffffffffu, mx, 2));
                const float m_new = fmaxf(m_i[mt][rr], mx);
                const float mC = m_new * CEXP;
                const float alpha = ex2(m_i[mt][rr] * CEXP - mC);
                float rs = 0.f;
#pragma unroll
                for (int nt = 0; nt < 8; nt++) {
                    float p0 = ex2(sacc[mt][nt][rr*2]   * CEXP - mC);
                    float p1 = ex2(sacc[mt][nt][rr*2+1] * CEXP - mC);
                    sacc[mt][nt][rr*2] = p0; sacc[mt][nt][rr*2+1] = p1;
                    rs += p0 + p1;
                }
                rs += __shfl_xor_sync(0xffffffffu, rs, 1);
                rs += __shfl_xor_sync(0xffffffffu, rs, 2);
                l_i[mt][rr] = l_i[mt][rr] * alpha + rs;
                m_i[mt][rr] = m_new;
#pragma unroll
                for (int nd = 0; nd < 8; nd++) {
                    Oacc[mt][nd][rr*2]   *= alpha;
                    Oacc[mt][nd][rr*2+1] *= alpha;
                }
            }

        // ---- fold sv into P, quantize two-level, stage to per-warp smem ----
        float srw[2][2];
#pragma unroll
        for (int mt = 0; mt < 2; mt++)
#pragma unroll
            for (int rr = 0; rr < 2; rr++) {
                float mx = 0.f;
#pragma unroll
                for (int nt = 0; nt < 8; nt++) {
                    const int c0 = nt * 8 + (lane & 3) * 2;
                    float w0 = sacc[mt][nt][rr*2]   * svs[c0];
                    float w1 = sacc[mt][nt][rr*2+1] * svs[c0 + 1];
                    sacc[mt][nt][rr*2] = w0; sacc[mt][nt][rr*2+1] = w1;
                    mx = fmaxf(mx, fmaxf(w0, w1));
                }
                mx = fmaxf(mx, __shfl_xor_sync(0xffffffffu, mx, 1));
                mx = fmaxf(mx, __shfl_xor_sync(0xffffffffu, mx, 2));
                mx = fmaxf(mx, 1e-30f);
                srw[mt][rr] = mx * (1.f / 127.f);
                const float inv = 127.f / mx;
                const int row = mt * 16 + (lane >> 2) + rr * 8;
                const uint32_t rswz = (uint32_t)((row >> 1) & 3);
                const uint32_t pb = sb + POFF + (uint32_t)(wid * 4096) + row * 64;
#pragma unroll
                for (int nt = 0; nt < 8; nt++) {
                    float a0 = sacc[mt][nt][rr*2] * inv;
                    float a1 = sacc[mt][nt][rr*2+1] * inv;
                    float f0 = rintf(a0), f1 = rintf(a1);
                    int b0 = (int)f0, b1 = (int)f1;
                    int r0 = (int)rintf((a0 - f0) * 254.f);
                    int r1 = (int)rintf((a1 - f1) * 254.f);
                    uint32_t col = (uint32_t)(nt * 8 + (lane & 3) * 2);
                    uint32_t ad = pb + ((((uint32_t)(nt >> 1)) ^ rswz) << 4) + (col & 15);
                    sts16(ad, (uint16_t)((b0 & 0xff) | ((b1 & 0xff) << 8)));
                    sts16(ad + 2048u, (uint16_t)((r0 & 0xff) | ((r1 & 0xff) << 8)));
                }
            }
        __syncwarp();

        // ---- O += W Vt, int8 two-level, in d halves ----
#pragma unroll
        for (int dh = 0; dh < 2; dh++) {
            int j1[2][4][4], j2[2][4][4];
#pragma unroll
            for (int i = 0; i < 2; i++)
#pragma unroll
                for (int j = 0; j < 4; j++)
#pragma unroll
                    for (int q = 0; q < 4; q++) { j1[i][j][q] = 0; j2[i][j][q] = 0; }
#pragma unroll
            for (int kc = 0; kc < 2; kc++) {
                uint32_t aw1[2][4], aw2[2][4];
#pragma unroll
                for (int mt = 0; mt < 2; mt++) {
                    int row = mt * 16 + (lane & 15);
                    uint32_t c = (uint32_t)(kc * 2 + (lane >> 4));
                    uint32_t off = (uint32_t)(wid * 4096) + (uint32_t)(row * 64)
                                 + ((c ^ (uint32_t)((row >> 1) & 3)) << 4);
                    ldm_x4(aw1[mt], sb + POFF + off);
                    ldm_x4(aw2[mt], sb + POFF + 2048u + off);
                }
                uint32_t bv1[2][4], bv2[2][4];
#pragma unroll
                for (int np2 = 0; np2 < 2; np2++) {
                    int row = (dh * 2 + np2) * 16 + (lane & 7) + ((lane >> 4) & 1) * 8;
                    uint32_t c = (uint32_t)(kc * 2 + ((lane >> 3) & 1));
                    uint32_t off = (uint32_t)(row * 64) + ((c ^ (uint32_t)((row >> 1) & 3)) << 4);
                    ldm_x4(bv1[np2], st + 8192u + off);
                    ldm_x4(bv2[np2], st + 12288u + off);
                }
#pragma unroll
                for (int mt = 0; mt < 2; mt++)
#pragma unroll
                    for (int np2 = 0; np2 < 2; np2++)
#pragma unroll
                        for (int nt2 = 0; nt2 < 2; nt2++) {
                            const int sl = np2 * 2 + nt2, hl = nt2 * 2;
                            mma_s8(j1[mt][sl], aw1[mt], bv1[np2][hl], bv1[np2][hl+1]);
                            mma_s8(j2[mt][sl], aw1[mt], bv2[np2][hl], bv2[np2][hl+1]);
                            mma_s8(j2[mt][sl], aw2[mt], bv1[np2][hl], bv1[np2][hl+1]);
                        }
            }
#pragma unroll
            for (int mt = 0; mt < 2; mt++)
#pragma unroll
                for (int sl = 0; sl < 4; sl++)
#pragma unroll
                    for (int e = 0; e < 4; e++)
                        Oacc[mt][dh * 4 + sl][e] += srw[mt][e >> 1] *
                            ((float)j1[mt][sl][e] + (float)j2[mt][sl][e] * R254);
        }
    }

    // ---- epilogue ----
#pragma unroll
    for (int mt = 0; mt < 2; mt++)
#pragma unroll
        for (int rr = 0; rr < 2; rr++) {
            const int row = wid * 32 + mt * 16 + (lane >> 2) + rr * 8;
            const float inv = 1.f / l_i[mt][rr];
            const size_t rb = (size_t)(qrow0 + row) * 2048 + hoff + (lane & 3) * 2;
#pragma unroll
            for (int nd = 0; nd < 8; nd++) {
                float v0 = Oacc[mt][nd][rr*2]   * inv;
                float v1 = Oacc[mt][nd][rr*2+1] * inv;
                *(float2*)(O + rb + nd * 8) = make_float2(v0, v1);
            }
        }
}

// ---------------------------------------------------------------------------
extern "C" void kernel_launch(void* const* d_in, const int* in_sizes, int n_in,
                              void* d_out, int out_size)
{
    const float* x  = (const float*)d_in[0];
    const float* Wq = (const float*)d_in[1];
    const float* bq = (const float*)d_in[2];
    const float* Wk = (const float*)d_in[3];
    const float* bk = (const float*)d_in[4];
    const float* Wv = (const float*)d_in[5];
    const float* bv = (const float*)d_in[6];
    const float* Wo = (const float*)d_in[7];
    const float* bo = (const float*)d_in[8];
    float* out = (float*)d_out;

    int8_t *x1, *x2, *a1, *a2;
    int8_t *wq1, *wq2, *wk1, *wk2, *wv1, *wv2, *wo1, *wo2;
    int8_t *q1, *q2, *k1, *k2, *vt1, *vt2;
    float *sx, *sa, *swq, *swk, *swv, *swo, *attn;
    float *qf, *kf, *vf, *sq, *sk, *sv;
    cudaGetSymbolAddress((void**)&x1, g_x1);
    cudaGetSymbolAddress((void**)&x2, g_x2);
    cudaGetSymbolAddress((void**)&sx, g_sx);
    cudaGetSymbolAddress((void**)&a1, g_a1);
    cudaGetSymbolAddress((void**)&a2, g_a2);
    cudaGetSymbolAddress((void**)&sa, g_sa);
    cudaGetSymbolAddress((void**)&attn, g_attn);
    cudaGetSymbolAddress((void**)&wq1, g_wq1);
    cudaGetSymbolAddress((void**)&wq2, g_wq2);
    cudaGetSymbolAddress((void**)&swq, g_swq);
    cudaGetSymbolAddress((void**)&wk1, g_wk1);
    cudaGetSymbolAddress((void**)&wk2, g_wk2);
    cudaGetSymbolAddress((void**)&swk, g_swk);
    cudaGetSymbolAddress((void**)&wv1, g_wv1);
    cudaGetSymbolAddress((void**)&wv2, g_wv2);
    cudaGetSymbolAddress((void**)&swv, g_swv);
    cudaGetSymbolAddress((void**)&wo1, g_wo1);
    cudaGetSymbolAddress((void**)&wo2, g_wo2);
    cudaGetSymbolAddress((void**)&swo, g_swo);
    cudaGetSymbolAddress((void**)&qf, g_qf);
    cudaGetSymbolAddress((void**)&kf, g_kf);
    cudaGetSymbolAddress((void**)&vf, g_vf);
    cudaGetSymbolAddress((void**)&q1, g_q1);
    cudaGetSymbolAddress((void**)&q2, g_q2);
    cudaGetSymbolAddress((void**)&k1, g_k1);
    cudaGetSymbolAddress((void**)&k2, g_k2);
    cudaGetSymbolAddress((void**)&vt1, g_vt1);
    cudaGetSymbolAddress((void**)&vt2, g_vt2);
    cudaGetSymbolAddress((void**)&sq, g_sq);
    cudaGetSymbolAddress((void**)&sk, g_sk);
    cudaGetSymbolAddress((void**)&sv, g_sv);

    cudaFuncSetAttribute(gemm_s8,
                         cudaFuncAttributeMaxDynamicSharedMemorySize, GS8_SMEM);
    cudaFuncSetAttribute(flash_s8,
                         cudaFuncAttributeMaxDynamicSharedMemorySize, FA_SMEM);

    rowquant<<<M_, 256>>>(x,  x1,  x2,  sx);
    rowquant<<<E_, 256>>>(Wq, wq1, wq2, swq);
    rowquant<<<E_, 256>>>(Wk, wk1, wk2, swk);
    rowquant<<<E_, 256>>>(Wv, wv1, wv2, swv);
    rowquant<<<E_, 256>>>(Wo, wo1, wo2, swo);

    GArgs aq{wq1, wq2, swq, bq, qf};
    GArgs ak{wk1, wk2, swk, bk, kf};
    GArgs av{wv1, wv2, swv, bv, vf};
    GArgs ao{wo1, wo2, swo, bo, out};

    dim3 gq(E_ / 128, M_ / 128, 3);
    gemm_s8<<<gq, 256, GS8_SMEM>>>(x1, x2, sx, aq, ak, av);

    qkquant<<<dim3(M_, 2), 256>>>(qf, kf, q1, q2, sq, k1, k2, sk);
    vquant<<<dim3(S_ / 64, H_, B_), 256>>>(vf, vt1, vt2, sv);

    dim3 ga(S_ / FQT, B_ * H_);
    flash_s8<<<ga, 256, FA_SMEM>>>(q1, q2, sq, k1, k2, sk, vt1, vt2, sv, attn);

    rowquant<<<M_, 256>>>(attn, a1, a2, sa);

    dim3 go(E_ / 128, M_ / 128, 1);
    gemm_s8<<<go, 256, GS8_SMEM>>>(a1, a2, sa, ao, ao, ao);
}

// round 9
// speedup vs baseline: 1.1645x; 1.1645x over previous
#include <cuda_runtime.h>
#include <cuda_bf16.h>
#include <cstdint>
#include <math.h>

#define B_ 2
#define S_ 2048
#define E_ 2048
#define H_ 32
#define D_ 64
#define M_ (B_*S_)
#define SCALE_ 0.125f

// ---------------- scratch ----------------
static __device__ __align__(128) int8_t g_x1[(size_t)M_ * E_];
static __device__ __align__(128) int8_t g_x2[(size_t)M_ * E_];
static __device__ __align__(128) float  g_sx[M_];
static __device__ __align__(128) int8_t g_a1[(size_t)M_ * E_];
static __device__ __align__(128) int8_t g_a2[(size_t)M_ * E_];
static __device__ __align__(128) float  g_sa[M_];
static __device__ __align__(128) float  g_attn[(size_t)M_ * E_];

static __device__ __align__(128) int8_t g_wq1[(size_t)E_ * E_];
static __device__ __align__(128) int8_t g_wq2[(size_t)E_ * E_];
static __device__ __align__(128) float  g_swq[E_];
static __device__ __align__(128) int8_t g_wk1[(size_t)E_ * E_];
static __device__ __align__(128) int8_t g_wk2[(size_t)E_ * E_];
static __device__ __align__(128) float  g_swk[E_];
static __device__ __align__(128) int8_t g_wv1[(size_t)E_ * E_];
static __device__ __align__(128) int8_t g_wv2[(size_t)E_ * E_];
static __device__ __align__(128) float  g_swv[E_];
static __device__ __align__(128) int8_t g_wo1[(size_t)E_ * E_];
static __device__ __align__(128) int8_t g_wo2[(size_t)E_ * E_];
static __device__ __align__(128) float  g_swo[E_];

static __device__ __align__(128) float g_qf[(size_t)M_ * E_];
static __device__ __align__(128) float g_kf[(size_t)M_ * E_];

static __device__ __align__(128) int8_t g_q1[(size_t)M_ * E_];
static __device__ __align__(128) int8_t g_q2[(size_t)M_ * E_];
static __device__ __align__(128) int8_t g_k1[(size_t)M_ * E_];
static __device__ __align__(128) int8_t g_k2[(size_t)M_ * E_];
static __device__ __align__(128) float  g_sq[(size_t)H_ * M_];
static __device__ __align__(128) float  g_sk[(size_t)H_ * M_];

static __device__ __align__(128) __nv_bfloat16 g_vh[(size_t)M_ * E_];
static __device__ __align__(128) __nv_bfloat16 g_vl[(size_t)M_ * E_];

// ---------------- helpers ----------------
__device__ __forceinline__ uint32_t smem_u32(const void* p) {
    uint32_t a;
    asm("{ .reg .u64 t; cvta.to.shared.u64 t, %1; cvt.u32.u64 %0, t; }"
        : "=r"(a) : "l"(p));
    return a;
}
__device__ __forceinline__ void cp_async16(uint32_t saddr, const void* gaddr) {
    asm volatile("cp.async.cg.shared.global [%0], [%1], 16;\n"
                 :: "r"(saddr), "l"(gaddr));
}
#define CP_COMMIT() asm volatile("cp.async.commit_group;\n" ::: "memory")
#define CP_WAIT0()  asm volatile("cp.async.wait_group 0;\n" ::: "memory")
#define CP_WAIT1()  asm volatile("cp.async.wait_group 1;\n" ::: "memory")
#define CP_WAIT2()  asm volatile("cp.async.wait_group 2;\n" ::: "memory")

__device__ __forceinline__ void ldm_x4(uint32_t* r, uint32_t addr) {
    asm volatile("ldmatrix.sync.aligned.m8n8.x4.shared.b16 {%0,%1,%2,%3}, [%4];"
                 : "=r"(r[0]), "=r"(r[1]), "=r"(r[2]), "=r"(r[3]) : "r"(addr));
}
__device__ __forceinline__ void ldm_x4t(uint32_t* r, uint32_t addr) {
    asm volatile("ldmatrix.sync.aligned.m8n8.x4.trans.shared.b16 {%0,%1,%2,%3}, [%4];"
                 : "=r"(r[0]), "=r"(r[1]), "=r"(r[2]), "=r"(r[3]) : "r"(addr));
}
__device__ __forceinline__ void mma16816(float* d, const uint32_t* a,
                                         uint32_t b0, uint32_t b1) {
    asm volatile(
        "mma.sync.aligned.m16n8k16.row.col.f32.bf16.bf16.f32 "
        "{%0,%1,%2,%3}, {%4,%5,%6,%7}, {%8,%9}, {%0,%1,%2,%3};"
        : "+f"(d[0]), "+f"(d[1]), "+f"(d[2]), "+f"(d[3])
        : "r"(a[0]), "r"(a[1]), "r"(a[2]), "r"(a[3]), "r"(b0), "r"(b1));
}
__device__ __forceinline__ void mma_s8(int* d, const uint32_t* a,
                                       uint32_t b0, uint32_t b1) {
    asm volatile(
        "mma.sync.aligned.m16n8k32.row.col.s32.s8.s8.s32 "
        "{%0,%1,%2,%3}, {%4,%5,%6,%7}, {%8,%9}, {%0,%1,%2,%3};"
        : "+r"(d[0]), "+r"(d[1]), "+r"(d[2]), "+r"(d[3])
        : "r"(a[0]), "r"(a[1]), "r"(a[2]), "r"(a[3]), "r"(b0), "r"(b1));
}
__device__ __forceinline__ uint32_t packbf(float lo, float hi) {
    uint32_t d;
    asm("cvt.rn.bf16x2.f32 %0, %1, %2;" : "=r"(d) : "f"(hi), "f"(lo));
    return d;
}
__device__ __forceinline__ float bf_lo(uint32_t u) { return __uint_as_float(u << 16); }
__device__ __forceinline__ float bf_hi(uint32_t u) { return __uint_as_float(u & 0xffff0000u); }
__device__ __forceinline__ float ex2(float x) {
    float y; asm("ex2.approx.f32 %0, %1;" : "=f"(y) : "f"(x)); return y;
}

// ---------------------------------------------------------------------------
// Row-wise two-level int8 quantization over 2048-col rows.
// ---------------------------------------------------------------------------
__global__ __launch_bounds__(256) void rowquant(
    const float* __restrict__ x, int8_t* __restrict__ q1,
    int8_t* __restrict__ q2, float* __restrict__ s)
{
    __shared__ float wmax[8];
    const int row = blockIdx.x, t = threadIdx.x;
    const float* xr = x + (size_t)row * 2048 + t * 8;
    float4 v0 = ((const float4*)xr)[0];
    float4 v1 = ((const float4*)xr)[1];
    float vv[8] = {v0.x, v0.y, v0.z, v0.w, v1.x, v1.y, v1.z, v1.w};
    float m = 0.f;
#pragma unroll
    for (int j = 0; j < 8; j++) m = fmaxf(m, fabsf(vv[j]));
#pragma unroll
    for (int o = 16; o; o >>= 1) m = fmaxf(m, __shfl_xor_sync(~0u, m, o));
    if ((t & 31) == 0) wmax[t >> 5] = m;
    __syncthreads();
    float mm = wmax[0];
#pragma unroll
    for (int i = 1; i < 8; i++) mm = fmaxf(mm, wmax[i]);
    mm = fmaxf(mm, 1e-20f);
    if (t == 0) s[row] = mm * (1.f / 127.f);
    const float inv = 127.f / mm;

    uint32_t p1[2] = {0, 0}, p2[2] = {0, 0};
#pragma unroll
    for (int j = 0; j < 8; j++) {
        float xs = vv[j] * inv;
        float qf = rintf(xs);
        float rf = rintf((xs - qf) * 254.f);
        int iq = (int)qf, ir = (int)rf;
        p1[j >> 2] |= (uint32_t)(iq & 0xff) << ((j & 3) * 8);
        p2[j >> 2] |= (uint32_t)(ir & 0xff) << ((j & 3) * 8);
    }
    ((uint32_t*)q1)[row * 512 + t * 2]     = p1[0];
    ((uint32_t*)q1)[row * 512 + t * 2 + 1] = p1[1];
    ((uint32_t*)q2)[row * 512 + t * 2]     = p2[0];
    ((uint32_t*)q2)[row * 512 + t * 2 + 1] = p2[1];
}

// ---------------------------------------------------------------------------
// Per-(row, head) two-level quantization of Q/K (64-col head segments).
// ---------------------------------------------------------------------------
__global__ __launch_bounds__(256) void qkquant(
    const float* __restrict__ Qf, const float* __restrict__ Kf,
    int8_t* __restrict__ Q1, int8_t* __restrict__ Q2, float* __restrict__ SQ,
    int8_t* __restrict__ K1, int8_t* __restrict__ K2, float* __restrict__ SK)
{
    const int row = blockIdx.x, t = threadIdx.x;
    const float* src = (blockIdx.y == 0) ? Qf : Kf;
    int8_t* o1 = (blockIdx.y == 0) ? Q1 : K1;
    int8_t* o2 = (blockIdx.y == 0) ? Q2 : K2;
    float* ss  = (blockIdx.y == 0) ? SQ : SK;

    const float* xr = src + (size_t)row * 2048 + t * 8;
    float4 v0 = ((const float4*)xr)[0];
    float4 v1 = ((const float4*)xr)[1];
    float vv[8] = {v0.x, v0.y, v0.z, v0.w, v1.x, v1.y, v1.z, v1.w};
    float m = 0.f;
#pragma unroll
    for (int j = 0; j < 8; j++) m = fmaxf(m, fabsf(vv[j]));
    m = fmaxf(m, __shfl_xor_sync(~0u, m, 1));
    m = fmaxf(m, __shfl_xor_sync(~0u, m, 2));
    m = fmaxf(m, __shfl_xor_sync(~0u, m, 4));
    m = fmaxf(m, 1e-20f);
    const int h = t >> 3;
    if ((t & 7) == 0) ss[(size_t)h * M_ + row] = m * (1.f / 127.f);
    const float inv = 127.f / m;

    uint32_t p1[2] = {0, 0}, p2[2] = {0, 0};
#pragma unroll
    for (int j = 0; j < 8; j++) {
        float xs = vv[j] * inv;
        float qf = rintf(xs);
        float rf = rintf((xs - qf) * 254.f);
        int iq = (int)qf, ir = (int)rf;
        p1[j >> 2] |= (uint32_t)(iq & 0xff) << ((j & 3) * 8);
        p2[j >> 2] |= (uint32_t)(ir & 0xff) << ((j & 3) * 8);
    }
    ((uint32_t*)o1)[row * 512 + t * 2]     = p1[0];
    ((uint32_t*)o1)[row * 512 + t * 2 + 1] = p1[1];
    ((uint32_t*)o2)[row * 512 + t * 2]     = p2[0];
    ((uint32_t*)o2)[row * 512 + t * 2 + 1] = p2[1];
}

// ---------------------------------------------------------------------------
// Two-level int8 GEMM. SPLIT=false -> fp32 C; SPLIT=true -> bf16 (hi,lo) out.
// ---------------------------------------------------------------------------
#define GK 2048
#define NCH8 32
#define SSTG 32768
#define GS8_SMEM (3 * SSTG)

struct GArgs {
    const int8_t *B1, *B2;
    const float* sB;
    const float* bias;
    float* C;
    __nv_bfloat16 *Ch, *Cl;
};

__device__ __forceinline__ void s8_load(
    const int8_t* __restrict__ A1, const int8_t* __restrict__ A2,
    const int8_t* __restrict__ B1, const int8_t* __restrict__ B2,
    int m0, int n0, int k0, uint32_t sb, int t)
{
#pragma unroll
    for (int i = 0; i < 2; i++) {
        int idx = t + i * 256, r = idx >> 2, c = idx & 3;
        uint32_t so = (uint32_t)(r * 64 + (((c ^ ((r >> 1) & 3))) << 4));
        size_t ga = (size_t)(m0 + r) * GK + k0 + c * 16;
        size_t gb = (size_t)(n0 + r) * GK + k0 + c * 16;
        cp_async16(sb +          so, A1 + ga);
        cp_async16(sb +  8192u + so, A2 + ga);
        cp_async16(sb + 16384u + so, B1 + gb);
        cp_async16(sb + 24576u + so, B2 + gb);
    }
}

template<bool SPLIT>
__global__ __launch_bounds__(256, 1) void gemm_s8(
    const int8_t* __restrict__ A1, const int8_t* __restrict__ A2,
    const float* __restrict__ sA, GArgs a0, GArgs a1, GArgs a2)
{
    extern __shared__ char smem[];
    const uint32_t sbase = smem_u32(smem);
    const GArgs ga = (blockIdx.z == 0) ? a0 : (blockIdx.z == 1) ? a1 : a2;
    const int t = threadIdx.x, lane = t & 31, wid = t >> 5;
    const int warp_m = wid >> 2, warp_n = wid & 3;
    const int m0 = blockIdx.y * 128;
    const int n0 = blockIdx.x * 128;

    int a_row[4], b_row[2];
    uint32_t a_sw[4], b_sw[2];
#pragma unroll
    for (int mt = 0; mt < 4; mt++) {
        a_row[mt] = warp_m * 64 + mt * 16 + (lane & 15);
        a_sw[mt]  = (uint32_t)((a_row[mt] >> 1) & 3);
    }
#pragma unroll
    for (int pt = 0; pt < 2; pt++) {
        b_row[pt] = warp_n * 32 + pt * 16 + (lane & 7) + ((lane >> 4) & 1) * 8;
        b_sw[pt]  = (uint32_t)((b_row[pt] >> 1) & 3);
    }
    const uint32_t a_ch = (uint32_t)(lane >> 4);
    const uint32_t b_ch = (uint32_t)((lane >> 3) & 1);

    int acc1[4][4][4], acc2[4][4][4];
#pragma unroll
    for (int i = 0; i < 4; i++)
#pragma unroll
        for (int j = 0; j < 4; j++)
#pragma unroll
            for (int q = 0; q < 4; q++) { acc1[i][j][q] = 0; acc2[i][j][q] = 0; }

    s8_load(A1, A2, ga.B1, ga.B2, m0, n0, 0,   sbase,            t); CP_COMMIT();
    s8_load(A1, A2, ga.B1, ga.B2, m0, n0, 64,  sbase + SSTG,     t); CP_COMMIT();
    s8_load(A1, A2, ga.B1, ga.B2, m0, n0, 128, sbase + 2 * SSTG, t); CP_COMMIT();

    uint32_t stg = 0;
    for (int ch = 0; ch < NCH8; ch++) {
        CP_WAIT2();
        __syncthreads();
        const uint32_t sb = sbase + stg * SSTG;

#pragma unroll
        for (int s = 0; s < 2; s++) {
            uint32_t Af1[4][4], Af2[4][4];
            uint32_t Bf1[2][4], Bf2[2][4];
#pragma unroll
            for (int mt = 0; mt < 4; mt++) {
                uint32_t c = (uint32_t)(s * 2) + a_ch;
                uint32_t off = (uint32_t)(a_row[mt] * 64) + ((c ^ a_sw[mt]) << 4);
                ldm_x4(Af1[mt], sb + off);
                ldm_x4(Af2[mt], sb + 8192u + off);
            }
#pragma unroll
            for (int pt = 0; pt < 2; pt++) {
                uint32_t c = (uint32_t)(s * 2) + b_ch;
                uint32_t off = (uint32_t)(b_row[pt] * 64) + ((c ^ b_sw[pt]) << 4);
                ldm_x4(Bf1[pt], sb + 16384u + off);
                ldm_x4(Bf2[pt], sb + 24576u + off);
            }
#pragma unroll
            for (int mt = 0; mt < 4; mt++)
#pragma unroll
                for (int nt = 0; nt < 4; nt++) {
                    const int pt = nt >> 1, hl = (nt & 1) * 2;
                    mma_s8(acc1[mt][nt], Af1[mt], Bf1[pt][hl], Bf1[pt][hl+1]);
                    mma_s8(acc2[mt][nt], Af1[mt], Bf2[pt][hl], Bf2[pt][hl+1]);
                    mma_s8(acc2[mt][nt], Af2[mt], Bf1[pt][hl], Bf1[pt][hl+1]);
                }
        }
        __syncthreads();
        if (ch + 3 < NCH8)
            s8_load(A1, A2, ga.B1, ga.B2, m0, n0, (ch + 3) * 64,
                    sbase + stg * SSTG, t);
        CP_COMMIT();
        stg = (stg == 2) ? 0 : stg + 1;
    }

    const float R = 1.f / 254.f;
#pragma unroll
    for (int mt = 0; mt < 4; mt++) {
        const int r0 = m0 + warp_m * 64 + mt * 16 + (lane >> 2);
        const float sa0 = sA[r0], sa1 = sA[r0 + 8];
#pragma unroll
        for (int nt = 0; nt < 4; nt++) {
            const int cc = n0 + warp_n * 32 + nt * 8 + (lane & 3) * 2;
            const float sb0 = ga.sB[cc], sb1 = ga.sB[cc + 1];
            const float bx = ga.bias[cc], by = ga.bias[cc + 1];
            float v0 = ((float)acc1[mt][nt][0] + (float)acc2[mt][nt][0] * R) * (sa0 * sb0) + bx;
            float v1 = ((float)acc1[mt][nt][1] + (float)acc2[mt][nt][1] * R) * (sa0 * sb1) + by;
            float v2 = ((float)acc1[mt][nt][2] + (float)acc2[mt][nt][2] * R) * (sa1 * sb0) + bx;
            float v3 = ((float)acc1[mt][nt][3] + (float)acc2[mt][nt][3] * R) * (sa1 * sb1) + by;
            if (!SPLIT) {
                *(float2*)(ga.C + (size_t)r0 * GK + cc)       = make_float2(v0, v1);
                *(float2*)(ga.C + (size_t)(r0 + 8) * GK + cc) = make_float2(v2, v3);
            } else {
                uint32_t h0 = packbf(v0, v1);
                uint32_t l0 = packbf(v0 - bf_lo(h0), v1 - bf_hi(h0));
                uint32_t h1 = packbf(v2, v3);
                uint32_t l1 = packbf(v2 - bf_lo(h1), v3 - bf_hi(h1));
                *(uint32_t*)(ga.Ch + (size_t)r0 * GK + cc)       = h0;
                *(uint32_t*)(ga.Cl + (size_t)r0 * GK + cc)       = l0;
                *(uint32_t*)(ga.Ch + (size_t)(r0 + 8) * GK + cc) = h1;
                *(uint32_t*)(ga.Cl + (size_t)(r0 + 8) * GK + cc) = l1;
            }
        }
    }
}

// ---------------------------------------------------------------------------
// Hybrid flash attention (causal): int8 two-level QK, split-bf16 PV
// with register-resident P. Heavy q-tiles scheduled first.
// smem: [0,49152) two KV stages: per stage k1 4K | k2 4K | vh 8K | vl 8K;
//       [49152,+512) k-scale double buffer; Q int8 staged at [0,32K) prologue.
// ---------------------------------------------------------------------------
#define FQT 256
#define FKT 64
#define STG_SZ 24576u
#define SCOFF 49152u
#define FA_SMEM 49664

__global__ __launch_bounds__(256, 1) void flash_hyb(
    const int8_t* __restrict__ q1g, const int8_t* __restrict__ q2g,
    const float* __restrict__ sqg,
    const int8_t* __restrict__ k1g, const int8_t* __restrict__ k2g,
    const float* __restrict__ skg,
    const __nv_bfloat16* __restrict__ Vh, const __nv_bfloat16* __restrict__ Vl,
    float* __restrict__ O)
{
    extern __shared__ char smem[];
    const uint32_t sb = smem_u32(smem);
    const int t = threadIdx.x, lane = t & 31, wid = t >> 5;
    const int qt = (int)gridDim.x - 1 - (int)blockIdx.x;   // heavy tiles first
    const int bh = blockIdx.y;
    const int b = bh >> 5, h = bh & 31;
    const int q0 = qt * FQT;
    const int qrow0 = b * S_ + q0;
    const int krow0 = b * S_;
    const int hoff = h * D_;
    const size_t vbase = ((size_t)b * S_) * E_ + hoff;   // bf16 V layout
    const float* skh = skg + (size_t)h * M_ + b * S_;
    const float R254 = 1.f / 254.f;
    const float CEXP = SCALE_ * 1.4426950408889634f;

    // ---- stage Q (int8, both levels) at [0,32K), hoist fragments ----
#pragma unroll
    for (int i = 0; i < 4; i++) {
        int idx = t + i * 256, r = idx >> 2, c = idx & 3;
        uint32_t so = (uint32_t)(r * 64 + ((c ^ ((r >> 1) & 3)) << 4));
        size_t g = (size_t)(qrow0 + r) * 2048 + hoff + c * 16;
        cp_async16(sb +          so, q1g + g);
        cp_async16(sb + 16384u + so, q2g + g);
    }
    CP_COMMIT(); CP_WAIT0();
    __syncthreads();

    uint32_t fq1[2][2][4], fq2[2][2][4];
#pragma unroll
    for (int mt = 0; mt < 2; mt++)
#pragma unroll
        for (int kc = 0; kc < 2; kc++) {
            int row = wid * 32 + mt * 16 + (lane & 15);
            uint32_t c = (uint32_t)(kc * 2 + (lane >> 4));
            uint32_t off = (uint32_t)(row * 64) + ((c ^ (uint32_t)((row >> 1) & 3)) << 4);
            ldm_x4(fq1[mt][kc], sb + off);
            ldm_x4(fq2[mt][kc], sb + 16384u + off);
        }
    float sqv[2][2];
#pragma unroll
    for (int mt = 0; mt < 2; mt++)
#pragma unroll
        for (int rr = 0; rr < 2; rr++)
            sqv[mt][rr] = sqg[(size_t)h * M_ + qrow0 + wid * 32 + mt * 16
                              + (lane >> 2) + rr * 8];
    __syncthreads();   // Q area now reusable for KV stages

    const int jmax = 4 * (qt + 1);
    {   // KV tile 0 -> stage 0
        int r = t >> 2, c = t & 3;
        uint32_t so = (uint32_t)(r * 64 + ((c ^ ((r >> 1) & 3)) << 4));
        size_t gk = (size_t)(krow0 + r) * 2048 + hoff + c * 16;
        cp_async16(sb +         so, k1g + gk);
        cp_async16(sb + 4096u + so, k2g + gk);
        if (t < 16) cp_async16(sb + SCOFF + t * 16u, skh + t * 4);
    }
#pragma unroll
    for (int i = 0; i < 2; i++) {      // V bf16: 64 rows x 128B per level
        int idx = t + i * 256, r = idx >> 3, c = idx & 7;
        uint32_t so = (uint32_t)(r * 128 + ((c ^ (r & 7)) << 4));
        size_t g = vbase + (size_t)r * E_ + c * 8;
        cp_async16(sb +  8192u + so, Vh + g);
        cp_async16(sb + 16384u + so, Vl + g);
    }
    CP_COMMIT();

    float Oacc[2][8][4];
#pragma unroll
    for (int i = 0; i < 2; i++)
#pragma unroll
        for (int j = 0; j < 8; j++)
#pragma unroll
            for (int q = 0; q < 4; q++) Oacc[i][j][q] = 0.f;
    float m_i[2][2] = {{-1e30f, -1e30f}, {-1e30f, -1e30f}};
    float l_i[2][2] = {{0.f, 0.f}, {0.f, 0.f}};

    for (int jt = 0; jt < jmax; jt++) {
        const int k0 = jt * FKT;
        __syncthreads();
        if (jt + 1 < jmax) {
            uint32_t st = (uint32_t)((jt + 1) & 1) * STG_SZ;
            {
                int r = t >> 2, c = t & 3;
                uint32_t so = (uint32_t)(r * 64 + ((c ^ ((r >> 1) & 3)) << 4));
                size_t gk = (size_t)(krow0 + k0 + FKT + r) * 2048 + hoff + c * 16;
                cp_async16(sb + st +         so, k1g + gk);
                cp_async16(sb + st + 4096u + so, k2g + gk);
                if (t < 16)
                    cp_async16(sb + SCOFF + (uint32_t)((jt + 1) & 1) * 256u + t * 16u,
                               skh + k0 + FKT + t * 4);
            }
#pragma unroll
            for (int i = 0; i < 2; i++) {
                int idx = t + i * 256, r = idx >> 3, c = idx & 7;
                uint32_t so = (uint32_t)(r * 128 + ((c ^ (r & 7)) << 4));
                size_t g = vbase + (size_t)(k0 + FKT + r) * E_ + c * 8;
                cp_async16(sb + st +  8192u + so, Vh + g);
                cp_async16(sb + st + 16384u + so, Vl + g);
            }
        }
        CP_COMMIT(); CP_WAIT1();
        __syncthreads();
        const uint32_t st = sb + (uint32_t)(jt & 1) * STG_SZ;
        const float* sks = (const float*)(smem + SCOFF + (jt & 1) * 256);

        // ---- S = Q K^T, int8 two-level, key halves ----
        float sacc[2][8][4];
#pragma unroll
        for (int kh = 0; kh < 2; kh++) {
            int i1[2][4][4], i2[2][4][4];
#pragma unroll
            for (int i = 0; i < 2; i++)
#pragma unroll
                for (int j = 0; j < 4; j++)
#pragma unroll
                    for (int q = 0; q < 4; q++) { i1[i][j][q] = 0; i2[i][j][q] = 0; }
#pragma unroll
            for (int kc = 0; kc < 2; kc++) {
                uint32_t bk1[2][4], bk2[2][4];
#pragma unroll
                for (int np2 = 0; np2 < 2; np2++) {
                    int row = (kh * 2 + np2) * 16 + (lane & 7) + ((lane >> 4) & 1) * 8;
                    uint32_t c = (uint32_t)(kc * 2 + ((lane >> 3) & 1));
                    uint32_t off = (uint32_t)(row * 64) + ((c ^ (uint32_t)((row >> 1) & 3)) << 4);
                    ldm_x4(bk1[np2], st + off);
                    ldm_x4(bk2[np2], st + 4096u + off);
                }
#pragma unroll
                for (int mt = 0; mt < 2; mt++)
#pragma unroll
                    for (int np2 = 0; np2 < 2; np2++)
#pragma unroll
                        for (int nt2 = 0; nt2 < 2; nt2++) {
                            const int sl = np2 * 2 + nt2, hl = nt2 * 2;
                            mma_s8(i1[mt][sl], fq1[mt][kc], bk1[np2][hl], bk1[np2][hl+1]);
                            mma_s8(i2[mt][sl], fq1[mt][kc], bk2[np2][hl], bk2[np2][hl+1]);
                            mma_s8(i2[mt][sl], fq2[mt][kc], bk1[np2][hl], bk1[np2][hl+1]);
                        }
            }
#pragma unroll
            for (int mt = 0; mt < 2; mt++)
#pragma unroll
                for (int sl = 0; sl < 4; sl++) {
                    const int nt = kh * 4 + sl;
                    const int c0 = nt * 8 + (lane & 3) * 2;
                    const float k0s = sks[c0], k1s = sks[c0 + 1];
#pragma unroll
                    for (int rr = 0; rr < 2; rr++) {
                        sacc[mt][nt][rr*2]   = sqv[mt][rr] * k0s *
                            ((float)i1[mt][sl][rr*2]   + (float)i2[mt][sl][rr*2]   * R254);
                        sacc[mt][nt][rr*2+1] = sqv[mt][rr] * k1s *
                            ((float)i1[mt][sl][rr*2+1] + (float)i2[mt][sl][rr*2+1] * R254);
                    }
                }
        }

        // ---- causal mask ----
        if (k0 + FKT - 1 > q0) {
#pragma unroll
            for (int mt = 0; mt < 2; mt++)
#pragma unroll
                for (int nt = 0; nt < 8; nt++)
#pragma unroll
                    for (int e = 0; e < 4; e++) {
                        int qrow = q0 + wid * 32 + mt * 16 + (lane >> 2) + (e >> 1) * 8;
                        int kcol = k0 + nt * 8 + (lane & 3) * 2 + (e & 1);
                        if (kcol > qrow) sacc[mt][nt][e] = -1e30f;
                    }
        }

        // ---- online softmax ----
#pragma unroll
        for (int mt = 0; mt < 2; mt++)
#pragma unroll
            for (int rr = 0; rr < 2; rr++) {
                float mx = -1e30f;
#pragma unroll
                for (int nt = 0; nt < 8; nt++)
                    mx = fmaxf(mx, fmaxf(sacc[mt][nt][rr*2], sacc[mt][nt][rr*2+1]));
                mx = fmaxf(mx, __shfl_xor_sync(0xffffffffu, mx, 1));
                mx = fmaxf(mx, __shfl_xor_sync(0xffffffffu, mx, 2));
                const float m_new = fmaxf(m_i[mt][rr], mx);
                const float mC = m_new * CEXP;
                const float alpha = ex2(m_i[mt][rr] * CEXP - mC);
                float rs = 0.f;
#pragma unroll
                for (int nt = 0; nt < 8; nt++) {
                    float p0 = ex2(sacc[mt][nt][rr*2]   * CEXP - mC);
                    float p1 = ex2(sacc[mt][nt][rr*2+1] * CEXP - mC);
                    sacc[mt][nt][rr*2] = p0; sacc[mt][nt][rr*2+1] = p1;
                    rs += p0 + p1;
                }
                rs += __shfl_xor_sync(0xffffffffu, rs, 1);
                rs += __shfl_xor_sync(0xffffffffu, rs, 2);
                l_i[mt][rr] = l_i[mt][rr] * alpha + rs;
                m_i[mt][rr] = m_new;
#pragma unroll
                for (int nd = 0; nd < 8; nd++) {
                    Oacc[mt][nd][rr*2]   *= alpha;
                    Oacc[mt][nd][rr*2+1] *= alpha;
                }
            }

        // ---- O += P V (register-resident split-bf16 P; bf16 V) ----
#pragma unroll
        for (int kc = 0; kc < 4; kc++) {
            uint32_t ph[2][4], pl[2][4];
#pragma unroll
            for (int mt = 0; mt < 2; mt++) {
                float p00 = sacc[mt][2*kc][0],   p01 = sacc[mt][2*kc][1];
                float p10 = sacc[mt][2*kc][2],   p11 = sacc[mt][2*kc][3];
                float p20 = sacc[mt][2*kc+1][0], p21 = sacc[mt][2*kc+1][1];
                float p30 = sacc[mt][2*kc+1][2], p31 = sacc[mt][2*kc+1][3];
                ph[mt][0] = packbf(p00, p01);
                ph[mt][1] = packbf(p10, p11);
                ph[mt][2] = packbf(p20, p21);
                ph[mt][3] = packbf(p30, p31);
                pl[mt][0] = packbf(p00 - bf_lo(ph[mt][0]), p01 - bf_hi(ph[mt][0]));
                pl[mt][1] = packbf(p10 - bf_lo(ph[mt][1]), p11 - bf_hi(ph[mt][1]));
                pl[mt][2] = packbf(p20 - bf_lo(ph[mt][2]), p21 - bf_hi(ph[mt][2]));
                pl[mt][3] = packbf(p30 - bf_lo(ph[mt][3]), p31 - bf_hi(ph[mt][3]));
            }
#pragma unroll
            for (int ndp = 0; ndp < 4; ndp++) {
                int row = kc * 16 + (lane & 7) + ((lane >> 3) & 1) * 8;
                uint32_t c = (uint32_t)(2 * ndp) + (uint32_t)(lane >> 4);
                uint32_t off = (uint32_t)(row * 128) + ((c ^ (uint32_t)(row & 7)) << 4);
                uint32_t bvh[4], bvl[4];
                ldm_x4t(bvh, st +  8192u + off);
                ldm_x4t(bvl, st + 16384u + off);
#pragma unroll
                for (int nt2 = 0; nt2 < 2; nt2++) {
                    const int nd = ndp * 2 + nt2;
#pragma unroll
                    for (int mt = 0; mt < 2; mt++) {
                        mma16816(Oacc[mt][nd], ph[mt], bvh[nt2*2], bvh[nt2*2+1]);
                        mma16816(Oacc[mt][nd], ph[mt], bvl[nt2*2], bvl[nt2*2+1]);
                        mma16816(Oacc[mt][nd], pl[mt], bvh[nt2*2], bvh[nt2*2+1]);
                    }
                }
            }
        }
    }

    // ---- epilogue: normalize, fp32 store ----
#pragma unroll
    for (int mt = 0; mt < 2; mt++)
#pragma unroll
        for (int rr = 0; rr < 2; rr++) {
            const int row = wid * 32 + mt * 16 + (lane >> 2) + rr * 8;
            const float inv = 1.f / l_i[mt][rr];
            const size_t rb = (size_t)(qrow0 + row) * 2048 + hoff + (lane & 3) * 2;
#pragma unroll
            for (int nd = 0; nd < 8; nd++) {
                float v0 = Oacc[mt][nd][rr*2]   * inv;
                float v1 = Oacc[mt][nd][rr*2+1] * inv;
                *(float2*)(O + rb + nd * 8) = make_float2(v0, v1);
            }
        }
}

// ---------------------------------------------------------------------------
extern "C" void kernel_launch(void* const* d_in, const int* in_sizes, int n_in,
                              void* d_out, int out_size)
{
    const float* x  = (const float*)d_in[0];
    const float* Wq = (const float*)d_in[1];
    const float* bq = (const float*)d_in[2];
    const float* Wk = (const float*)d_in[3];
    const float* bk = (const float*)d_in[4];
    const float* Wv = (const float*)d_in[5];
    const float* bv = (const float*)d_in[6];
    const float* Wo = (const float*)d_in[7];
    const float* bo = (const float*)d_in[8];
    float* out = (float*)d_out;

    int8_t *x1, *x2, *a1, *a2;
    int8_t *wq1, *wq2, *wk1, *wk2, *wv1, *wv2, *wo1, *wo2;
    int8_t *q1, *q2, *k1, *k2;
    float *sx, *sa, *swq, *swk, *swv, *swo, *attn;
    float *qf, *kf, *sq, *sk;
    __nv_bfloat16 *vh, *vl;
    cudaGetSymbolAddress((void**)&x1, g_x1);
    cudaGetSymbolAddress((void**)&x2, g_x2);
    cudaGetSymbolAddress((void**)&sx, g_sx);
    cudaGetSymbolAddress((void**)&a1, g_a1);
    cudaGetSymbolAddress((void**)&a2, g_a2);
    cudaGetSymbolAddress((void**)&sa, g_sa);
    cudaGetSymbolAddress((void**)&attn, g_attn);
    cudaGetSymbolAddress((void**)&wq1, g_wq1);
    cudaGetSymbolAddress((void**)&wq2, g_wq2);
    cudaGetSymbolAddress((void**)&swq, g_swq);
    cudaGetSymbolAddress((void**)&wk1, g_wk1);
    cudaGetSymbolAddress((void**)&wk2, g_wk2);
    cudaGetSymbolAddress((void**)&swk, g_swk);
    cudaGetSymbolAddress((void**)&wv1, g_wv1);
    cudaGetSymbolAddress((void**)&wv2, g_wv2);
    cudaGetSymbolAddress((void**)&swv, g_swv);
    cudaGetSymbolAddress((void**)&wo1, g_wo1);
    cudaGetSymbolAddress((void**)&wo2, g_wo2);
    cudaGetSymbolAddress((void**)&swo, g_swo);
    cudaGetSymbolAddress((void**)&qf, g_qf);
    cudaGetSymbolAddress((void**)&kf, g_kf);
    cudaGetSymbolAddress((void**)&q1, g_q1);
    cudaGetSymbolAddress((void**)&q2, g_q2);
    cudaGetSymbolAddress((void**)&k1, g_k1);
    cudaGetSymbolAddress((void**)&k2, g_k2);
    cudaGetSymbolAddress((void**)&sq, g_sq);
    cudaGetSymbolAddress((void**)&sk, g_sk);
    cudaGetSymbolAddress((void**)&vh, g_vh);
    cudaGetSymbolAddress((void**)&vl, g_vl);

    cudaFuncSetAttribute(gemm_s8<false>,
                         cudaFuncAttributeMaxDynamicSharedMemorySize, GS8_SMEM);
    cudaFuncSetAttribute(gemm_s8<true>,
                         cudaFuncAttributeMaxDynamicSharedMemorySize, GS8_SMEM);
    cudaFuncSetAttribute(flash_hyb,
                         cudaFuncAttributeMaxDynamicSharedMemorySize, FA_SMEM);

    rowquant<<<M_, 256>>>(x,  x1,  x2,  sx);
    rowquant<<<E_, 256>>>(Wq, wq1, wq2, swq);
    rowquant<<<E_, 256>>>(Wk, wk1, wk2, swk);
    rowquant<<<E_, 256>>>(Wv, wv1, wv2, swv);
    rowquant<<<E_, 256>>>(Wo, wo1, wo2, swo);

    GArgs aq{wq1, wq2, swq, bq, qf, nullptr, nullptr};
    GArgs ak{wk1, wk2, swk, bk, kf, nullptr, nullptr};
    GArgs av{wv1, wv2, swv, bv, nullptr, vh, vl};
    GArgs ao{wo1, wo2, swo, bo, out, nullptr, nullptr};

    dim3 gqk(E_ / 128, M_ / 128, 2);
    gemm_s8<false><<<gqk, 256, GS8_SMEM>>>(x1, x2, sx, aq, ak, ak);
    dim3 gv(E_ / 128, M_ / 128, 1);
    gemm_s8<true><<<gv, 256, GS8_SMEM>>>(x1, x2, sx, av, av, av);

    qkquant<<<dim3(M_, 2), 256>>>(qf, kf, q1, q2, sq, k1, k2, sk);

    dim3 ga(S_ / FQT, B_ * H_);
    flash_hyb<<<ga, 256, FA_SMEM>>>(q1, q2, sq, k1, k2, sk, vh, vl, attn);

    rowquant<<<M_, 256>>>(attn, a1, a2, sa);

    dim3 go(E_ / 128, M_ / 128, 1);
    gemm_s8<false><<<go, 256, GS8_SMEM>>>(a1, a2, sa, ao, ao, ao);
}

// round 11
// speedup vs baseline: 1.1677x; 1.0027x over previous
#include <cuda_runtime.h>
#include <cuda_bf16.h>
#include <cstdint>
#include <math.h>

#define B_ 2
#define S_ 2048
#define E_ 2048
#define H_ 32
#define D_ 64
#define M_ (B_*S_)
#define SCALE_ 0.125f

// ---------------- scratch ----------------
static __device__ __align__(128) int8_t g_x1[(size_t)M_ * E_];
static __device__ __align__(128) int8_t g_x2[(size_t)M_ * E_];
static __device__ __align__(128) float  g_sx[M_];
static __device__ __align__(128) int8_t g_a1[(size_t)M_ * E_];
static __device__ __align__(128) int8_t g_a2[(size_t)M_ * E_];
static __device__ __align__(128) float  g_sa[M_];
static __device__ __align__(128) float  g_attn[(size_t)M_ * E_];

static __device__ __align__(128) int8_t g_wq1[(size_t)E_ * E_];
static __device__ __align__(128) int8_t g_wq2[(size_t)E_ * E_];
static __device__ __align__(128) float  g_swq[E_];
static __device__ __align__(128) int8_t g_wk1[(size_t)E_ * E_];
static __device__ __align__(128) int8_t g_wk2[(size_t)E_ * E_];
static __device__ __align__(128) float  g_swk[E_];
static __device__ __align__(128) int8_t g_wv1[(size_t)E_ * E_];
static __device__ __align__(128) int8_t g_wv2[(size_t)E_ * E_];
static __device__ __align__(128) float  g_swv[E_];
static __device__ __align__(128) int8_t g_wo1[(size_t)E_ * E_];
static __device__ __align__(128) int8_t g_wo2[(size_t)E_ * E_];
static __device__ __align__(128) float  g_swo[E_];

static __device__ __align__(128) int8_t g_q1[(size_t)M_ * E_];
static __device__ __align__(128) int8_t g_q2[(size_t)M_ * E_];
static __device__ __align__(128) int8_t g_k1[(size_t)M_ * E_];
static __device__ __align__(128) int8_t g_k2[(size_t)M_ * E_];
static __device__ __align__(128) float  g_sq[(size_t)H_ * M_];
static __device__ __align__(128) float  g_sk[(size_t)H_ * M_];

static __device__ __align__(128) __nv_bfloat16 g_vh[(size_t)M_ * E_];
static __device__ __align__(128) __nv_bfloat16 g_vl[(size_t)M_ * E_];

// ---------------- helpers ----------------
__device__ __forceinline__ uint32_t smem_u32(const void* p) {
    uint32_t a;
    asm("{ .reg .u64 t; cvta.to.shared.u64 t, %1; cvt.u32.u64 %0, t; }"
        : "=r"(a) : "l"(p));
    return a;
}
__device__ __forceinline__ void cp_async16(uint32_t saddr, const void* gaddr) {
    asm volatile("cp.async.cg.shared.global [%0], [%1], 16;\n"
                 :: "r"(saddr), "l"(gaddr));
}
#define CP_COMMIT() asm volatile("cp.async.commit_group;\n" ::: "memory")
#define CP_WAIT0()  asm volatile("cp.async.wait_group 0;\n" ::: "memory")
#define CP_WAIT1()  asm volatile("cp.async.wait_group 1;\n" ::: "memory")
#define CP_WAIT2()  asm volatile("cp.async.wait_group 2;\n" ::: "memory")

__device__ __forceinline__ void ldm_x4(uint32_t* r, uint32_t addr) {
    asm volatile("ldmatrix.sync.aligned.m8n8.x4.shared.b16 {%0,%1,%2,%3}, [%4];"
                 : "=r"(r[0]), "=r"(r[1]), "=r"(r[2]), "=r"(r[3]) : "r"(addr));
}
__device__ __forceinline__ void ldm_x4t(uint32_t* r, uint32_t addr) {
    asm volatile("ldmatrix.sync.aligned.m8n8.x4.trans.shared.b16 {%0,%1,%2,%3}, [%4];"
                 : "=r"(r[0]), "=r"(r[1]), "=r"(r[2]), "=r"(r[3]) : "r"(addr));
}
__device__ __forceinline__ void mma16816(float* d, const uint32_t* a,
                                         uint32_t b0, uint32_t b1) {
    asm volatile(
        "mma.sync.aligned.m16n8k16.row.col.f32.bf16.bf16.f32 "
        "{%0,%1,%2,%3}, {%4,%5,%6,%7}, {%8,%9}, {%0,%1,%2,%3};"
        : "+f"(d[0]), "+f"(d[1]), "+f"(d[2]), "+f"(d[3])
        : "r"(a[0]), "r"(a[1]), "r"(a[2]), "r"(a[3]), "r"(b0), "r"(b1));
}
__device__ __forceinline__ void mma_s8(int* d, const uint32_t* a,
                                       uint32_t b0, uint32_t b1) {
    asm volatile(
        "mma.sync.aligned.m16n8k32.row.col.s32.s8.s8.s32 "
        "{%0,%1,%2,%3}, {%4,%5,%6,%7}, {%8,%9}, {%0,%1,%2,%3};"
        : "+r"(d[0]), "+r"(d[1]), "+r"(d[2]), "+r"(d[3])
        : "r"(a[0]), "r"(a[1]), "r"(a[2]), "r"(a[3]), "r"(b0), "r"(b1));
}
__device__ __forceinline__ uint32_t packbf(float lo, float hi) {
    uint32_t d;
    asm("cvt.rn.bf16x2.f32 %0, %1, %2;" : "=r"(d) : "f"(hi), "f"(lo));
    return d;
}
__device__ __forceinline__ float bf_lo(uint32_t u) { return __uint_as_float(u << 16); }
__device__ __forceinline__ float bf_hi(uint32_t u) { return __uint_as_float(u & 0xffff0000u); }
__device__ __forceinline__ float ex2(float x) {
    float y; asm("ex2.approx.f32 %0, %1;" : "=f"(y) : "f"(x)); return y;
}

// ---------------------------------------------------------------------------
// Row-wise two-level int8 quantization over 2048-col rows.
// ---------------------------------------------------------------------------
struct RQArgs { const float* src; int8_t* q1; int8_t* q2; float* s; int rows; };

__device__ __forceinline__ void rowquant_body(
    const float* __restrict__ x, int8_t* __restrict__ q1,
    int8_t* __restrict__ q2, float* __restrict__ s, int row, int t,
    float* wmax)
{
    const float* xr = x + (size_t)row * 2048 + t * 8;
    float4 v0 = ((const float4*)xr)[0];
    float4 v1 = ((const float4*)xr)[1];
    float vv[8] = {v0.x, v0.y, v0.z, v0.w, v1.x, v1.y, v1.z, v1.w};
    float m = 0.f;
#pragma unroll
    for (int j = 0; j < 8; j++) m = fmaxf(m, fabsf(vv[j]));
#pragma unroll
    for (int o = 16; o; o >>= 1) m = fmaxf(m, __shfl_xor_sync(~0u, m, o));
    if ((t & 31) == 0) wmax[t >> 5] = m;
    __syncthreads();
    float mm = wmax[0];
#pragma unroll
    for (int i = 1; i < 8; i++) mm = fmaxf(mm, wmax[i]);
    mm = fmaxf(mm, 1e-20f);
    if (t == 0) s[row] = mm * (1.f / 127.f);
    const float inv = 127.f / mm;

    uint32_t p1[2] = {0, 0}, p2[2] = {0, 0};
#pragma unroll
    for (int j = 0; j < 8; j++) {
        float xs = vv[j] * inv;
        float qf = rintf(xs);
        float rf = rintf((xs - qf) * 254.f);
        int iq = (int)qf, ir = (int)rf;
        p1[j >> 2] |= (uint32_t)(iq & 0xff) << ((j & 3) * 8);
        p2[j >> 2] |= (uint32_t)(ir & 0xff) << ((j & 3) * 8);
    }
    ((uint32_t*)q1)[row * 512 + t * 2]     = p1[0];
    ((uint32_t*)q1)[row * 512 + t * 2 + 1] = p1[1];
    ((uint32_t*)q2)[row * 512 + t * 2]     = p2[0];
    ((uint32_t*)q2)[row * 512 + t * 2 + 1] = p2[1];
}

__global__ __launch_bounds__(256) void rowquant(
    const float* __restrict__ x, int8_t* __restrict__ q1,
    int8_t* __restrict__ q2, float* __restrict__ s)
{
    __shared__ float wmax[8];
    rowquant_body(x, q1, q2, s, blockIdx.x, threadIdx.x, wmax);
}

__global__ __launch_bounds__(256) void rowquant5(
    RQArgs a0, RQArgs a1, RQArgs a2, RQArgs a3, RQArgs a4)
{
    __shared__ float wmax[8];
    RQArgs a = (blockIdx.y == 0) ? a0 : (blockIdx.y == 1) ? a1
             : (blockIdx.y == 2) ? a2 : (blockIdx.y == 3) ? a3 : a4;
    if ((int)blockIdx.x >= a.rows) return;
    rowquant_body(a.src, a.q1, a.q2, a.s, blockIdx.x, threadIdx.x, wmax);
}

// ---------------------------------------------------------------------------
// Two-level int8 GEMM.
// EPI 0: fp32 C + bias.
// EPI 1: split bf16 (hi, lo) C + bias (for V).
// EPI 2: fused per-(row, 64-col head) two-level int8 quant output + scales.
// ---------------------------------------------------------------------------
#define GK 2048
#define NCH8 32
#define SSTG 32768
#define GS8_SMEM (3 * SSTG)

struct GArgs {
    const int8_t *B1, *B2;
    const float* sB;
    const float* bias;
    float* C;
    __nv_bfloat16 *Ch, *Cl;
    int8_t *Q1, *Q2;
    float* SQ;
};

__device__ __forceinline__ void s8_load(
    const int8_t* __restrict__ A1, const int8_t* __restrict__ A2,
    const int8_t* __restrict__ B1, const int8_t* __restrict__ B2,
    int m0, int n0, int k0, uint32_t sb, int t)
{
#pragma unroll
    for (int i = 0; i < 2; i++) {
        int idx = t + i * 256, r = idx >> 2, c = idx & 3;
        uint32_t so = (uint32_t)(r * 64 + (((c ^ ((r >> 1) & 3))) << 4));
        size_t ga = (size_t)(m0 + r) * GK + k0 + c * 16;
        size_t gb = (size_t)(n0 + r) * GK + k0 + c * 16;
        cp_async16(sb +          so, A1 + ga);
        cp_async16(sb +  8192u + so, A2 + ga);
        cp_async16(sb + 16384u + so, B1 + gb);
        cp_async16(sb + 24576u + so, B2 + gb);
    }
}

template<int EPI>
__global__ __launch_bounds__(256, 1) void gemm_s8(
    const int8_t* __restrict__ A1, const int8_t* __restrict__ A2,
    const float* __restrict__ sA, GArgs a0, GArgs a1, GArgs a2)
{
    extern __shared__ char smem[];
    const uint32_t sbase = smem_u32(smem);
    const GArgs ga = (blockIdx.z == 0) ? a0 : (blockIdx.z == 1) ? a1 : a2;
    const int t = threadIdx.x, lane = t & 31, wid = t >> 5;
    const int warp_m = wid >> 2, warp_n = wid & 3;
    const int m0 = blockIdx.y * 128;
    const int n0 = blockIdx.x * 128;

    int a_row[4], b_row[2];
    uint32_t a_sw[4], b_sw[2];
#pragma unroll
    for (int mt = 0; mt < 4; mt++) {
        a_row[mt] = warp_m * 64 + mt * 16 + (lane & 15);
        a_sw[mt]  = (uint32_t)((a_row[mt] >> 1) & 3);
    }
#pragma unroll
    for (int pt = 0; pt < 2; pt++) {
        b_row[pt] = warp_n * 32 + pt * 16 + (lane & 7) + ((lane >> 4) & 1) * 8;
        b_sw[pt]  = (uint32_t)((b_row[pt] >> 1) & 3);
    }
    const uint32_t a_ch = (uint32_t)(lane >> 4);
    const uint32_t b_ch = (uint32_t)((lane >> 3) & 1);

    int acc1[4][4][4], acc2[4][4][4];
#pragma unroll
    for (int i = 0; i < 4; i++)
#pragma unroll
        for (int j = 0; j < 4; j++)
#pragma unroll
            for (int q = 0; q < 4; q++) { acc1[i][j][q] = 0; acc2[i][j][q] = 0; }

    s8_load(A1, A2, ga.B1, ga.B2, m0, n0, 0,   sbase,            t); CP_COMMIT();
    s8_load(A1, A2, ga.B1, ga.B2, m0, n0, 64,  sbase + SSTG,     t); CP_COMMIT();
    s8_load(A1, A2, ga.B1, ga.B2, m0, n0, 128, sbase + 2 * SSTG, t); CP_COMMIT();

    uint32_t stg = 0;
    for (int ch = 0; ch < NCH8; ch++) {
        CP_WAIT2();
        __syncthreads();
        const uint32_t sb = sbase + stg * SSTG;

#pragma unroll
        for (int s = 0; s < 2; s++) {
            uint32_t Af1[4][4], Af2[4][4];
            uint32_t Bf1[2][4], Bf2[2][4];
#pragma unroll
            for (int mt = 0; mt < 4; mt++) {
                uint32_t c = (uint32_t)(s * 2) + a_ch;
                uint32_t off = (uint32_t)(a_row[mt] * 64) + ((c ^ a_sw[mt]) << 4);
                ldm_x4(Af1[mt], sb + off);
                ldm_x4(Af2[mt], sb + 8192u + off);
            }
#pragma unroll
            for (int pt = 0; pt < 2; pt++) {
                uint32_t c = (uint32_t)(s * 2) + b_ch;
                uint32_t off = (uint32_t)(b_row[pt] * 64) + ((c ^ b_sw[pt]) << 4);
                ldm_x4(Bf1[pt], sb + 16384u + off);
                ldm_x4(Bf2[pt], sb + 24576u + off);
            }
#pragma unroll
            for (int mt = 0; mt < 4; mt++)
#pragma unroll
                for (int nt = 0; nt < 4; nt++) {
                    const int pt = nt >> 1, hl = (nt & 1) * 2;
                    mma_s8(acc1[mt][nt], Af1[mt], Bf1[pt][hl], Bf1[pt][hl+1]);
                    mma_s8(acc2[mt][nt], Af1[mt], Bf2[pt][hl], Bf2[pt][hl+1]);
                    mma_s8(acc2[mt][nt], Af2[mt], Bf1[pt][hl], Bf1[pt][hl+1]);
                }
        }
        __syncthreads();
        if (ch + 3 < NCH8)
            s8_load(A1, A2, ga.B1, ga.B2, m0, n0, (ch + 3) * 64,
                    sbase + stg * SSTG, t);
        CP_COMMIT();
        stg = (stg == 2) ? 0 : stg + 1;
    }

    const float R = 1.f / 254.f;
    if (EPI == 0 || EPI == 1) {
#pragma unroll
        for (int mt = 0; mt < 4; mt++) {
            const int r0 = m0 + warp_m * 64 + mt * 16 + (lane >> 2);
            const float sa0 = sA[r0], sa1 = sA[r0 + 8];
#pragma unroll
            for (int nt = 0; nt < 4; nt++) {
                const int cc = n0 + warp_n * 32 + nt * 8 + (lane & 3) * 2;
                const float sb0 = ga.sB[cc], sb1 = ga.sB[cc + 1];
                const float bx = ga.bias[cc], by = ga.bias[cc + 1];
                float v0 = ((float)acc1[mt][nt][0] + (float)acc2[mt][nt][0] * R) * (sa0 * sb0) + bx;
                float v1 = ((float)acc1[mt][nt][1] + (float)acc2[mt][nt][1] * R) * (sa0 * sb1) + by;
                float v2 = ((float)acc1[mt][nt][2] + (float)acc2[mt][nt][2] * R) * (sa1 * sb0) + bx;
                float v3 = ((float)acc1[mt][nt][3] + (float)acc2[mt][nt][3] * R) * (sa1 * sb1) + by;
                if (EPI == 0) {
                    *(float2*)(ga.C + (size_t)r0 * GK + cc)       = make_float2(v0, v1);
                    *(float2*)(ga.C + (size_t)(r0 + 8) * GK + cc) = make_float2(v2, v3);
                } else {
                    uint32_t h0 = packbf(v0, v1);
                    uint32_t l0 = packbf(v0 - bf_lo(h0), v1 - bf_hi(h0));
                    uint32_t h1 = packbf(v2, v3);
                    uint32_t l1 = packbf(v2 - bf_lo(h1), v3 - bf_hi(h1));
                    *(uint32_t*)(ga.Ch + (size_t)r0 * GK + cc)       = h0;
                    *(uint32_t*)(ga.Cl + (size_t)r0 * GK + cc)       = l0;
                    *(uint32_t*)(ga.Ch + (size_t)(r0 + 8) * GK + cc) = h1;
                    *(uint32_t*)(ga.Cl + (size_t)(r0 + 8) * GK + cc) = l1;
                }
            }
        }
    } else {
        // EPI == 2: fused per-(row, 64-col head) two-level int8 quantization
        CP_WAIT0();
        __syncthreads();
        float* red = (float*)smem;      // 8 warps x 64 rows
        const int rbase = wid * 64;
#pragma unroll
        for (int mt = 0; mt < 4; mt++) {
            const int r0g = m0 + warp_m * 64 + mt * 16 + (lane >> 2);
            const float sa0 = sA[r0g], sa1 = sA[r0g + 8];
#pragma unroll
            for (int rr = 0; rr < 2; rr++) {
                const float sa = rr ? sa1 : sa0;
                float mx = 0.f;
#pragma unroll
                for (int nt = 0; nt < 4; nt++) {
                    const int cc = n0 + warp_n * 32 + nt * 8 + (lane & 3) * 2;
                    float v0 = ((float)acc1[mt][nt][rr*2]   + (float)acc2[mt][nt][rr*2]   * R)
                               * (sa * ga.sB[cc])     + ga.bias[cc];
                    float v1 = ((float)acc1[mt][nt][rr*2+1] + (float)acc2[mt][nt][rr*2+1] * R)
                               * (sa * ga.sB[cc + 1]) + ga.bias[cc + 1];
                    mx = fmaxf(mx, fmaxf(fabsf(v0), fabsf(v1)));
                }
                mx = fmaxf(mx, __shfl_xor_sync(~0u, mx, 1));
                mx = fmaxf(mx, __shfl_xor_sync(~0u, mx, 2));
                red[rbase + mt * 16 + rr * 8 + (lane >> 2)] = mx;
            }
        }
        __syncthreads();
        const int h = (n0 >> 6) + (warp_n >> 1);
#pragma unroll
        for (int mt = 0; mt < 4; mt++) {
            const int r0g = m0 + warp_m * 64 + mt * 16 + (lane >> 2);
            const float sa0 = sA[r0g], sa1 = sA[r0g + 8];
#pragma unroll
            for (int rr = 0; rr < 2; rr++) {
                const float sa = rr ? sa1 : sa0;
                const int idx = mt * 16 + rr * 8 + (lane >> 2);
                float m2 = fmaxf(red[rbase + idx], red[(rbase ^ 64) + idx]);
                m2 = fmaxf(m2, 1e-20f);
                const int grow = r0g + rr * 8;
                if ((lane & 3) == 0)
                    ga.SQ[(size_t)h * M_ + grow] = m2 * (1.f / 127.f);
                const float inv = 127.f / m2;
#pragma unroll
                for (int nt = 0; nt < 4; nt++) {
                    const int cc = n0 + warp_n * 32 + nt * 8 + (lane & 3) * 2;
                    float v0 = ((float)acc1[mt][nt][rr*2]   + (float)acc2[mt][nt][rr*2]   * R)
                               * (sa * ga.sB[cc])     + ga.bias[cc];
                    float v1 = ((float)acc1[mt][nt][rr*2+1] + (float)acc2[mt][nt][rr*2+1] * R)
                               * (sa * ga.sB[cc + 1]) + ga.bias[cc + 1];
                    float A0 = v0 * inv, A1v = v1 * inv;
                    float f0 = rintf(A0), f1 = rintf(A1v);
                    int i0 = (int)f0, i1 = (int)f1;
                    int r0v = (int)rintf((A0 - f0) * 254.f);
                    int r1v = (int)rintf((A1v - f1) * 254.f);
                    *(uint16_t*)(ga.Q1 + (size_t)grow * 2048 + cc) =
                        (uint16_t)((i0 & 0xff) | ((i1 & 0xff) << 8));
                    *(uint16_t*)(ga.Q2 + (size_t)grow * 2048 + cc) =
                        (uint16_t)((r0v & 0xff) | ((r1v & 0xff) << 8));
                }
            }
        }
    }
}

// ---------------------------------------------------------------------------
// Hybrid flash attention (causal): int8 two-level QK, split-bf16 PV
// with register-resident P (validated round 9). Heavy q-tiles first.
// smem: 2 stages x (k1 4K | k2 4K | vh 8K | vl 8K) = 48K; k-scales at 49152.
// ---------------------------------------------------------------------------
#define FQT 256
#define FKT 64
#define STG_SZ 24576u
#define SCOFF 49152u
#define FA_SMEM 49664

__global__ __launch_bounds__(256, 1) void flash_hyb(
    const int8_t* __restrict__ q1g, const int8_t* __restrict__ q2g,
    const float* __restrict__ sqg,
    const int8_t* __restrict__ k1g, const int8_t* __restrict__ k2g,
    const float* __restrict__ skg,
    const __nv_bfloat16* __restrict__ Vh, const __nv_bfloat16* __restrict__ Vl,
    float* __restrict__ O)
{
    extern __shared__ char smem[];
    const uint32_t sb = smem_u32(smem);
    const int t = threadIdx.x, lane = t & 31, wid = t >> 5;
    const int qt = (int)gridDim.x - 1 - (int)blockIdx.x;
    const int bh = blockIdx.y;
    const int b = bh >> 5, h = bh & 31;
    const int q0 = qt * FQT;
    const int qrow0 = b * S_ + q0;
    const int krow0 = b * S_;
    const int hoff = h * D_;
    const size_t vbase = ((size_t)b * S_) * E_ + hoff;
    const float* skh = skg + (size_t)h * M_ + b * S_;
    const float R254 = 1.f / 254.f;
    const float CEXP = SCALE_ * 1.4426950408889634f;

    // ---- stage Q (int8, both levels) at [0,32K), hoist fragments ----
#pragma unroll
    for (int i = 0; i < 4; i++) {
        int idx = t + i * 256, r = idx >> 2, c = idx & 3;
        uint32_t so = (uint32_t)(r * 64 + ((c ^ ((r >> 1) & 3)) << 4));
        size_t g = (size_t)(qrow0 + r) * 2048 + hoff + c * 16;
        cp_async16(sb +          so, q1g + g);
        cp_async16(sb + 16384u + so, q2g + g);
    }
    CP_COMMIT(); CP_WAIT0();
    __syncthreads();

    uint32_t fq1[2][2][4], fq2[2][2][4];
#pragma unroll
    for (int mt = 0; mt < 2; mt++)
#pragma unroll
        for (int kc = 0; kc < 2; kc++) {
            int row = wid * 32 + mt * 16 + (lane & 15);
            uint32_t c = (uint32_t)(kc * 2 + (lane >> 4));
            uint32_t off = (uint32_t)(row * 64) + ((c ^ (uint32_t)((row >> 1) & 3)) << 4);
            ldm_x4(fq1[mt][kc], sb + off);
            ldm_x4(fq2[mt][kc], sb + 16384u + off);
        }
    float sqv[2][2];
#pragma unroll
    for (int mt = 0; mt < 2; mt++)
#pragma unroll
        for (int rr = 0; rr < 2; rr++)
            sqv[mt][rr] = sqg[(size_t)h * M_ + qrow0 + wid * 32 + mt * 16
                              + (lane >> 2) + rr * 8];
    __syncthreads();   // Q area now reusable for KV stages

    const int jmax = 4 * (qt + 1);
    {   // KV tile 0 -> stage 0
        int r = t >> 2, c = t & 3;
        uint32_t so = (uint32_t)(r * 64 + ((c ^ ((r >> 1) & 3)) << 4));
        size_t gk = (size_t)(krow0 + r) * 2048 + hoff + c * 16;
        cp_async16(sb +         so, k1g + gk);
        cp_async16(sb + 4096u + so, k2g + gk);
        if (t < 16) cp_async16(sb + SCOFF + t * 16u, skh + t * 4);
    }
#pragma unroll
    for (int i = 0; i < 2; i++) {      // V bf16: 64 rows x 128B per level
        int idx = t + i * 256, r = idx >> 3, c = idx & 7;
        uint32_t so = (uint32_t)(r * 128 + ((c ^ (r & 7)) << 4));
        size_t g = vbase + (size_t)r * E_ + c * 8;
        cp_async16(sb +  8192u + so, Vh + g);
        cp_async16(sb + 16384u + so, Vl + g);
    }
    CP_COMMIT();

    float Oacc[2][8][4];
#pragma unroll
    for (int i = 0; i < 2; i++)
#pragma unroll
        for (int j = 0; j < 8; j++)
#pragma unroll
            for (int q = 0; q < 4; q++) Oacc[i][j][q] = 0.f;
    float m_i[2][2] = {{-1e30f, -1e30f}, {-1e30f, -1e30f}};
    float l_i[2][2] = {{0.f, 0.f}, {0.f, 0.f}};

    for (int jt = 0; jt < jmax; jt++) {
        const int k0 = jt * FKT;
        __syncthreads();
        if (jt + 1 < jmax) {
            uint32_t st = (uint32_t)((jt + 1) & 1) * STG_SZ;
            {
                int r = t >> 2, c = t & 3;
                uint32_t so = (uint32_t)(r * 64 + ((c ^ ((r >> 1) & 3)) << 4));
                size_t gk = (size_t)(krow0 + k0 + FKT + r) * 2048 + hoff + c * 16;
                cp_async16(sb + st +         so, k1g + gk);
                cp_async16(sb + st + 4096u + so, k2g + gk);
                if (t < 16)
                    cp_async16(sb + SCOFF + (uint32_t)((jt + 1) & 1) * 256u + t * 16u,
                               skh + k0 + FKT + t * 4);
            }
#pragma unroll
            for (int i = 0; i < 2; i++) {
                int idx = t + i * 256, r = idx >> 3, c = idx & 7;
                uint32_t so = (uint32_t)(r * 128 + ((c ^ (r & 7)) << 4));
                size_t g = vbase + (size_t)(k0 + FKT + r) * E_ + c * 8;
                cp_async16(sb + st +  8192u + so, Vh + g);
                cp_async16(sb + st + 16384u + so, Vl + g);
            }
        }
        CP_COMMIT(); CP_WAIT1();
        __syncthreads();
        const uint32_t st = sb + (uint32_t)(jt & 1) * STG_SZ;
        const float* sks = (const float*)(smem + SCOFF + (jt & 1) * 256);

        // ---- S = Q K^T, int8 two-level, key halves ----
        float sacc[2][8][4];
#pragma unroll
        for (int kh = 0; kh < 2; kh++) {
            int i1[2][4][4], i2[2][4][4];
#pragma unroll
            for (int i = 0; i < 2; i++)
#pragma unroll
                for (int j = 0; j < 4; j++)
#pragma unroll
                    for (int q = 0; q < 4; q++) { i1[i][j][q] = 0; i2[i][j][q] = 0; }
#pragma unroll
            for (int kc = 0; kc < 2; kc++) {
                uint32_t bk1[2][4], bk2[2][4];
#pragma unroll
                for (int np2 = 0; np2 < 2; np2++) {
                    int row = (kh * 2 + np2) * 16 + (lane & 7) + ((lane >> 4) & 1) * 8;
                    uint32_t c = (uint32_t)(kc * 2 + ((lane >> 3) & 1));
                    uint32_t off = (uint32_t)(row * 64) + ((c ^ (uint32_t)((row >> 1) & 3)) << 4);
                    ldm_x4(bk1[np2], st + off);
                    ldm_x4(bk2[np2], st + 4096u + off);
                }
#pragma unroll
                for (int mt = 0; mt < 2; mt++)
#pragma unroll
                    for (int np2 = 0; np2 < 2; np2++)
#pragma unroll
                        for (int nt2 = 0; nt2 < 2; nt2++) {
                            const int sl = np2 * 2 + nt2, hl = nt2 * 2;
                            mma_s8(i1[mt][sl], fq1[mt][kc], bk1[np2][hl], bk1[np2][hl+1]);
                            mma_s8(i2[mt][sl], fq1[mt][kc], bk2[np2][hl], bk2[np2][hl+1]);
                            mma_s8(i2[mt][sl], fq2[mt][kc], bk1[np2][hl], bk1[np2][hl+1]);
                        }
            }
#pragma unroll
            for (int mt = 0; mt < 2; mt++)
#pragma unroll
                for (int sl = 0; sl < 4; sl++) {
                    const int nt = kh * 4 + sl;
                    const int c0 = nt * 8 + (lane & 3) * 2;
                    const float k0s = sks[c0], k1s = sks[c0 + 1];
#pragma unroll
                    for (int rr = 0; rr < 2; rr++) {
                        sacc[mt][nt][rr*2]   = sqv[mt][rr] * k0s *
                            ((float)i1[mt][sl][rr*2]   + (float)i2[mt][sl][rr*2]   * R254);
                        sacc[mt][nt][rr*2+1] = sqv[mt][rr] * k1s *
                            ((float)i1[mt][sl][rr*2+1] + (float)i2[mt][sl][rr*2+1] * R254);
                    }
                }
        }

        // ---- causal mask ----
        if (k0 + FKT - 1 > q0) {
#pragma unroll
            for (int mt = 0; mt < 2; mt++)
#pragma unroll
                for (int nt = 0; nt < 8; nt++)
#pragma unroll
                    for (int e = 0; e < 4; e++) {
                        int qrow = q0 + wid * 32 + mt * 16 + (lane >> 2) + (e >> 1) * 8;
                        int kcol = k0 + nt * 8 + (lane & 3) * 2 + (e & 1);
                        if (kcol > qrow) sacc[mt][nt][e] = -1e30f;
                    }
        }

        // ---- online softmax ----
#pragma unroll
        for (int mt = 0; mt < 2; mt++)
#pragma unroll
            for (int rr = 0; rr < 2; rr++) {
                float mx = -1e30f;
#pragma unroll
                for (int nt = 0; nt < 8; nt++)
                    mx = fmaxf(mx, fmaxf(sacc[mt][nt][rr*2], sacc[mt][nt][rr*2+1]));
                mx = fmaxf(mx, __shfl_xor_sync(0xffffffffu, mx, 1));
                mx = fmaxf(mx, __shfl_xor_sync(0xffffffffu, mx, 2));
                const float m_new = fmaxf(m_i[mt][rr], mx);
                const float mC = m_new * CEXP;
                const float alpha = ex2(m_i[mt][rr] * CEXP - mC);
                float rs = 0.f;
#pragma unroll
                for (int nt = 0; nt < 8; nt++) {
                    float p0 = ex2(sacc[mt][nt][rr*2]   * CEXP - mC);
                    float p1 = ex2(sacc[mt][nt][rr*2+1] * CEXP - mC);
                    sacc[mt][nt][rr*2] = p0; sacc[mt][nt][rr*2+1] = p1;
                    rs += p0 + p1;
                }
                rs += __shfl_xor_sync(0xffffffffu, rs, 1);
                rs += __shfl_xor_sync(0xffffffffu, rs, 2);
                l_i[mt][rr] = l_i[mt][rr] * alpha + rs;
                m_i[mt][rr] = m_new;
#pragma unroll
                for (int nd = 0; nd < 8; nd++) {
                    Oacc[mt][nd][rr*2]   *= alpha;
                    Oacc[mt][nd][rr*2+1] *= alpha;
                }
            }

        // ---- O += P V (register-resident split-bf16 P; two-level bf16 V) ----
#pragma unroll
        for (int kc = 0; kc < 4; kc++) {
            uint32_t ph[2][4], pl[2][4];
#pragma unroll
            for (int mt = 0; mt < 2; mt++) {
                float p00 = sacc[mt][2*kc][0],   p01 = sacc[mt][2*kc][1];
                float p10 = sacc[mt][2*kc][2],   p11 = sacc[mt][2*kc][3];
                float p20 = sacc[mt][2*kc+1][0], p21 = sacc[mt][2*kc+1][1];
                float p30 = sacc[mt][2*kc+1][2], p31 = sacc[mt][2*kc+1][3];
                ph[mt][0] = packbf(p00, p01);
                ph[mt][1] = packbf(p10, p11);
                ph[mt][2] = packbf(p20, p21);
                ph[mt][3] = packbf(p30, p31);
                pl[mt][0] = packbf(p00 - bf_lo(ph[mt][0]), p01 - bf_hi(ph[mt][0]));
                pl[mt][1] = packbf(p10 - bf_lo(ph[mt][1]), p11 - bf_hi(ph[mt][1]));
                pl[mt][2] = packbf(p20 - bf_lo(ph[mt][2]), p21 - bf_hi(ph[mt][2]));
                pl[mt][3] = packbf(p30 - bf_lo(ph[mt][3]), p31 - bf_hi(ph[mt][3]));
            }
#pragma unroll
            for (int ndp = 0; ndp < 4; ndp++) {
                int row = kc * 16 + (lane & 7) + ((lane >> 3) & 1) * 8;
                uint32_t c = (uint32_t)(2 * ndp) + (uint32_t)(lane >> 4);
                uint32_t off = (uint32_t)(row * 128) + ((c ^ (uint32_t)(row & 7)) << 4);
                uint32_t bvh[4], bvl[4];
                ldm_x4t(bvh, st +  8192u + off);
                ldm_x4t(bvl, st + 16384u + off);
#pragma unroll
                for (int nt2 = 0; nt2 < 2; nt2++) {
                    const int nd = ndp * 2 + nt2;
#pragma unroll
                    for (int mt = 0; mt < 2; mt++) {
                        mma16816(Oacc[mt][nd], ph[mt], bvh[nt2*2], bvh[nt2*2+1]);
                        mma16816(Oacc[mt][nd], ph[mt], bvl[nt2*2], bvl[nt2*2+1]);
                        mma16816(Oacc[mt][nd], pl[mt], bvh[nt2*2], bvh[nt2*2+1]);
                    }
                }
            }
        }
    }

    // ---- epilogue: normalize, fp32 store ----
#pragma unroll
    for (int mt = 0; mt < 2; mt++)
#pragma unroll
        for (int rr = 0; rr < 2; rr++) {
            const int row = wid * 32 + mt * 16 + (lane >> 2) + rr * 8;
            const float inv = 1.f / l_i[mt][rr];
            const size_t rb = (size_t)(qrow0 + row) * 2048 + hoff + (lane & 3) * 2;
#pragma unroll
            for (int nd = 0; nd < 8; nd++) {
                float v0 = Oacc[mt][nd][rr*2]   * inv;
                float v1 = Oacc[mt][nd][rr*2+1] * inv;
                *(float2*)(O + rb + nd * 8) = make_float2(v0, v1);
            }
        }
}

// ---------------------------------------------------------------------------
extern "C" void kernel_launch(void* const* d_in, const int* in_sizes, int n_in,
                              void* d_out, int out_size)
{
    const float* x  = (const float*)d_in[0];
    const float* Wq = (const float*)d_in[1];
    const float* bq = (const float*)d_in[2];
    const float* Wk = (const float*)d_in[3];
    const float* bk = (const float*)d_in[4];
    const float* Wv = (const float*)d_in[5];
    const float* bv = (const float*)d_in[6];
    const float* Wo = (const float*)d_in[7];
    const float* bo = (const float*)d_in[8];
    float* out = (float*)d_out;

    int8_t *x1, *x2, *a1, *a2;
    int8_t *wq1, *wq2, *wk1, *wk2, *wv1, *wv2, *wo1, *wo2;
    int8_t *q1, *q2, *k1, *k2;
    float *sx, *sa, *swq, *swk, *swv, *swo, *attn, *sq, *sk;
    __nv_bfloat16 *vh, *vl;
    cudaGetSymbolAddress((void**)&x1, g_x1);
    cudaGetSymbolAddress((void**)&x2, g_x2);
    cudaGetSymbolAddress((void**)&sx, g_sx);
    cudaGetSymbolAddress((void**)&a1, g_a1);
    cudaGetSymbolAddress((void**)&a2, g_a2);
    cudaGetSymbolAddress((void**)&sa, g_sa);
    cudaGetSymbolAddress((void**)&attn, g_attn);
    cudaGetSymbolAddress((void**)&wq1, g_wq1);
    cudaGetSymbolAddress((void**)&wq2, g_wq2);
    cudaGetSymbolAddress((void**)&swq, g_swq);
    cudaGetSymbolAddress((void**)&wk1, g_wk1);
    cudaGetSymbolAddress((void**)&wk2, g_wk2);
    cudaGetSymbolAddress((void**)&swk, g_swk);
    cudaGetSymbolAddress((void**)&wv1, g_wv1);
    cudaGetSymbolAddress((void**)&wv2, g_wv2);
    cudaGetSymbolAddress((void**)&swv, g_swv);
    cudaGetSymbolAddress((void**)&wo1, g_wo1);
    cudaGetSymbolAddress((void**)&wo2, g_wo2);
    cudaGetSymbolAddress((void**)&swo, g_swo);
    cudaGetSymbolAddress((void**)&q1, g_q1);
    cudaGetSymbolAddress((void**)&q2, g_q2);
    cudaGetSymbolAddress((void**)&k1, g_k1);
    cudaGetSymbolAddress((void**)&k2, g_k2);
    cudaGetSymbolAddress((void**)&sq, g_sq);
    cudaGetSymbolAddress((void**)&sk, g_sk);
    cudaGetSymbolAddress((void**)&vh, g_vh);
    cudaGetSymbolAddress((void**)&vl, g_vl);

    cudaFuncSetAttribute(gemm_s8<0>,
                         cudaFuncAttributeMaxDynamicSharedMemorySize, GS8_SMEM);
    cudaFuncSetAttribute(gemm_s8<1>,
                         cudaFuncAttributeMaxDynamicSharedMemorySize, GS8_SMEM);
    cudaFuncSetAttribute(gemm_s8<2>,
                         cudaFuncAttributeMaxDynamicSharedMemorySize, GS8_SMEM);
    cudaFuncSetAttribute(flash_hyb,
                         cudaFuncAttributeMaxDynamicSharedMemorySize, FA_SMEM);

    // merged input quantization (x + 4 weights)
    RQArgs rx{x,  x1,  x2,  sx,  M_};
    RQArgs rq{Wq, wq1, wq2, swq, E_};
    RQArgs rk{Wk, wk1, wk2, swk, E_};
    RQArgs rv{Wv, wv1, wv2, swv, E_};
    RQArgs ro{Wo, wo1, wo2, swo, E_};
    rowquant5<<<dim3(M_, 5), 256>>>(rx, rq, rk, rv, ro);

    GArgs aq{wq1, wq2, swq, bq, nullptr, nullptr, nullptr, q1, q2, sq};
    GArgs ak{wk1, wk2, swk, bk, nullptr, nullptr, nullptr, k1, k2, sk};
    GArgs av{wv1, wv2, swv, bv, nullptr, vh, vl, nullptr, nullptr, nullptr};
    GArgs ao{wo1, wo2, swo, bo, out, nullptr, nullptr, nullptr, nullptr, nullptr};

    dim3 gqk(E_ / 128, M_ / 128, 2);
    gemm_s8<2><<<gqk, 256, GS8_SMEM>>>(x1, x2, sx, aq, ak, ak);
    dim3 gv(E_ / 128, M_ / 128, 1);
    gemm_s8<1><<<gv, 256, GS8_SMEM>>>(x1, x2, sx, av, av, av);

    dim3 ga(S_ / FQT, B_ * H_);
    flash_hyb<<<ga, 256, FA_SMEM>>>(q1, q2, sq, k1, k2, sk, vh, vl, attn);

    rowquant<<<M_, 256>>>(attn, a1, a2, sa);

    dim3 go(E_ / 128, M_ / 128, 1);
    gemm_s8<0><<<go, 256, GS8_SMEM>>>(a1, a2, sa, ao, ao, ao);
}

// round 12
// speedup vs baseline: 1.1862x; 1.0158x over previous
#include <cuda_runtime.h>
#include <cuda_bf16.h>
#include <cstdint>
#include <math.h>

#define B_ 2
#define S_ 2048
#define E_ 2048
#define H_ 32
#define D_ 64
#define M_ (B_*S_)
#define SCALE_ 0.125f

// ---------------- scratch ----------------
static __device__ __align__(128) int8_t g_x1[(size_t)M_ * E_];
static __device__ __align__(128) int8_t g_x2[(size_t)M_ * E_];
static __device__ __align__(128) float  g_sx[M_];
static __device__ __align__(128) int8_t g_a1[(size_t)M_ * E_];
static __device__ __align__(128) int8_t g_a2[(size_t)M_ * E_];
static __device__ __align__(128) float  g_sa[M_];
static __device__ __align__(128) float  g_attn[(size_t)M_ * E_];

static __device__ __align__(128) int8_t g_wq1[(size_t)E_ * E_];
static __device__ __align__(128) int8_t g_wq2[(size_t)E_ * E_];
static __device__ __align__(128) float  g_swq[E_];
static __device__ __align__(128) int8_t g_wk1[(size_t)E_ * E_];
static __device__ __align__(128) int8_t g_wk2[(size_t)E_ * E_];
static __device__ __align__(128) float  g_swk[E_];
static __device__ __align__(128) int8_t g_wv1[(size_t)E_ * E_];
static __device__ __align__(128) int8_t g_wv2[(size_t)E_ * E_];
static __device__ __align__(128) float  g_swv[E_];
static __device__ __align__(128) int8_t g_wo1[(size_t)E_ * E_];
static __device__ __align__(128) int8_t g_wo2[(size_t)E_ * E_];
static __device__ __align__(128) float  g_swo[E_];

static __device__ __align__(128) int8_t g_q1[(size_t)M_ * E_];
static __device__ __align__(128) int8_t g_q2[(size_t)M_ * E_];
static __device__ __align__(128) int8_t g_k1[(size_t)M_ * E_];
static __device__ __align__(128) int8_t g_k2[(size_t)M_ * E_];
static __device__ __align__(128) float  g_sq[(size_t)H_ * M_];
static __device__ __align__(128) float  g_sk[(size_t)H_ * M_];

static __device__ __align__(128) __nv_bfloat16 g_vh[(size_t)M_ * E_];
static __device__ __align__(128) __nv_bfloat16 g_vl[(size_t)M_ * E_];

// ---------------- helpers ----------------
__device__ __forceinline__ uint32_t smem_u32(const void* p) {
    uint32_t a;
    asm("{ .reg .u64 t; cvta.to.shared.u64 t, %1; cvt.u32.u64 %0, t; }"
        : "=r"(a) : "l"(p));
    return a;
}
__device__ __forceinline__ void cp_async16(uint32_t saddr, const void* gaddr) {
    asm volatile("cp.async.cg.shared.global [%0], [%1], 16;\n"
                 :: "r"(saddr), "l"(gaddr));
}
#define CP_COMMIT() asm volatile("cp.async.commit_group;\n" ::: "memory")
#define CP_WAIT0()  asm volatile("cp.async.wait_group 0;\n" ::: "memory")
#define CP_WAIT1()  asm volatile("cp.async.wait_group 1;\n" ::: "memory")
#define CP_WAIT2()  asm volatile("cp.async.wait_group 2;\n" ::: "memory")

__device__ __forceinline__ void ldm_x4(uint32_t* r, uint32_t addr) {
    asm volatile("ldmatrix.sync.aligned.m8n8.x4.shared.b16 {%0,%1,%2,%3}, [%4];"
                 : "=r"(r[0]), "=r"(r[1]), "=r"(r[2]), "=r"(r[3]) : "r"(addr));
}
__device__ __forceinline__ void ldm_x4t(uint32_t* r, uint32_t addr) {
    asm volatile("ldmatrix.sync.aligned.m8n8.x4.trans.shared.b16 {%0,%1,%2,%3}, [%4];"
                 : "=r"(r[0]), "=r"(r[1]), "=r"(r[2]), "=r"(r[3]) : "r"(addr));
}
__device__ __forceinline__ void mma16816(float* d, const uint32_t* a,
                                         uint32_t b0, uint32_t b1) {
    asm volatile(
        "mma.sync.aligned.m16n8k16.row.col.f32.bf16.bf16.f32 "
        "{%0,%1,%2,%3}, {%4,%5,%6,%7}, {%8,%9}, {%0,%1,%2,%3};"
        : "+f"(d[0]), "+f"(d[1]), "+f"(d[2]), "+f"(d[3])
        : "r"(a[0]), "r"(a[1]), "r"(a[2]), "r"(a[3]), "r"(b0), "r"(b1));
}
__device__ __forceinline__ void mma_s8(int* d, const uint32_t* a,
                                       uint32_t b0, uint32_t b1) {
    asm volatile(
        "mma.sync.aligned.m16n8k32.row.col.s32.s8.s8.s32 "
        "{%0,%1,%2,%3}, {%4,%5,%6,%7}, {%8,%9}, {%0,%1,%2,%3};"
        : "+r"(d[0]), "+r"(d[1]), "+r"(d[2]), "+r"(d[3])
        : "r"(a[0]), "r"(a[1]), "r"(a[2]), "r"(a[3]), "r"(b0), "r"(b1));
}
__device__ __forceinline__ uint32_t packbf(float lo, float hi) {
    uint32_t d;
    asm("cvt.rn.bf16x2.f32 %0, %1, %2;" : "=r"(d) : "f"(hi), "f"(lo));
    return d;
}
__device__ __forceinline__ float bf_lo(uint32_t u) { return __uint_as_float(u << 16); }
__device__ __forceinline__ float bf_hi(uint32_t u) { return __uint_as_float(u & 0xffff0000u); }
__device__ __forceinline__ float ex2(float x) {
    float y; asm("ex2.approx.f32 %0, %1;" : "=f"(y) : "f"(x)); return y;
}

// ---------------------------------------------------------------------------
// Row-wise two-level int8 quantization over 2048-col rows.
// ---------------------------------------------------------------------------
struct RQArgs { const float* src; int8_t* q1; int8_t* q2; float* s; int rows; };

__device__ __forceinline__ void rowquant_body(
    const float* __restrict__ x, int8_t* __restrict__ q1,
    int8_t* __restrict__ q2, float* __restrict__ s, int row, int t,
    float* wmax)
{
    const float* xr = x + (size_t)row * 2048 + t * 8;
    float4 v0 = ((const float4*)xr)[0];
    float4 v1 = ((const float4*)xr)[1];
    float vv[8] = {v0.x, v0.y, v0.z, v0.w, v1.x, v1.y, v1.z, v1.w};
    float m = 0.f;
#pragma unroll
    for (int j = 0; j < 8; j++) m = fmaxf(m, fabsf(vv[j]));
#pragma unroll
    for (int o = 16; o; o >>= 1) m = fmaxf(m, __shfl_xor_sync(~0u, m, o));
    if ((t & 31) == 0) wmax[t >> 5] = m;
    __syncthreads();
    float mm = wmax[0];
#pragma unroll
    for (int i = 1; i < 8; i++) mm = fmaxf(mm, wmax[i]);
    mm = fmaxf(mm, 1e-20f);
    if (t == 0) s[row] = mm * (1.f / 127.f);
    const float inv = 127.f / mm;

    uint32_t p1[2] = {0, 0}, p2[2] = {0, 0};
#pragma unroll
    for (int j = 0; j < 8; j++) {
        float xs = vv[j] * inv;
        float qf = rintf(xs);
        float rf = rintf((xs - qf) * 254.f);
        int iq = (int)qf, ir = (int)rf;
        p1[j >> 2] |= (uint32_t)(iq & 0xff) << ((j & 3) * 8);
        p2[j >> 2] |= (uint32_t)(ir & 0xff) << ((j & 3) * 8);
    }
    ((uint32_t*)q1)[row * 512 + t * 2]     = p1[0];
    ((uint32_t*)q1)[row * 512 + t * 2 + 1] = p1[1];
    ((uint32_t*)q2)[row * 512 + t * 2]     = p2[0];
    ((uint32_t*)q2)[row * 512 + t * 2 + 1] = p2[1];
}

__global__ __launch_bounds__(256) void rowquant(
    const float* __restrict__ x, int8_t* __restrict__ q1,
    int8_t* __restrict__ q2, float* __restrict__ s)
{
    __shared__ float wmax[8];
    rowquant_body(x, q1, q2, s, blockIdx.x, threadIdx.x, wmax);
}

__global__ __launch_bounds__(256) void rowquant5(
    RQArgs a0, RQArgs a1, RQArgs a2, RQArgs a3, RQArgs a4)
{
    __shared__ float wmax[8];
    RQArgs a = (blockIdx.y == 0) ? a0 : (blockIdx.y == 1) ? a1
             : (blockIdx.y == 2) ? a2 : (blockIdx.y == 3) ? a3 : a4;
    if ((int)blockIdx.x >= a.rows) return;
    rowquant_body(a.src, a.q1, a.q2, a.s, blockIdx.x, threadIdx.x, wmax);
}

// ---------------------------------------------------------------------------
// Two-level int8 GEMM.
// EPI 0: fp32 C + bias.
// EPI 1: split bf16 (hi, lo) C + bias (for V).
// EPI 2: fused per-(row, 64-col head) two-level int8 quant output + scales.
// ---------------------------------------------------------------------------
#define GK 2048
#define NCH8 32
#define SSTG 32768
#define GS8_SMEM (3 * SSTG)

struct GArgs {
    const int8_t *B1, *B2;
    const float* sB;
    const float* bias;
    float* C;
    __nv_bfloat16 *Ch, *Cl;
    int8_t *Q1, *Q2;
    float* SQ;
};

__device__ __forceinline__ void s8_load(
    const int8_t* __restrict__ A1, const int8_t* __restrict__ A2,
    const int8_t* __restrict__ B1, const int8_t* __restrict__ B2,
    int m0, int n0, int k0, uint32_t sb, int t)
{
#pragma unroll
    for (int i = 0; i < 2; i++) {
        int idx = t + i * 256, r = idx >> 2, c = idx & 3;
        uint32_t so = (uint32_t)(r * 64 + (((c ^ ((r >> 1) & 3))) << 4));
        size_t ga = (size_t)(m0 + r) * GK + k0 + c * 16;
        size_t gb = (size_t)(n0 + r) * GK + k0 + c * 16;
        cp_async16(sb +          so, A1 + ga);
        cp_async16(sb +  8192u + so, A2 + ga);
        cp_async16(sb + 16384u + so, B1 + gb);
        cp_async16(sb + 24576u + so, B2 + gb);
    }
}

template<int EPI>
__global__ __launch_bounds__(256, 1) void gemm_s8(
    const int8_t* __restrict__ A1, const int8_t* __restrict__ A2,
    const float* __restrict__ sA, GArgs a0, GArgs a1, GArgs a2)
{
    extern __shared__ char smem[];
    const uint32_t sbase = smem_u32(smem);
    const GArgs ga = (blockIdx.z == 0) ? a0 : (blockIdx.z == 1) ? a1 : a2;
    const int t = threadIdx.x, lane = t & 31, wid = t >> 5;
    const int warp_m = wid >> 2, warp_n = wid & 3;
    const int m0 = blockIdx.y * 128;
    const int n0 = blockIdx.x * 128;

    int a_row[4], b_row[2];
    uint32_t a_sw[4], b_sw[2];
#pragma unroll
    for (int mt = 0; mt < 4; mt++) {
        a_row[mt] = warp_m * 64 + mt * 16 + (lane & 15);
        a_sw[mt]  = (uint32_t)((a_row[mt] >> 1) & 3);
    }
#pragma unroll
    for (int pt = 0; pt < 2; pt++) {
        b_row[pt] = warp_n * 32 + pt * 16 + (lane & 7) + ((lane >> 4) & 1) * 8;
        b_sw[pt]  = (uint32_t)((b_row[pt] >> 1) & 3);
    }
    const uint32_t a_ch = (uint32_t)(lane >> 4);
    const uint32_t b_ch = (uint32_t)((lane >> 3) & 1);

    int acc1[4][4][4], acc2[4][4][4];
#pragma unroll
    for (int i = 0; i < 4; i++)
#pragma unroll
        for (int j = 0; j < 4; j++)
#pragma unroll
            for (int q = 0; q < 4; q++) { acc1[i][j][q] = 0; acc2[i][j][q] = 0; }

    s8_load(A1, A2, ga.B1, ga.B2, m0, n0, 0,   sbase,            t); CP_COMMIT();
    s8_load(A1, A2, ga.B1, ga.B2, m0, n0, 64,  sbase + SSTG,     t); CP_COMMIT();
    s8_load(A1, A2, ga.B1, ga.B2, m0, n0, 128, sbase + 2 * SSTG, t); CP_COMMIT();

    uint32_t stg = 0;
    for (int ch = 0; ch < NCH8; ch++) {
        CP_WAIT2();
        __syncthreads();
        const uint32_t sb = sbase + stg * SSTG;

#pragma unroll
        for (int s = 0; s < 2; s++) {
            uint32_t Af1[4][4], Af2[4][4];
            uint32_t Bf1[2][4], Bf2[2][4];
#pragma unroll
            for (int mt = 0; mt < 4; mt++) {
                uint32_t c = (uint32_t)(s * 2) + a_ch;
                uint32_t off = (uint32_t)(a_row[mt] * 64) + ((c ^ a_sw[mt]) << 4);
                ldm_x4(Af1[mt], sb + off);
                ldm_x4(Af2[mt], sb + 8192u + off);
            }
#pragma unroll
            for (int pt = 0; pt < 2; pt++) {
                uint32_t c = (uint32_t)(s * 2) + b_ch;
                uint32_t off = (uint32_t)(b_row[pt] * 64) + ((c ^ b_sw[pt]) << 4);
                ldm_x4(Bf1[pt], sb + 16384u + off);
                ldm_x4(Bf2[pt], sb + 24576u + off);
            }
#pragma unroll
            for (int mt = 0; mt < 4; mt++)
#pragma unroll
                for (int nt = 0; nt < 4; nt++) {
                    const int pt = nt >> 1, hl = (nt & 1) * 2;
                    mma_s8(acc1[mt][nt], Af1[mt], Bf1[pt][hl], Bf1[pt][hl+1]);
                    mma_s8(acc2[mt][nt], Af1[mt], Bf2[pt][hl], Bf2[pt][hl+1]);
                    mma_s8(acc2[mt][nt], Af2[mt], Bf1[pt][hl], Bf1[pt][hl+1]);
                }
        }
        __syncthreads();
        if (ch + 3 < NCH8)
            s8_load(A1, A2, ga.B1, ga.B2, m0, n0, (ch + 3) * 64,
                    sbase + stg * SSTG, t);
        CP_COMMIT();
        stg = (stg == 2) ? 0 : stg + 1;
    }

    const float R = 1.f / 254.f;
    if (EPI == 0 || EPI == 1) {
#pragma unroll
        for (int mt = 0; mt < 4; mt++) {
            const int r0 = m0 + warp_m * 64 + mt * 16 + (lane >> 2);
            const float sa0 = sA[r0], sa1 = sA[r0 + 8];
#pragma unroll
            for (int nt = 0; nt < 4; nt++) {
                const int cc = n0 + warp_n * 32 + nt * 8 + (lane & 3) * 2;
                const float sb0 = ga.sB[cc], sb1 = ga.sB[cc + 1];
                const float bx = ga.bias[cc], by = ga.bias[cc + 1];
                float v0 = ((float)acc1[mt][nt][0] + (float)acc2[mt][nt][0] * R) * (sa0 * sb0) + bx;
                float v1 = ((float)acc1[mt][nt][1] + (float)acc2[mt][nt][1] * R) * (sa0 * sb1) + by;
                float v2 = ((float)acc1[mt][nt][2] + (float)acc2[mt][nt][2] * R) * (sa1 * sb0) + bx;
                float v3 = ((float)acc1[mt][nt][3] + (float)acc2[mt][nt][3] * R) * (sa1 * sb1) + by;
                if (EPI == 0) {
                    *(float2*)(ga.C + (size_t)r0 * GK + cc)       = make_float2(v0, v1);
                    *(float2*)(ga.C + (size_t)(r0 + 8) * GK + cc) = make_float2(v2, v3);
                } else {
                    uint32_t h0 = packbf(v0, v1);
                    uint32_t l0 = packbf(v0 - bf_lo(h0), v1 - bf_hi(h0));
                    uint32_t h1 = packbf(v2, v3);
                    uint32_t l1 = packbf(v2 - bf_lo(h1), v3 - bf_hi(h1));
                    *(uint32_t*)(ga.Ch + (size_t)r0 * GK + cc)       = h0;
                    *(uint32_t*)(ga.Cl + (size_t)r0 * GK + cc)       = l0;
                    *(uint32_t*)(ga.Ch + (size_t)(r0 + 8) * GK + cc) = h1;
                    *(uint32_t*)(ga.Cl + (size_t)(r0 + 8) * GK + cc) = l1;
                }
            }
        }
    } else {
        // EPI == 2: fused per-(row, 64-col head) two-level int8 quantization
        CP_WAIT0();
        __syncthreads();
        float* red = (float*)smem;      // 8 warps x 64 rows
        const int rbase = wid * 64;
#pragma unroll
        for (int mt = 0; mt < 4; mt++) {
            const int r0g = m0 + warp_m * 64 + mt * 16 + (lane >> 2);
            const float sa0 = sA[r0g], sa1 = sA[r0g + 8];
#pragma unroll
            for (int rr = 0; rr < 2; rr++) {
                const float sa = rr ? sa1 : sa0;
                float mx = 0.f;
#pragma unroll
                for (int nt = 0; nt < 4; nt++) {
                    const int cc = n0 + warp_n * 32 + nt * 8 + (lane & 3) * 2;
                    float v0 = ((float)acc1[mt][nt][rr*2]   + (float)acc2[mt][nt][rr*2]   * R)
                               * (sa * ga.sB[cc])     + ga.bias[cc];
                    float v1 = ((float)acc1[mt][nt][rr*2+1] + (float)acc2[mt][nt][rr*2+1] * R)
                               * (sa * ga.sB[cc + 1]) + ga.bias[cc + 1];
                    mx = fmaxf(mx, fmaxf(fabsf(v0), fabsf(v1)));
                }
                mx = fmaxf(mx, __shfl_xor_sync(~0u, mx, 1));
                mx = fmaxf(mx, __shfl_xor_sync(~0u, mx, 2));
                red[rbase + mt * 16 + rr * 8 + (lane >> 2)] = mx;
            }
        }
        __syncthreads();
        const int h = (n0 >> 6) + (warp_n >> 1);
#pragma unroll
        for (int mt = 0; mt < 4; mt++) {
            const int r0g = m0 + warp_m * 64 + mt * 16 + (lane >> 2);
            const float sa0 = sA[r0g], sa1 = sA[r0g + 8];
#pragma unroll
            for (int rr = 0; rr < 2; rr++) {
                const float sa = rr ? sa1 : sa0;
                const int idx = mt * 16 + rr * 8 + (lane >> 2);
                float m2 = fmaxf(red[rbase + idx], red[(rbase ^ 64) + idx]);
                m2 = fmaxf(m2, 1e-20f);
                const int grow = r0g + rr * 8;
                if ((lane & 3) == 0)
                    ga.SQ[(size_t)h * M_ + grow] = m2 * (1.f / 127.f);
                const float inv = 127.f / m2;
#pragma unroll
                for (int nt = 0; nt < 4; nt++) {
                    const int cc = n0 + warp_n * 32 + nt * 8 + (lane & 3) * 2;
                    float v0 = ((float)acc1[mt][nt][rr*2]   + (float)acc2[mt][nt][rr*2]   * R)
                               * (sa * ga.sB[cc])     + ga.bias[cc];
                    float v1 = ((float)acc1[mt][nt][rr*2+1] + (float)acc2[mt][nt][rr*2+1] * R)
                               * (sa * ga.sB[cc + 1]) + ga.bias[cc + 1];
                    float A0 = v0 * inv, A1v = v1 * inv;
                    float f0 = rintf(A0), f1 = rintf(A1v);
                    int i0 = (int)f0, i1 = (int)f1;
                    int r0v = (int)rintf((A0 - f0) * 254.f);
                    int r1v = (int)rintf((A1v - f1) * 254.f);
                    *(uint16_t*)(ga.Q1 + (size_t)grow * 2048 + cc) =
                        (uint16_t)((i0 & 0xff) | ((i1 & 0xff) << 8));
                    *(uint16_t*)(ga.Q2 + (size_t)grow * 2048 + cc) =
                        (uint16_t)((r0v & 0xff) | ((r1v & 0xff) << 8));
                }
            }
        }
    }
}

// ---------------------------------------------------------------------------
// Hybrid flash attention (causal): int8 two-level QK, split-bf16 PV.
// FQT=128 (16 rows/warp), 2 CTAs/SM for latency hiding.
// smem: 2 stages x (k1 4K | k2 4K | vh 8K | vl 8K) = 48K; k-scales at 49152.
// ---------------------------------------------------------------------------
#define FQT 128
#define FKT 64
#define STG_SZ 24576u
#define SCOFF 49152u
#define FA_SMEM 49664

__global__ __launch_bounds__(256, 2) void flash_hyb(
    const int8_t* __restrict__ q1g, const int8_t* __restrict__ q2g,
    const float* __restrict__ sqg,
    const int8_t* __restrict__ k1g, const int8_t* __restrict__ k2g,
    const float* __restrict__ skg,
    const __nv_bfloat16* __restrict__ Vh, const __nv_bfloat16* __restrict__ Vl,
    float* __restrict__ O)
{
    extern __shared__ char smem[];
    const uint32_t sb = smem_u32(smem);
    const int t = threadIdx.x, lane = t & 31, wid = t >> 5;
    const int qt = (int)gridDim.x - 1 - (int)blockIdx.x;   // heavy tiles first
    const int bh = blockIdx.y;
    const int b = bh >> 5, h = bh & 31;
    const int q0 = qt * FQT;
    const int qrow0 = b * S_ + q0;
    const int krow0 = b * S_;
    const int hoff = h * D_;
    const size_t vbase = ((size_t)b * S_) * E_ + hoff;
    const float* skh = skg + (size_t)h * M_ + b * S_;
    const float R254 = 1.f / 254.f;
    const float CEXP = SCALE_ * 1.4426950408889634f;

    // ---- stage Q (int8, both levels): 128 rows x 64B per level = 8K each ----
#pragma unroll
    for (int i = 0; i < 2; i++) {
        int idx = t + i * 256, r = idx >> 2, c = idx & 3;
        uint32_t so = (uint32_t)(r * 64 + ((c ^ ((r >> 1) & 3)) << 4));
        size_t g = (size_t)(qrow0 + r) * 2048 + hoff + c * 16;
        cp_async16(sb +         so, q1g + g);
        cp_async16(sb + 8192u + so, q2g + g);
    }
    CP_COMMIT(); CP_WAIT0();
    __syncthreads();

    uint32_t fq1[2][4], fq2[2][4];
#pragma unroll
    for (int kc = 0; kc < 2; kc++) {
        int row = wid * 16 + (lane & 15);
        uint32_t c = (uint32_t)(kc * 2 + (lane >> 4));
        uint32_t off = (uint32_t)(row * 64) + ((c ^ (uint32_t)((row >> 1) & 3)) << 4);
        ldm_x4(fq1[kc], sb + off);
        ldm_x4(fq2[kc], sb + 8192u + off);
    }
    float sqv[2];
#pragma unroll
    for (int rr = 0; rr < 2; rr++)
        sqv[rr] = sqg[(size_t)h * M_ + qrow0 + wid * 16 + (lane >> 2) + rr * 8];
    __syncthreads();   // Q area now reusable for KV stages

    const int jmax = 2 * (qt + 1);
    {   // KV tile 0 -> stage 0
        int r = t >> 2, c = t & 3;
        uint32_t so = (uint32_t)(r * 64 + ((c ^ ((r >> 1) & 3)) << 4));
        size_t gk = (size_t)(krow0 + r) * 2048 + hoff + c * 16;
        cp_async16(sb +         so, k1g + gk);
        cp_async16(sb + 4096u + so, k2g + gk);
        if (t < 16) cp_async16(sb + SCOFF + t * 16u, skh + t * 4);
    }
#pragma unroll
    for (int i = 0; i < 2; i++) {
        int idx = t + i * 256, r = idx >> 3, c = idx & 7;
        uint32_t so = (uint32_t)(r * 128 + ((c ^ (r & 7)) << 4));
        size_t g = vbase + (size_t)r * E_ + c * 8;
        cp_async16(sb +  8192u + so, Vh + g);
        cp_async16(sb + 16384u + so, Vl + g);
    }
    CP_COMMIT();

    float Oacc[8][4];
#pragma unroll
    for (int j = 0; j < 8; j++)
#pragma unroll
        for (int q = 0; q < 4; q++) Oacc[j][q] = 0.f;
    float m_i[2] = {-1e30f, -1e30f};
    float l_i[2] = {0.f, 0.f};

    for (int jt = 0; jt < jmax; jt++) {
        const int k0 = jt * FKT;
        __syncthreads();
        if (jt + 1 < jmax) {
            uint32_t st = (uint32_t)((jt + 1) & 1) * STG_SZ;
            {
                int r = t >> 2, c = t & 3;
                uint32_t so = (uint32_t)(r * 64 + ((c ^ ((r >> 1) & 3)) << 4));
                size_t gk = (size_t)(krow0 + k0 + FKT + r) * 2048 + hoff + c * 16;
                cp_async16(sb + st +         so, k1g + gk);
                cp_async16(sb + st + 4096u + so, k2g + gk);
                if (t < 16)
                    cp_async16(sb + SCOFF + (uint32_t)((jt + 1) & 1) * 256u + t * 16u,
                               skh + k0 + FKT + t * 4);
            }
#pragma unroll
            for (int i = 0; i < 2; i++) {
                int idx = t + i * 256, r = idx >> 3, c = idx & 7;
                uint32_t so = (uint32_t)(r * 128 + ((c ^ (r & 7)) << 4));
                size_t g = vbase + (size_t)(k0 + FKT + r) * E_ + c * 8;
                cp_async16(sb + st +  8192u + so, Vh + g);
                cp_async16(sb + st + 16384u + so, Vl + g);
            }
        }
        CP_COMMIT(); CP_WAIT1();
        __syncthreads();
        const uint32_t st = sb + (uint32_t)(jt & 1) * STG_SZ;
        const float* sks = (const float*)(smem + SCOFF + (jt & 1) * 256);

        // ---- S = Q K^T, int8 two-level, key halves ----
        float sacc[8][4];
#pragma unroll
        for (int kh = 0; kh < 2; kh++) {
            int i1[4][4], i2[4][4];
#pragma unroll
            for (int j = 0; j < 4; j++)
#pragma unroll
                for (int q = 0; q < 4; q++) { i1[j][q] = 0; i2[j][q] = 0; }
#pragma unroll
            for (int kc = 0; kc < 2; kc++) {
                uint32_t bk1[2][4], bk2[2][4];
#pragma unroll
                for (int np2 = 0; np2 < 2; np2++) {
                    int row = (kh * 2 + np2) * 16 + (lane & 7) + ((lane >> 4) & 1) * 8;
                    uint32_t c = (uint32_t)(kc * 2 + ((lane >> 3) & 1));
                    uint32_t off = (uint32_t)(row * 64) + ((c ^ (uint32_t)((row >> 1) & 3)) << 4);
                    ldm_x4(bk1[np2], st + off);
                    ldm_x4(bk2[np2], st + 4096u + off);
                }
#pragma unroll
                for (int np2 = 0; np2 < 2; np2++)
#pragma unroll
                    for (int nt2 = 0; nt2 < 2; nt2++) {
                        const int sl = np2 * 2 + nt2, hl = nt2 * 2;
                        mma_s8(i1[sl], fq1[kc], bk1[np2][hl], bk1[np2][hl+1]);
                        mma_s8(i2[sl], fq1[kc], bk2[np2][hl], bk2[np2][hl+1]);
                        mma_s8(i2[sl], fq2[kc], bk1[np2][hl], bk1[np2][hl+1]);
                    }
            }
#pragma unroll
            for (int sl = 0; sl < 4; sl++) {
                const int nt = kh * 4 + sl;
                const int c0 = nt * 8 + (lane & 3) * 2;
                const float k0s = sks[c0], k1s = sks[c0 + 1];
#pragma unroll
                for (int rr = 0; rr < 2; rr++) {
                    sacc[nt][rr*2]   = sqv[rr] * k0s *
                        ((float)i1[sl][rr*2]   + (float)i2[sl][rr*2]   * R254);
                    sacc[nt][rr*2+1] = sqv[rr] * k1s *
                        ((float)i1[sl][rr*2+1] + (float)i2[sl][rr*2+1] * R254);
                }
            }
        }

        // ---- causal mask ----
        if (k0 + FKT - 1 > q0) {
#pragma unroll
            for (int nt = 0; nt < 8; nt++)
#pragma unroll
                for (int e = 0; e < 4; e++) {
                    int qrow = q0 + wid * 16 + (lane >> 2) + (e >> 1) * 8;
                    int kcol = k0 + nt * 8 + (lane & 3) * 2 + (e & 1);
                    if (kcol > qrow) sacc[nt][e] = -1e30f;
                }
        }

        // ---- online softmax ----
#pragma unroll
        for (int rr = 0; rr < 2; rr++) {
            float mx = -1e30f;
#pragma unroll
            for (int nt = 0; nt < 8; nt++)
                mx = fmaxf(mx, fmaxf(sacc[nt][rr*2], sacc[nt][rr*2+1]));
            mx = fmaxf(mx, __shfl_xor_sync(0xffffffffu, mx, 1));
            mx = fmaxf(mx, __shfl_xor_sync(0xffffffffu, mx, 2));
            const float m_new = fmaxf(m_i[rr], mx);
            const float mC = m_new * CEXP;
            const float alpha = ex2(m_i[rr] * CEXP - mC);
            float rs = 0.f;
#pragma unroll
            for (int nt = 0; nt < 8; nt++) {
                float p0 = ex2(sacc[nt][rr*2]   * CEXP - mC);
                float p1 = ex2(sacc[nt][rr*2+1] * CEXP - mC);
                sacc[nt][rr*2] = p0; sacc[nt][rr*2+1] = p1;
                rs += p0 + p1;
            }
            rs += __shfl_xor_sync(0xffffffffu, rs, 1);
            rs += __shfl_xor_sync(0xffffffffu, rs, 2);
            l_i[rr] = l_i[rr] * alpha + rs;
            m_i[rr] = m_new;
#pragma unroll
            for (int nd = 0; nd < 8; nd++) {
                Oacc[nd][rr*2]   *= alpha;
                Oacc[nd][rr*2+1] *= alpha;
            }
        }

        // ---- O += P V (register-resident split-bf16 P; two-level bf16 V) ----
#pragma unroll
        for (int kc = 0; kc < 4; kc++) {
            uint32_t ph[4], pl[4];
            {
                float p00 = sacc[2*kc][0],   p01 = sacc[2*kc][1];
                float p10 = sacc[2*kc][2],   p11 = sacc[2*kc][3];
                float p20 = sacc[2*kc+1][0], p21 = sacc[2*kc+1][1];
                float p30 = sacc[2*kc+1][2], p31 = sacc[2*kc+1][3];
                ph[0] = packbf(p00, p01);
                ph[1] = packbf(p10, p11);
                ph[2] = packbf(p20, p21);
                ph[3] = packbf(p30, p31);
                pl[0] = packbf(p00 - bf_lo(ph[0]), p01 - bf_hi(ph[0]));
                pl[1] = packbf(p10 - bf_lo(ph[1]), p11 - bf_hi(ph[1]));
                pl[2] = packbf(p20 - bf_lo(ph[2]), p21 - bf_hi(ph[2]));
                pl[3] = packbf(p30 - bf_lo(ph[3]), p31 - bf_hi(ph[3]));
            }
#pragma unroll
            for (int ndp = 0; ndp < 4; ndp++) {
                int row = kc * 16 + (lane & 7) + ((lane >> 3) & 1) * 8;
                uint32_t c = (uint32_t)(2 * ndp) + (uint32_t)(lane >> 4);
                uint32_t off = (uint32_t)(row * 128) + ((c ^ (uint32_t)(row & 7)) << 4);
                uint32_t bvh[4], bvl[4];
                ldm_x4t(bvh, st +  8192u + off);
                ldm_x4t(bvl, st + 16384u + off);
#pragma unroll
                for (int nt2 = 0; nt2 < 2; nt2++) {
                    const int nd = ndp * 2 + nt2;
                    mma16816(Oacc[nd], ph, bvh[nt2*2], bvh[nt2*2+1]);
                    mma16816(Oacc[nd], ph, bvl[nt2*2], bvl[nt2*2+1]);
                    mma16816(Oacc[nd], pl, bvh[nt2*2], bvh[nt2*2+1]);
                }
            }
        }
    }

    // ---- epilogue: normalize, fp32 store ----
#pragma unroll
    for (int rr = 0; rr < 2; rr++) {
        const int row = wid * 16 + (lane >> 2) + rr * 8;
        const float inv = 1.f / l_i[rr];
        const size_t rb = (size_t)(qrow0 + row) * 2048 + hoff + (lane & 3) * 2;
#pragma unroll
        for (int nd = 0; nd < 8; nd++) {
            float v0 = Oacc[nd][rr*2]   * inv;
            float v1 = Oacc[nd][rr*2+1] * inv;
            *(float2*)(O + rb + nd * 8) = make_float2(v0, v1);
        }
    }
}

// ---------------------------------------------------------------------------
extern "C" void kernel_launch(void* const* d_in, const int* in_sizes, int n_in,
                              void* d_out, int out_size)
{
    const float* x  = (const float*)d_in[0];
    const float* Wq = (const float*)d_in[1];
    const float* bq = (const float*)d_in[2];
    const float* Wk = (const float*)d_in[3];
    const float* bk = (const float*)d_in[4];
    const float* Wv = (const float*)d_in[5];
    const float* bv = (const float*)d_in[6];
    const float* Wo = (const float*)d_in[7];
    const float* bo = (const float*)d_in[8];
    float* out = (float*)d_out;

    int8_t *x1, *x2, *a1, *a2;
    int8_t *wq1, *wq2, *wk1, *wk2, *wv1, *wv2, *wo1, *wo2;
    int8_t *q1, *q2, *k1, *k2;
    float *sx, *sa, *swq, *swk, *swv, *swo, *attn, *sq, *sk;
    __nv_bfloat16 *vh, *vl;
    cudaGetSymbolAddress((void**)&x1, g_x1);
    cudaGetSymbolAddress((void**)&x2, g_x2);
    cudaGetSymbolAddress((void**)&sx, g_sx);
    cudaGetSymbolAddress((void**)&a1, g_a1);
    cudaGetSymbolAddress((void**)&a2, g_a2);
    cudaGetSymbolAddress((void**)&sa, g_sa);
    cudaGetSymbolAddress((void**)&attn, g_attn);
    cudaGetSymbolAddress((void**)&wq1, g_wq1);
    cudaGetSymbolAddress((void**)&wq2, g_wq2);
    cudaGetSymbolAddress((void**)&swq, g_swq);
    cudaGetSymbolAddress((void**)&wk1, g_wk1);
    cudaGetSymbolAddress((void**)&wk2, g_wk2);
    cudaGetSymbolAddress((void**)&swk, g_swk);
    cudaGetSymbolAddress((void**)&wv1, g_wv1);
    cudaGetSymbolAddress((void**)&wv2, g_wv2);
    cudaGetSymbolAddress((void**)&swv, g_swv);
    cudaGetSymbolAddress((void**)&wo1, g_wo1);
    cudaGetSymbolAddress((void**)&wo2, g_wo2);
    cudaGetSymbolAddress((void**)&swo, g_swo);
    cudaGetSymbolAddress((void**)&q1, g_q1);
    cudaGetSymbolAddress((void**)&q2, g_q2);
    cudaGetSymbolAddress((void**)&k1, g_k1);
    cudaGetSymbolAddress((void**)&k2, g_k2);
    cudaGetSymbolAddress((void**)&sq, g_sq);
    cudaGetSymbolAddress((void**)&sk, g_sk);
    cudaGetSymbolAddress((void**)&vh, g_vh);
    cudaGetSymbolAddress((void**)&vl, g_vl);

    cudaFuncSetAttribute(gemm_s8<0>,
                         cudaFuncAttributeMaxDynamicSharedMemorySize, GS8_SMEM);
    cudaFuncSetAttribute(gemm_s8<1>,
                         cudaFuncAttributeMaxDynamicSharedMemorySize, GS8_SMEM);
    cudaFuncSetAttribute(gemm_s8<2>,
                         cudaFuncAttributeMaxDynamicSharedMemorySize, GS8_SMEM);
    cudaFuncSetAttribute(flash_hyb,
                         cudaFuncAttributeMaxDynamicSharedMemorySize, FA_SMEM);

    RQArgs rx{x,  x1,  x2,  sx,  M_};
    RQArgs rq{Wq, wq1, wq2, swq, E_};
    RQArgs rk{Wk, wk1, wk2, swk, E_};
    RQArgs rv{Wv, wv1, wv2, swv, E_};
    RQArgs ro{Wo, wo1, wo2, swo, E_};
    rowquant5<<<dim3(M_, 5), 256>>>(rx, rq, rk, rv, ro);

    GArgs aq{wq1, wq2, swq, bq, nullptr, nullptr, nullptr, q1, q2, sq};
    GArgs ak{wk1, wk2, swk, bk, nullptr, nullptr, nullptr, k1, k2, sk};
    GArgs av{wv1, wv2, swv, bv, nullptr, vh, vl, nullptr, nullptr, nullptr};
    GArgs ao{wo1, wo2, swo, bo, out, nullptr, nullptr, nullptr, nullptr, nullptr};

    dim3 gqk(E_ / 128, M_ / 128, 2);
    gemm_s8<2><<<gqk, 256, GS8_SMEM>>>(x1, x2, sx, aq, ak, ak);
    dim3 gv(E_ / 128, M_ / 128, 1);
    gemm_s8<1><<<gv, 256, GS8_SMEM>>>(x1, x2, sx, av, av, av);

    dim3 ga(S_ / FQT, B_ * H_);     // (16, 64)
    flash_hyb<<<ga, 256, FA_SMEM>>>(q1, q2, sq, k1, k2, sk, vh, vl, attn);

    rowquant<<<M_, 256>>>(attn, a1, a2, sa);

    dim3 go(E_ / 128, M_ / 128, 1);
    gemm_s8<0><<<go, 256, GS8_SMEM>>>(a1, a2, sa, ao, ao, ao);
}

// round 13
// speedup vs baseline: 1.3301x; 1.1213x over previous
#include <cuda_runtime.h>
#include <cuda_bf16.h>
#include <cuda_fp16.h>
#include <cstdint>
#include <math.h>

#define B_ 2
#define S_ 2048
#define E_ 2048
#define H_ 32
#define D_ 64
#define M_ (B_*S_)
#define SCALE_ 0.125f

// ---------------- scratch ----------------
static __device__ __align__(128) int8_t g_x1[(size_t)M_ * E_];
static __device__ __align__(128) int8_t g_x2[(size_t)M_ * E_];
static __device__ __align__(128) float  g_sx[M_];
static __device__ __align__(128) int8_t g_a1[(size_t)M_ * E_];
static __device__ __align__(128) int8_t g_a2[(size_t)M_ * E_];
static __device__ __align__(128) float  g_sa[M_];
static __device__ __align__(128) float  g_attn[(size_t)M_ * E_];

static __device__ __align__(128) int8_t g_wq1[(size_t)E_ * E_];
static __device__ __align__(128) int8_t g_wq2[(size_t)E_ * E_];
static __device__ __align__(128) float  g_swq[E_];
static __device__ __align__(128) int8_t g_wk1[(size_t)E_ * E_];
static __device__ __align__(128) int8_t g_wk2[(size_t)E_ * E_];
static __device__ __align__(128) float  g_swk[E_];
static __device__ __align__(128) int8_t g_wv1[(size_t)E_ * E_];
static __device__ __align__(128) int8_t g_wv2[(size_t)E_ * E_];
static __device__ __align__(128) float  g_swv[E_];
static __device__ __align__(128) int8_t g_wo1[(size_t)E_ * E_];
static __device__ __align__(128) int8_t g_wo2[(size_t)E_ * E_];
static __device__ __align__(128) float  g_swo[E_];

static __device__ __align__(128) int8_t g_q1[(size_t)M_ * E_];
static __device__ __align__(128) int8_t g_q2[(size_t)M_ * E_];
static __device__ __align__(128) int8_t g_k1[(size_t)M_ * E_];
static __device__ __align__(128) int8_t g_k2[(size_t)M_ * E_];
static __device__ __align__(128) float  g_sq[(size_t)H_ * M_];
static __device__ __align__(128) float  g_sk[(size_t)H_ * M_];

static __device__ __align__(128) __half g_vh[(size_t)M_ * E_];

// ---------------- helpers ----------------
__device__ __forceinline__ uint32_t smem_u32(const void* p) {
    uint32_t a;
    asm("{ .reg .u64 t; cvta.to.shared.u64 t, %1; cvt.u32.u64 %0, t; }"
        : "=r"(a) : "l"(p));
    return a;
}
__device__ __forceinline__ void cp_async16(uint32_t saddr, const void* gaddr) {
    asm volatile("cp.async.cg.shared.global [%0], [%1], 16;\n"
                 :: "r"(saddr), "l"(gaddr));
}
#define CP_COMMIT() asm volatile("cp.async.commit_group;\n" ::: "memory")
#define CP_WAIT0()  asm volatile("cp.async.wait_group 0;\n" ::: "memory")
#define CP_WAIT1()  asm volatile("cp.async.wait_group 1;\n" ::: "memory")
#define CP_WAIT2()  asm volatile("cp.async.wait_group 2;\n" ::: "memory")

__device__ __forceinline__ void ldm_x4(uint32_t* r, uint32_t addr) {
    asm volatile("ldmatrix.sync.aligned.m8n8.x4.shared.b16 {%0,%1,%2,%3}, [%4];"
                 : "=r"(r[0]), "=r"(r[1]), "=r"(r[2]), "=r"(r[3]) : "r"(addr));
}
__device__ __forceinline__ void ldm_x4t(uint32_t* r, uint32_t addr) {
    asm volatile("ldmatrix.sync.aligned.m8n8.x4.trans.shared.b16 {%0,%1,%2,%3}, [%4];"
                 : "=r"(r[0]), "=r"(r[1]), "=r"(r[2]), "=r"(r[3]) : "r"(addr));
}
__device__ __forceinline__ void mma_h(float* d, const uint32_t* a,
                                      uint32_t b0, uint32_t b1) {
    asm volatile(
        "mma.sync.aligned.m16n8k16.row.col.f32.f16.f16.f32 "
        "{%0,%1,%2,%3}, {%4,%5,%6,%7}, {%8,%9}, {%0,%1,%2,%3};"
        : "+f"(d[0]), "+f"(d[1]), "+f"(d[2]), "+f"(d[3])
        : "r"(a[0]), "r"(a[1]), "r"(a[2]), "r"(a[3]), "r"(b0), "r"(b1));
}
__device__ __forceinline__ void mma_s8(int* d, const uint32_t* a,
                                       uint32_t b0, uint32_t b1) {
    asm volatile(
        "mma.sync.aligned.m16n8k32.row.col.s32.s8.s8.s32 "
        "{%0,%1,%2,%3}, {%4,%5,%6,%7}, {%8,%9}, {%0,%1,%2,%3};"
        : "+r"(d[0]), "+r"(d[1]), "+r"(d[2]), "+r"(d[3])
        : "r"(a[0]), "r"(a[1]), "r"(a[2]), "r"(a[3]), "r"(b0), "r"(b1));
}
__device__ __forceinline__ uint32_t packbf(float lo, float hi) {
    uint32_t d;
    asm("cvt.rn.bf16x2.f32 %0, %1, %2;" : "=r"(d) : "f"(hi), "f"(lo));
    return d;
}
__device__ __forceinline__ uint32_t packh(float lo, float hi) {
    uint32_t d;
    asm("cvt.rn.f16x2.f32 %0, %1, %2;" : "=r"(d) : "f"(hi), "f"(lo));
    return d;
}
__device__ __forceinline__ float bf_lo(uint32_t u) { return __uint_as_float(u << 16); }
__device__ __forceinline__ float bf_hi(uint32_t u) { return __uint_as_float(u & 0xffff0000u); }
__device__ __forceinline__ float ex2(float x) {
    float y; asm("ex2.approx.f32 %0, %1;" : "=f"(y) : "f"(x)); return y;
}

// ---------------------------------------------------------------------------
// Row-wise two-level int8 quantization over 2048-col rows.
// ---------------------------------------------------------------------------
struct RQArgs { const float* src; int8_t* q1; int8_t* q2; float* s; int rows; };

__device__ __forceinline__ void rowquant_body(
    const float* __restrict__ x, int8_t* __restrict__ q1,
    int8_t* __restrict__ q2, float* __restrict__ s, int row, int t,
    float* wmax)
{
    const float* xr = x + (size_t)row * 2048 + t * 8;
    float4 v0 = ((const float4*)xr)[0];
    float4 v1 = ((const float4*)xr)[1];
    float vv[8] = {v0.x, v0.y, v0.z, v0.w, v1.x, v1.y, v1.z, v1.w};
    float m = 0.f;
#pragma unroll
    for (int j = 0; j < 8; j++) m = fmaxf(m, fabsf(vv[j]));
#pragma unroll
    for (int o = 16; o; o >>= 1) m = fmaxf(m, __shfl_xor_sync(~0u, m, o));
    if ((t & 31) == 0) wmax[t >> 5] = m;
    __syncthreads();
    float mm = wmax[0];
#pragma unroll
    for (int i = 1; i < 8; i++) mm = fmaxf(mm, wmax[i]);
    mm = fmaxf(mm, 1e-20f);
    if (t == 0) s[row] = mm * (1.f / 127.f);
    const float inv = 127.f / mm;

    uint32_t p1[2] = {0, 0}, p2[2] = {0, 0};
#pragma unroll
    for (int j = 0; j < 8; j++) {
        float xs = vv[j] * inv;
        float qf = rintf(xs);
        float rf = rintf((xs - qf) * 254.f);
        int iq = (int)qf, ir = (int)rf;
        p1[j >> 2] |= (uint32_t)(iq & 0xff) << ((j & 3) * 8);
        p2[j >> 2] |= (uint32_t)(ir & 0xff) << ((j & 3) * 8);
    }
    ((uint32_t*)q1)[row * 512 + t * 2]     = p1[0];
    ((uint32_t*)q1)[row * 512 + t * 2 + 1] = p1[1];
    ((uint32_t*)q2)[row * 512 + t * 2]     = p2[0];
    ((uint32_t*)q2)[row * 512 + t * 2 + 1] = p2[1];
}

__global__ __launch_bounds__(256) void rowquant(
    const float* __restrict__ x, int8_t* __restrict__ q1,
    int8_t* __restrict__ q2, float* __restrict__ s)
{
    __shared__ float wmax[8];
    rowquant_body(x, q1, q2, s, blockIdx.x, threadIdx.x, wmax);
}

__global__ __launch_bounds__(256) void rowquant5(
    RQArgs a0, RQArgs a1, RQArgs a2, RQArgs a3, RQArgs a4)
{
    __shared__ float wmax[8];
    RQArgs a = (blockIdx.y == 0) ? a0 : (blockIdx.y == 1) ? a1
             : (blockIdx.y == 2) ? a2 : (blockIdx.y == 3) ? a3 : a4;
    if ((int)blockIdx.x >= a.rows) return;
    rowquant_body(a.src, a.q1, a.q2, a.s, blockIdx.x, threadIdx.x, wmax);
}

// ---------------------------------------------------------------------------
// Two-level int8 GEMM.
// EPI 0: fp32 C + bias.
// EPI 1: fp16 C + bias (for V).
// EPI 2: fused per-(row, 64-col head) two-level int8 quant output + scales.
// ---------------------------------------------------------------------------
#define GK 2048
#define NCH8 32
#define SSTG 32768
#define GS8_SMEM (3 * SSTG)

struct GArgs {
    const int8_t *B1, *B2;
    const float* sB;
    const float* bias;
    float* C;
    __half* Ch;
    int8_t *Q1, *Q2;
    float* SQ;
};

__device__ __forceinline__ void s8_load(
    const int8_t* __restrict__ A1, const int8_t* __restrict__ A2,
    const int8_t* __restrict__ B1, const int8_t* __restrict__ B2,
    int m0, int n0, int k0, uint32_t sb, int t)
{
#pragma unroll
    for (int i = 0; i < 2; i++) {
        int idx = t + i * 256, r = idx >> 2, c = idx & 3;
        uint32_t so = (uint32_t)(r * 64 + (((c ^ ((r >> 1) & 3))) << 4));
        size_t ga = (size_t)(m0 + r) * GK + k0 + c * 16;
        size_t gb = (size_t)(n0 + r) * GK + k0 + c * 16;
        cp_async16(sb +          so, A1 + ga);
        cp_async16(sb +  8192u + so, A2 + ga);
        cp_async16(sb + 16384u + so, B1 + gb);
        cp_async16(sb + 24576u + so, B2 + gb);
    }
}

template<int EPI>
__global__ __launch_bounds__(256, 1) void gemm_s8(
    const int8_t* __restrict__ A1, const int8_t* __restrict__ A2,
    const float* __restrict__ sA, GArgs a0, GArgs a1, GArgs a2)
{
    extern __shared__ char smem[];
    const uint32_t sbase = smem_u32(smem);
    const GArgs ga = (blockIdx.z == 0) ? a0 : (blockIdx.z == 1) ? a1 : a2;
    const int t = threadIdx.x, lane = t & 31, wid = t >> 5;
    const int warp_m = wid >> 2, warp_n = wid & 3;
    const int m0 = blockIdx.y * 128;
    const int n0 = blockIdx.x * 128;

    int a_row[4], b_row[2];
    uint32_t a_sw[4], b_sw[2];
#pragma unroll
    for (int mt = 0; mt < 4; mt++) {
        a_row[mt] = warp_m * 64 + mt * 16 + (lane & 15);
        a_sw[mt]  = (uint32_t)((a_row[mt] >> 1) & 3);
    }
#pragma unroll
    for (int pt = 0; pt < 2; pt++) {
        b_row[pt] = warp_n * 32 + pt * 16 + (lane & 7) + ((lane >> 4) & 1) * 8;
        b_sw[pt]  = (uint32_t)((b_row[pt] >> 1) & 3);
    }
    const uint32_t a_ch = (uint32_t)(lane >> 4);
    const uint32_t b_ch = (uint32_t)((lane >> 3) & 1);

    int acc1[4][4][4], acc2[4][4][4];
#pragma unroll
    for (int i = 0; i < 4; i++)
#pragma unroll
        for (int j = 0; j < 4; j++)
#pragma unroll
            for (int q = 0; q < 4; q++) { acc1[i][j][q] = 0; acc2[i][j][q] = 0; }

    s8_load(A1, A2, ga.B1, ga.B2, m0, n0, 0,   sbase,            t); CP_COMMIT();
    s8_load(A1, A2, ga.B1, ga.B2, m0, n0, 64,  sbase + SSTG,     t); CP_COMMIT();
    s8_load(A1, A2, ga.B1, ga.B2, m0, n0, 128, sbase + 2 * SSTG, t); CP_COMMIT();

    uint32_t stg = 0;
    for (int ch = 0; ch < NCH8; ch++) {
        CP_WAIT2();
        __syncthreads();
        const uint32_t sb = sbase + stg * SSTG;

#pragma unroll
        for (int s = 0; s < 2; s++) {
            uint32_t Af1[4][4], Af2[4][4];
            uint32_t Bf1[2][4], Bf2[2][4];
#pragma unroll
            for (int mt = 0; mt < 4; mt++) {
                uint32_t c = (uint32_t)(s * 2) + a_ch;
                uint32_t off = (uint32_t)(a_row[mt] * 64) + ((c ^ a_sw[mt]) << 4);
                ldm_x4(Af1[mt], sb + off);
                ldm_x4(Af2[mt], sb + 8192u + off);
            }
#pragma unroll
            for (int pt = 0; pt < 2; pt++) {
                uint32_t c = (uint32_t)(s * 2) + b_ch;
                uint32_t off = (uint32_t)(b_row[pt] * 64) + ((c ^ b_sw[pt]) << 4);
                ldm_x4(Bf1[pt], sb + 16384u + off);
                ldm_x4(Bf2[pt], sb + 24576u + off);
            }
#pragma unroll
            for (int mt = 0; mt < 4; mt++)
#pragma unroll
                for (int nt = 0; nt < 4; nt++) {
                    const int pt = nt >> 1, hl = (nt & 1) * 2;
                    mma_s8(acc1[mt][nt], Af1[mt], Bf1[pt][hl], Bf1[pt][hl+1]);
                    mma_s8(acc2[mt][nt], Af1[mt], Bf2[pt][hl], Bf2[pt][hl+1]);
                    mma_s8(acc2[mt][nt], Af2[mt], Bf1[pt][hl], Bf1[pt][hl+1]);
                }
        }
        __syncthreads();
        if (ch + 3 < NCH8)
            s8_load(A1, A2, ga.B1, ga.B2, m0, n0, (ch + 3) * 64,
                    sbase + stg * SSTG, t);
        CP_COMMIT();
        stg = (stg == 2) ? 0 : stg + 1;
    }

    const float R = 1.f / 254.f;
    if (EPI == 0 || EPI == 1) {
#pragma unroll
        for (int mt = 0; mt < 4; mt++) {
            const int r0 = m0 + warp_m * 64 + mt * 16 + (lane >> 2);
            const float sa0 = sA[r0], sa1 = sA[r0 + 8];
#pragma unroll
            for (int nt = 0; nt < 4; nt++) {
                const int cc = n0 + warp_n * 32 + nt * 8 + (lane & 3) * 2;
                const float sb0 = ga.sB[cc], sb1 = ga.sB[cc + 1];
                const float bx = ga.bias[cc], by = ga.bias[cc + 1];
                float v0 = ((float)acc1[mt][nt][0] + (float)acc2[mt][nt][0] * R) * (sa0 * sb0) + bx;
                float v1 = ((float)acc1[mt][nt][1] + (float)acc2[mt][nt][1] * R) * (sa0 * sb1) + by;
                float v2 = ((float)acc1[mt][nt][2] + (float)acc2[mt][nt][2] * R) * (sa1 * sb0) + bx;
                float v3 = ((float)acc1[mt][nt][3] + (float)acc2[mt][nt][3] * R) * (sa1 * sb1) + by;
                if (EPI == 0) {
                    *(float2*)(ga.C + (size_t)r0 * GK + cc)       = make_float2(v0, v1);
                    *(float2*)(ga.C + (size_t)(r0 + 8) * GK + cc) = make_float2(v2, v3);
                } else {
                    *(uint32_t*)(ga.Ch + (size_t)r0 * GK + cc)       = packh(v0, v1);
                    *(uint32_t*)(ga.Ch + (size_t)(r0 + 8) * GK + cc) = packh(v2, v3);
                }
            }
        }
    } else {
        // EPI == 2: fused per-(row, 64-col head) two-level int8 quantization
        CP_WAIT0();
        __syncthreads();
        float* red = (float*)smem;      // 8 warps x 64 rows
        const int rbase = wid * 64;
#pragma unroll
        for (int mt = 0; mt < 4; mt++) {
            const int r0g = m0 + warp_m * 64 + mt * 16 + (lane >> 2);
            const float sa0 = sA[r0g], sa1 = sA[r0g + 8];
#pragma unroll
            for (int rr = 0; rr < 2; rr++) {
                const float sa = rr ? sa1 : sa0;
                float mx = 0.f;
#pragma unroll
                for (int nt = 0; nt < 4; nt++) {
                    const int cc = n0 + warp_n * 32 + nt * 8 + (lane & 3) * 2;
                    float v0 = ((float)acc1[mt][nt][rr*2]   + (float)acc2[mt][nt][rr*2]   * R)
                               * (sa * ga.sB[cc])     + ga.bias[cc];
                    float v1 = ((float)acc1[mt][nt][rr*2+1] + (float)acc2[mt][nt][rr*2+1] * R)
                               * (sa * ga.sB[cc + 1]) + ga.bias[cc + 1];
                    mx = fmaxf(mx, fmaxf(fabsf(v0), fabsf(v1)));
                }
                mx = fmaxf(mx, __shfl_xor_sync(~0u, mx, 1));
                mx = fmaxf(mx, __shfl_xor_sync(~0u, mx, 2));
                red[rbase + mt * 16 + rr * 8 + (lane >> 2)] = mx;
            }
        }
        __syncthreads();
        const int h = (n0 >> 6) + (warp_n >> 1);
#pragma unroll
        for (int mt = 0; mt < 4; mt++) {
            const int r0g = m0 + warp_m * 64 + mt * 16 + (lane >> 2);
            const float sa0 = sA[r0g], sa1 = sA[r0g + 8];
#pragma unroll
            for (int rr = 0; rr < 2; rr++) {
                const float sa = rr ? sa1 : sa0;
                const int idx = mt * 16 + rr * 8 + (lane >> 2);
                float m2 = fmaxf(red[rbase + idx], red[(rbase ^ 64) + idx]);
                m2 = fmaxf(m2, 1e-20f);
                const int grow = r0g + rr * 8;
                if ((lane & 3) == 0)
                    ga.SQ[(size_t)h * M_ + grow] = m2 * (1.f / 127.f);
                const float inv = 127.f / m2;
#pragma unroll
                for (int nt = 0; nt < 4; nt++) {
                    const int cc = n0 + warp_n * 32 + nt * 8 + (lane & 3) * 2;
                    float v0 = ((float)acc1[mt][nt][rr*2]   + (float)acc2[mt][nt][rr*2]   * R)
                               * (sa * ga.sB[cc])     + ga.bias[cc];
                    float v1 = ((float)acc1[mt][nt][rr*2+1] + (float)acc2[mt][nt][rr*2+1] * R)
                               * (sa * ga.sB[cc + 1]) + ga.bias[cc + 1];
                    float A0 = v0 * inv, A1v = v1 * inv;
                    float f0 = rintf(A0), f1 = rintf(A1v);
                    int i0 = (int)f0, i1 = (int)f1;
                    int r0v = (int)rintf((A0 - f0) * 254.f);
                    int r1v = (int)rintf((A1v - f1) * 254.f);
                    *(uint16_t*)(ga.Q1 + (size_t)grow * 2048 + cc) =
                        (uint16_t)((i0 & 0xff) | ((i1 & 0xff) << 8));
                    *(uint16_t*)(ga.Q2 + (size_t)grow * 2048 + cc) =
                        (uint16_t)((r0v & 0xff) | ((r1v & 0xff) << 8));
                }
            }
        }
    }
}

// ---------------------------------------------------------------------------
// Hybrid flash attention (causal): int8 two-level QK, fp16 P x fp16 V PV.
// FQT=128 (16 rows/warp), 2 CTAs/SM.
// smem: 2 stages x (k1 4K | k2 4K | vh 8K) = 32K; k-scales at 32768 (+512).
// ---------------------------------------------------------------------------
#define FQT 128
#define FKT 64
#define STG_SZ 16384u
#define SCOFF 32768u
#define FA_SMEM 33280

__global__ __launch_bounds__(256, 2) void flash_hyb(
    const int8_t* __restrict__ q1g, const int8_t* __restrict__ q2g,
    const float* __restrict__ sqg,
    const int8_t* __restrict__ k1g, const int8_t* __restrict__ k2g,
    const float* __restrict__ skg,
    const __half* __restrict__ Vh,
    float* __restrict__ O)
{
    extern __shared__ char smem[];
    const uint32_t sb = smem_u32(smem);
    const int t = threadIdx.x, lane = t & 31, wid = t >> 5;
    const int qt = (int)gridDim.x - 1 - (int)blockIdx.x;   // heavy tiles first
    const int bh = blockIdx.y;
    const int b = bh >> 5, h = bh & 31;
    const int q0 = qt * FQT;
    const int qrow0 = b * S_ + q0;
    const int krow0 = b * S_;
    const int hoff = h * D_;
    const size_t vbase = ((size_t)b * S_) * E_ + hoff;
    const float* skh = skg + (size_t)h * M_ + b * S_;
    const float R254 = 1.f / 254.f;
    const float CEXP = SCALE_ * 1.4426950408889634f;

    // ---- stage Q (int8, both levels): 128 rows x 64B per level = 8K each ----
#pragma unroll
    for (int i = 0; i < 2; i++) {
        int idx = t + i * 256, r = idx >> 2, c = idx & 3;
        uint32_t so = (uint32_t)(r * 64 + ((c ^ ((r >> 1) & 3)) << 4));
        size_t g = (size_t)(qrow0 + r) * 2048 + hoff + c * 16;
        cp_async16(sb +         so, q1g + g);
        cp_async16(sb + 8192u + so, q2g + g);
    }
    CP_COMMIT(); CP_WAIT0();
    __syncthreads();

    uint32_t fq1[2][4], fq2[2][4];
#pragma unroll
    for (int kc = 0; kc < 2; kc++) {
        int row = wid * 16 + (lane & 15);
        uint32_t c = (uint32_t)(kc * 2 + (lane >> 4));
        uint32_t off = (uint32_t)(row * 64) + ((c ^ (uint32_t)((row >> 1) & 3)) << 4);
        ldm_x4(fq1[kc], sb + off);
        ldm_x4(fq2[kc], sb + 8192u + off);
    }
    float sqv[2];
#pragma unroll
    for (int rr = 0; rr < 2; rr++)
        sqv[rr] = sqg[(size_t)h * M_ + qrow0 + wid * 16 + (lane >> 2) + rr * 8];
    __syncthreads();   // Q area now reusable for KV stages

    const int jmax = 2 * (qt + 1);
    {   // KV tile 0 -> stage 0
        int r = t >> 2, c = t & 3;
        uint32_t so = (uint32_t)(r * 64 + ((c ^ ((r >> 1) & 3)) << 4));
        size_t gk = (size_t)(krow0 + r) * 2048 + hoff + c * 16;
        cp_async16(sb +         so, k1g + gk);
        cp_async16(sb + 4096u + so, k2g + gk);
        if (t < 16) cp_async16(sb + SCOFF + t * 16u, skh + t * 4);
    }
#pragma unroll
    for (int i = 0; i < 2; i++) {      // V fp16: 64 rows x 128B
        int idx = t + i * 256, r = idx >> 3, c = idx & 7;
        uint32_t so = (uint32_t)(r * 128 + ((c ^ (r & 7)) << 4));
        size_t g = vbase + (size_t)r * E_ + c * 8;
        cp_async16(sb + 8192u + so, Vh + g);
    }
    CP_COMMIT();

    float Oacc[8][4];
#pragma unroll
    for (int j = 0; j < 8; j++)
#pragma unroll
        for (int q = 0; q < 4; q++) Oacc[j][q] = 0.f;
    float m_i[2] = {-1e30f, -1e30f};
    float l_i[2] = {0.f, 0.f};

    for (int jt = 0; jt < jmax; jt++) {
        const int k0 = jt * FKT;
        __syncthreads();
        if (jt + 1 < jmax) {
            uint32_t st = (uint32_t)((jt + 1) & 1) * STG_SZ;
            {
                int r = t >> 2, c = t & 3;
                uint32_t so = (uint32_t)(r * 64 + ((c ^ ((r >> 1) & 3)) << 4));
                size_t gk = (size_t)(krow0 + k0 + FKT + r) * 2048 + hoff + c * 16;
                cp_async16(sb + st +         so, k1g + gk);
                cp_async16(sb + st + 4096u + so, k2g + gk);
                if (t < 16)
                    cp_async16(sb + SCOFF + (uint32_t)((jt + 1) & 1) * 256u + t * 16u,
                               skh + k0 + FKT + t * 4);
            }
#pragma unroll
            for (int i = 0; i < 2; i++) {
                int idx = t + i * 256, r = idx >> 3, c = idx & 7;
                uint32_t so = (uint32_t)(r * 128 + ((c ^ (r & 7)) << 4));
                size_t g = vbase + (size_t)(k0 + FKT + r) * E_ + c * 8;
                cp_async16(sb + st + 8192u + so, Vh + g);
            }
        }
        CP_COMMIT(); CP_WAIT1();
        __syncthreads();
        const uint32_t st = sb + (uint32_t)(jt & 1) * STG_SZ;
        const float* sks = (const float*)(smem + SCOFF + (jt & 1) * 256);

        // ---- S = Q K^T, int8 two-level, key halves ----
        float sacc[8][4];
#pragma unroll
        for (int kh = 0; kh < 2; kh++) {
            int i1[4][4], i2[4][4];
#pragma unroll
            for (int j = 0; j < 4; j++)
#pragma unroll
                for (int q = 0; q < 4; q++) { i1[j][q] = 0; i2[j][q] = 0; }
#pragma unroll
            for (int kc = 0; kc < 2; kc++) {
                uint32_t bk1[2][4], bk2[2][4];
#pragma unroll
                for (int np2 = 0; np2 < 2; np2++) {
                    int row = (kh * 2 + np2) * 16 + (lane & 7) + ((lane >> 4) & 1) * 8;
                    uint32_t c = (uint32_t)(kc * 2 + ((lane >> 3) & 1));
                    uint32_t off = (uint32_t)(row * 64) + ((c ^ (uint32_t)((row >> 1) & 3)) << 4);
                    ldm_x4(bk1[np2], st + off);
                    ldm_x4(bk2[np2], st + 4096u + off);
                }
#pragma unroll
                for (int np2 = 0; np2 < 2; np2++)
#pragma unroll
                    for (int nt2 = 0; nt2 < 2; nt2++) {
                        const int sl = np2 * 2 + nt2, hl = nt2 * 2;
                        mma_s8(i1[sl], fq1[kc], bk1[np2][hl], bk1[np2][hl+1]);
                        mma_s8(i2[sl], fq1[kc], bk2[np2][hl], bk2[np2][hl+1]);
                        mma_s8(i2[sl], fq2[kc], bk1[np2][hl], bk1[np2][hl+1]);
                    }
            }
#pragma unroll
            for (int sl = 0; sl < 4; sl++) {
                const int nt = kh * 4 + sl;
                const int c0 = nt * 8 + (lane & 3) * 2;
                const float k0s = sks[c0], k1s = sks[c0 + 1];
#pragma unroll
                for (int rr = 0; rr < 2; rr++) {
                    sacc[nt][rr*2]   = sqv[rr] * k0s *
                        ((float)i1[sl][rr*2]   + (float)i2[sl][rr*2]   * R254);
                    sacc[nt][rr*2+1] = sqv[rr] * k1s *
                        ((float)i1[sl][rr*2+1] + (float)i2[sl][rr*2+1] * R254);
                }
            }
        }

        // ---- causal mask ----
        if (k0 + FKT - 1 > q0) {
#pragma unroll
            for (int nt = 0; nt < 8; nt++)
#pragma unroll
                for (int e = 0; e < 4; e++) {
                    int qrow = q0 + wid * 16 + (lane >> 2) + (e >> 1) * 8;
                    int kcol = k0 + nt * 8 + (lane & 3) * 2 + (e & 1);
                    if (kcol > qrow) sacc[nt][e] = -1e30f;
                }
        }

        // ---- online softmax ----
#pragma unroll
        for (int rr = 0; rr < 2; rr++) {
            float mx = -1e30f;
#pragma unroll
            for (int nt = 0; nt < 8; nt++)
                mx = fmaxf(mx, fmaxf(sacc[nt][rr*2], sacc[nt][rr*2+1]));
            mx = fmaxf(mx, __shfl_xor_sync(0xffffffffu, mx, 1));
            mx = fmaxf(mx, __shfl_xor_sync(0xffffffffu, mx, 2));
            const float m_new = fmaxf(m_i[rr], mx);
            const float mC = m_new * CEXP;
            const float alpha = ex2(m_i[rr] * CEXP - mC);
            float rs = 0.f;
#pragma unroll
            for (int nt = 0; nt < 8; nt++) {
                float p0 = ex2(sacc[nt][rr*2]   * CEXP - mC);
                float p1 = ex2(sacc[nt][rr*2+1] * CEXP - mC);
                sacc[nt][rr*2] = p0; sacc[nt][rr*2+1] = p1;
                rs += p0 + p1;
            }
            rs += __shfl_xor_sync(0xffffffffu, rs, 1);
            rs += __shfl_xor_sync(0xffffffffu, rs, 2);
            l_i[rr] = l_i[rr] * alpha + rs;
            m_i[rr] = m_new;
#pragma unroll
            for (int nd = 0; nd < 8; nd++) {
                Oacc[nd][rr*2]   *= alpha;
                Oacc[nd][rr*2+1] *= alpha;
            }
        }

        // ---- O += P V (fp16 P register-resident; fp16 V) ----
#pragma unroll
        for (int kc = 0; kc < 4; kc++) {
            uint32_t ph[4];
            ph[0] = packh(sacc[2*kc][0],   sacc[2*kc][1]);
            ph[1] = packh(sacc[2*kc][2],   sacc[2*kc][3]);
            ph[2] = packh(sacc[2*kc+1][0], sacc[2*kc+1][1]);
            ph[3] = packh(sacc[2*kc+1][2], sacc[2*kc+1][3]);
#pragma unroll
            for (int ndp = 0; ndp < 4; ndp++) {
                int row = kc * 16 + (lane & 7) + ((lane >> 3) & 1) * 8;
                uint32_t c = (uint32_t)(2 * ndp) + (uint32_t)(lane >> 4);
                uint32_t off = (uint32_t)(row * 128) + ((c ^ (uint32_t)(row & 7)) << 4);
                uint32_t bvh[4];
                ldm_x4t(bvh, st + 8192u + off);
#pragma unroll
                for (int nt2 = 0; nt2 < 2; nt2++) {
                    const int nd = ndp * 2 + nt2;
                    mma_h(Oacc[nd], ph, bvh[nt2*2], bvh[nt2*2+1]);
                }
            }
        }
    }

    // ---- epilogue: normalize, fp32 store ----
#pragma unroll
    for (int rr = 0; rr < 2; rr++) {
        const int row = wid * 16 + (lane >> 2) + rr * 8;
        const float inv = 1.f / l_i[rr];
        const size_t rb = (size_t)(qrow0 + row) * 2048 + hoff + (lane & 3) * 2;
#pragma unroll
        for (int nd = 0; nd < 8; nd++) {
            float v0 = Oacc[nd][rr*2]   * inv;
            float v1 = Oacc[nd][rr*2+1] * inv;
            *(float2*)(O + rb + nd * 8) = make_float2(v0, v1);
        }
    }
}

// ---------------------------------------------------------------------------
extern "C" void kernel_launch(void* const* d_in, const int* in_sizes, int n_in,
                              void* d_out, int out_size)
{
    const float* x  = (const float*)d_in[0];
    const float* Wq = (const float*)d_in[1];
    const float* bq = (const float*)d_in[2];
    const float* Wk = (const float*)d_in[3];
    const float* bk = (const float*)d_in[4];
    const float* Wv = (const float*)d_in[5];
    const float* bv = (const float*)d_in[6];
    const float* Wo = (const float*)d_in[7];
    const float* bo = (const float*)d_in[8];
    float* out = (float*)d_out;

    int8_t *x1, *x2, *a1, *a2;
    int8_t *wq1, *wq2, *wk1, *wk2, *wv1, *wv2, *wo1, *wo2;
    int8_t *q1, *q2, *k1, *k2;
    float *sx, *sa, *swq, *swk, *swv, *swo, *attn, *sq, *sk;
    __half *vh;
    cudaGetSymbolAddress((void**)&x1, g_x1);
    cudaGetSymbolAddress((void**)&x2, g_x2);
    cudaGetSymbolAddress((void**)&sx, g_sx);
    cudaGetSymbolAddress((void**)&a1, g_a1);
    cudaGetSymbolAddress((void**)&a2, g_a2);
    cudaGetSymbolAddress((void**)&sa, g_sa);
    cudaGetSymbolAddress((void**)&attn, g_attn);
    cudaGetSymbolAddress((void**)&wq1, g_wq1);
    cudaGetSymbolAddress((void**)&wq2, g_wq2);
    cudaGetSymbolAddress((void**)&swq, g_swq);
    cudaGetSymbolAddress((void**)&wk1, g_wk1);
    cudaGetSymbolAddress((void**)&wk2, g_wk2);
    cudaGetSymbolAddress((void**)&swk, g_swk);
    cudaGetSymbolAddress((void**)&wv1, g_wv1);
    cudaGetSymbolAddress((void**)&wv2, g_wv2);
    cudaGetSymbolAddress((void**)&swv, g_swv);
    cudaGetSymbolAddress((void**)&wo1, g_wo1);
    cudaGetSymbolAddress((void**)&wo2, g_wo2);
    cudaGetSymbolAddress((void**)&swo, g_swo);
    cudaGetSymbolAddress((void**)&q1, g_q1);
    cudaGetSymbolAddress((void**)&q2, g_q2);
    cudaGetSymbolAddress((void**)&k1, g_k1);
    cudaGetSymbolAddress((void**)&k2, g_k2);
    cudaGetSymbolAddress((void**)&sq, g_sq);
    cudaGetSymbolAddress((void**)&sk, g_sk);
    cudaGetSymbolAddress((void**)&vh, g_vh);

    cudaFuncSetAttribute(gemm_s8<0>,
                         cudaFuncAttributeMaxDynamicSharedMemorySize, GS8_SMEM);
    cudaFuncSetAttribute(gemm_s8<1>,
                         cudaFuncAttributeMaxDynamicSharedMemorySize, GS8_SMEM);
    cudaFuncSetAttribute(gemm_s8<2>,
                         cudaFuncAttributeMaxDynamicSharedMemorySize, GS8_SMEM);
    cudaFuncSetAttribute(flash_hyb,
                         cudaFuncAttributeMaxDynamicSharedMemorySize, FA_SMEM);

    RQArgs rx{x,  x1,  x2,  sx,  M_};
    RQArgs rq{Wq, wq1, wq2, swq, E_};
    RQArgs rk{Wk, wk1, wk2, swk, E_};
    RQArgs rv{Wv, wv1, wv2, swv, E_};
    RQArgs ro{Wo, wo1, wo2, swo, E_};
    rowquant5<<<dim3(M_, 5), 256>>>(rx, rq, rk, rv, ro);

    GArgs aq{wq1, wq2, swq, bq, nullptr, nullptr, q1, q2, sq};
    GArgs ak{wk1, wk2, swk, bk, nullptr, nullptr, k1, k2, sk};
    GArgs av{wv1, wv2, swv, bv, nullptr, vh, nullptr, nullptr, nullptr};
    GArgs ao{wo1, wo2, swo, bo, out, nullptr, nullptr, nullptr, nullptr};

    dim3 gqk(E_ / 128, M_ / 128, 2);
    gemm_s8<2><<<gqk, 256, GS8_SMEM>>>(x1, x2, sx, aq, ak, ak);
    dim3 gv(E_ / 128, M_ / 128, 1);
    gemm_s8<1><<<gv, 256, GS8_SMEM>>>(x1, x2, sx, av, av, av);

    dim3 ga(S_ / FQT, B_ * H_);     // (16, 64)
    flash_hyb<<<ga, 256, FA_SMEM>>>(q1, q2, sq, k1, k2, sk, vh, attn);

    rowquant<<<M_, 256>>>(attn, a1, a2, sa);

    dim3 go(E_ / 128, M_ / 128, 1);
    gemm_s8<0><<<go, 256, GS8_SMEM>>>(a1, a2, sa, ao, ao, ao);
}

// round 14
// speedup vs baseline: 1.3477x; 1.0132x over previous
#include <cuda_runtime.h>
#include <cuda_bf16.h>
#include <cuda_fp16.h>
#include <cstdint>
#include <math.h>

#define B_ 2
#define S_ 2048
#define E_ 2048
#define H_ 32
#define D_ 64
#define M_ (B_*S_)
#define SCALE_ 0.125f

// ---------------- scratch ----------------
static __device__ __align__(128) int8_t g_x1[(size_t)M_ * E_];
static __device__ __align__(128) int8_t g_x2[(size_t)M_ * E_];
static __device__ __align__(128) float  g_sx[M_];
static __device__ __align__(128) int8_t g_a1[(size_t)M_ * E_];
static __device__ __align__(128) int8_t g_a2[(size_t)M_ * E_];
static __device__ __align__(128) float  g_sa[M_];
static __device__ __align__(128) float  g_attn[(size_t)M_ * E_];

static __device__ __align__(128) int8_t g_wq1[(size_t)E_ * E_];
static __device__ __align__(128) int8_t g_wq2[(size_t)E_ * E_];
static __device__ __align__(128) float  g_swq[E_];
static __device__ __align__(128) int8_t g_wk1[(size_t)E_ * E_];
static __device__ __align__(128) int8_t g_wk2[(size_t)E_ * E_];
static __device__ __align__(128) float  g_swk[E_];
static __device__ __align__(128) int8_t g_wv1[(size_t)E_ * E_];
static __device__ __align__(128) int8_t g_wv2[(size_t)E_ * E_];
static __device__ __align__(128) float  g_swv[E_];
static __device__ __align__(128) int8_t g_wo1[(size_t)E_ * E_];
static __device__ __align__(128) int8_t g_wo2[(size_t)E_ * E_];
static __device__ __align__(128) float  g_swo[E_];

static __device__ __align__(128) int8_t g_q1[(size_t)M_ * E_];
static __device__ __align__(128) int8_t g_q2[(size_t)M_ * E_];
static __device__ __align__(128) int8_t g_k1[(size_t)M_ * E_];
static __device__ __align__(128) int8_t g_k2[(size_t)M_ * E_];
static __device__ __align__(128) float  g_sq[(size_t)H_ * M_];
static __device__ __align__(128) float  g_sk[(size_t)H_ * M_];

static __device__ __align__(128) __half g_vh[(size_t)M_ * E_];

// ---------------- helpers ----------------
__device__ __forceinline__ uint32_t smem_u32(const void* p) {
    uint32_t a;
    asm("{ .reg .u64 t; cvta.to.shared.u64 t, %1; cvt.u32.u64 %0, t; }"
        : "=r"(a) : "l"(p));
    return a;
}
__device__ __forceinline__ void cp_async16(uint32_t saddr, const void* gaddr) {
    asm volatile("cp.async.cg.shared.global [%0], [%1], 16;\n"
                 :: "r"(saddr), "l"(gaddr));
}
#define CP_COMMIT() asm volatile("cp.async.commit_group;\n" ::: "memory")
#define CP_WAIT0()  asm volatile("cp.async.wait_group 0;\n" ::: "memory")
#define CP_WAIT1()  asm volatile("cp.async.wait_group 1;\n" ::: "memory")
#define CP_WAIT2()  asm volatile("cp.async.wait_group 2;\n" ::: "memory")

__device__ __forceinline__ void ldm_x4(uint32_t* r, uint32_t addr) {
    asm volatile("ldmatrix.sync.aligned.m8n8.x4.shared.b16 {%0,%1,%2,%3}, [%4];"
                 : "=r"(r[0]), "=r"(r[1]), "=r"(r[2]), "=r"(r[3]) : "r"(addr));
}
__device__ __forceinline__ void ldm_x4t(uint32_t* r, uint32_t addr) {
    asm volatile("ldmatrix.sync.aligned.m8n8.x4.trans.shared.b16 {%0,%1,%2,%3}, [%4];"
                 : "=r"(r[0]), "=r"(r[1]), "=r"(r[2]), "=r"(r[3]) : "r"(addr));
}
__device__ __forceinline__ void mma_h(float* d, const uint32_t* a,
                                      uint32_t b0, uint32_t b1) {
    asm volatile(
        "mma.sync.aligned.m16n8k16.row.col.f32.f16.f16.f32 "
        "{%0,%1,%2,%3}, {%4,%5,%6,%7}, {%8,%9}, {%0,%1,%2,%3};"
        : "+f"(d[0]), "+f"(d[1]), "+f"(d[2]), "+f"(d[3])
        : "r"(a[0]), "r"(a[1]), "r"(a[2]), "r"(a[3]), "r"(b0), "r"(b1));
}
__device__ __forceinline__ void mma_s8(int* d, const uint32_t* a,
                                       uint32_t b0, uint32_t b1) {
    asm volatile(
        "mma.sync.aligned.m16n8k32.row.col.s32.s8.s8.s32 "
        "{%0,%1,%2,%3}, {%4,%5,%6,%7}, {%8,%9}, {%0,%1,%2,%3};"
        : "+r"(d[0]), "+r"(d[1]), "+r"(d[2]), "+r"(d[3])
        : "r"(a[0]), "r"(a[1]), "r"(a[2]), "r"(a[3]), "r"(b0), "r"(b1));
}
__device__ __forceinline__ uint32_t packh(float lo, float hi) {
    uint32_t d;
    asm("cvt.rn.f16x2.f32 %0, %1, %2;" : "=r"(d) : "f"(hi), "f"(lo));
    return d;
}
__device__ __forceinline__ uint32_t ex2h2(uint32_t x) {
    uint32_t y;
    asm("ex2.approx.f16x2 %0, %1;" : "=r"(y) : "r"(x));
    return y;
}
__device__ __forceinline__ float ex2(float x) {
    float y; asm("ex2.approx.f32 %0, %1;" : "=f"(y) : "f"(x)); return y;
}

// ---------------------------------------------------------------------------
// Row-wise two-level int8 quantization over 2048-col rows.
// ---------------------------------------------------------------------------
struct RQArgs { const float* src; int8_t* q1; int8_t* q2; float* s; int rows; };

__device__ __forceinline__ void rowquant_body(
    const float* __restrict__ x, int8_t* __restrict__ q1,
    int8_t* __restrict__ q2, float* __restrict__ s, int row, int t,
    float* wmax)
{
    const float* xr = x + (size_t)row * 2048 + t * 8;
    float4 v0 = ((const float4*)xr)[0];
    float4 v1 = ((const float4*)xr)[1];
    float vv[8] = {v0.x, v0.y, v0.z, v0.w, v1.x, v1.y, v1.z, v1.w};
    float m = 0.f;
#pragma unroll
    for (int j = 0; j < 8; j++) m = fmaxf(m, fabsf(vv[j]));
#pragma unroll
    for (int o = 16; o; o >>= 1) m = fmaxf(m, __shfl_xor_sync(~0u, m, o));
    if ((t & 31) == 0) wmax[t >> 5] = m;
    __syncthreads();
    float mm = wmax[0];
#pragma unroll
    for (int i = 1; i < 8; i++) mm = fmaxf(mm, wmax[i]);
    mm = fmaxf(mm, 1e-20f);
    if (t == 0) s[row] = mm * (1.f / 127.f);
    const float inv = 127.f / mm;

    uint32_t p1[2] = {0, 0}, p2[2] = {0, 0};
#pragma unroll
    for (int j = 0; j < 8; j++) {
        float xs = vv[j] * inv;
        float qf = rintf(xs);
        float rf = rintf((xs - qf) * 254.f);
        int iq = (int)qf, ir = (int)rf;
        p1[j >> 2] |= (uint32_t)(iq & 0xff) << ((j & 3) * 8);
        p2[j >> 2] |= (uint32_t)(ir & 0xff) << ((j & 3) * 8);
    }
    ((uint32_t*)q1)[row * 512 + t * 2]     = p1[0];
    ((uint32_t*)q1)[row * 512 + t * 2 + 1] = p1[1];
    ((uint32_t*)q2)[row * 512 + t * 2]     = p2[0];
    ((uint32_t*)q2)[row * 512 + t * 2 + 1] = p2[1];
}

__global__ __launch_bounds__(256) void rowquant(
    const float* __restrict__ x, int8_t* __restrict__ q1,
    int8_t* __restrict__ q2, float* __restrict__ s)
{
    __shared__ float wmax[8];
    rowquant_body(x, q1, q2, s, blockIdx.x, threadIdx.x, wmax);
}

__global__ __launch_bounds__(256) void rowquant5(
    RQArgs a0, RQArgs a1, RQArgs a2, RQArgs a3, RQArgs a4)
{
    __shared__ float wmax[8];
    RQArgs a = (blockIdx.y == 0) ? a0 : (blockIdx.y == 1) ? a1
             : (blockIdx.y == 2) ? a2 : (blockIdx.y == 3) ? a3 : a4;
    if ((int)blockIdx.x >= a.rows) return;
    rowquant_body(a.src, a.q1, a.q2, a.s, blockIdx.x, threadIdx.x, wmax);
}

// ---------------------------------------------------------------------------
// Two-level int8 GEMM.
// EPI 0: fp32 C + bias.
// EPI 3: merged QKV — z<2: fused int8 quant (Q/K); z==2: fp16 C (V).
// ---------------------------------------------------------------------------
#define GK 2048
#define NCH8 32
#define SSTG 32768
#define GS8_SMEM (3 * SSTG)

struct GArgs {
    const int8_t *B1, *B2;
    const float* sB;
    const float* bias;
    float* C;
    __half* Ch;
    int8_t *Q1, *Q2;
    float* SQ;
};

__device__ __forceinline__ void s8_load(
    const int8_t* __restrict__ A1, const int8_t* __restrict__ A2,
    const int8_t* __restrict__ B1, const int8_t* __restrict__ B2,
    int m0, int n0, int k0, uint32_t sb, int t)
{
#pragma unroll
    for (int i = 0; i < 2; i++) {
        int idx = t + i * 256, r = idx >> 2, c = idx & 3;
        uint32_t so = (uint32_t)(r * 64 + (((c ^ ((r >> 1) & 3))) << 4));
        size_t ga = (size_t)(m0 + r) * GK + k0 + c * 16;
        size_t gb = (size_t)(n0 + r) * GK + k0 + c * 16;
        cp_async16(sb +          so, A1 + ga);
        cp_async16(sb +  8192u + so, A2 + ga);
        cp_async16(sb + 16384u + so, B1 + gb);
        cp_async16(sb + 24576u + so, B2 + gb);
    }
}

template<int EPI>
__global__ __launch_bounds__(256, 1) void gemm_s8(
    const int8_t* __restrict__ A1, const int8_t* __restrict__ A2,
    const float* __restrict__ sA, GArgs a0, GArgs a1, GArgs a2)
{
    extern __shared__ char smem[];
    const uint32_t sbase = smem_u32(smem);
    const GArgs ga = (blockIdx.z == 0) ? a0 : (blockIdx.z == 1) ? a1 : a2;
    const int t = threadIdx.x, lane = t & 31, wid = t >> 5;
    const int warp_m = wid >> 2, warp_n = wid & 3;
    const int m0 = blockIdx.y * 128;
    const int n0 = blockIdx.x * 128;

    int a_row[4], b_row[2];
    uint32_t a_sw[4], b_sw[2];
#pragma unroll
    for (int mt = 0; mt < 4; mt++) {
        a_row[mt] = warp_m * 64 + mt * 16 + (lane & 15);
        a_sw[mt]  = (uint32_t)((a_row[mt] >> 1) & 3);
    }
#pragma unroll
    for (int pt = 0; pt < 2; pt++) {
        b_row[pt] = warp_n * 32 + pt * 16 + (lane & 7) + ((lane >> 4) & 1) * 8;
        b_sw[pt]  = (uint32_t)((b_row[pt] >> 1) & 3);
    }
    const uint32_t a_ch = (uint32_t)(lane >> 4);
    const uint32_t b_ch = (uint32_t)((lane >> 3) & 1);

    int acc1[4][4][4], acc2[4][4][4];
#pragma unroll
    for (int i = 0; i < 4; i++)
#pragma unroll
        for (int j = 0; j < 4; j++)
#pragma unroll
            for (int q = 0; q < 4; q++) { acc1[i][j][q] = 0; acc2[i][j][q] = 0; }

    s8_load(A1, A2, ga.B1, ga.B2, m0, n0, 0,   sbase,            t); CP_COMMIT();
    s8_load(A1, A2, ga.B1, ga.B2, m0, n0, 64,  sbase + SSTG,     t); CP_COMMIT();
    s8_load(A1, A2, ga.B1, ga.B2, m0, n0, 128, sbase + 2 * SSTG, t); CP_COMMIT();

    uint32_t stg = 0;
    for (int ch = 0; ch < NCH8; ch++) {
        CP_WAIT2();
        __syncthreads();
        const uint32_t sb = sbase + stg * SSTG;

#pragma unroll
        for (int s = 0; s < 2; s++) {
            uint32_t Af1[4][4], Af2[4][4];
            uint32_t Bf1[2][4], Bf2[2][4];
#pragma unroll
            for (int mt = 0; mt < 4; mt++) {
                uint32_t c = (uint32_t)(s * 2) + a_ch;
                uint32_t off = (uint32_t)(a_row[mt] * 64) + ((c ^ a_sw[mt]) << 4);
                ldm_x4(Af1[mt], sb + off);
                ldm_x4(Af2[mt], sb + 8192u + off);
            }
#pragma unroll
            for (int pt = 0; pt < 2; pt++) {
                uint32_t c = (uint32_t)(s * 2) + b_ch;
                uint32_t off = (uint32_t)(b_row[pt] * 64) + ((c ^ b_sw[pt]) << 4);
                ldm_x4(Bf1[pt], sb + 16384u + off);
                ldm_x4(Bf2[pt], sb + 24576u + off);
            }
#pragma unroll
            for (int mt = 0; mt < 4; mt++)
#pragma unroll
                for (int nt = 0; nt < 4; nt++) {
                    const int pt = nt >> 1, hl = (nt & 1) * 2;
                    mma_s8(acc1[mt][nt], Af1[mt], Bf1[pt][hl], Bf1[pt][hl+1]);
                    mma_s8(acc2[mt][nt], Af1[mt], Bf2[pt][hl], Bf2[pt][hl+1]);
                    mma_s8(acc2[mt][nt], Af2[mt], Bf1[pt][hl], Bf1[pt][hl+1]);
                }
        }
        __syncthreads();
        if (ch + 3 < NCH8)
            s8_load(A1, A2, ga.B1, ga.B2, m0, n0, (ch + 3) * 64,
                    sbase + stg * SSTG, t);
        CP_COMMIT();
        stg = (stg == 2) ? 0 : stg + 1;
    }

    const float R = 1.f / 254.f;
    if (EPI == 0 || (EPI == 3 && blockIdx.z == 2)) {
#pragma unroll
        for (int mt = 0; mt < 4; mt++) {
            const int r0 = m0 + warp_m * 64 + mt * 16 + (lane >> 2);
            const float sa0 = sA[r0], sa1 = sA[r0 + 8];
#pragma unroll
            for (int nt = 0; nt < 4; nt++) {
                const int cc = n0 + warp_n * 32 + nt * 8 + (lane & 3) * 2;
                const float sb0 = ga.sB[cc], sb1 = ga.sB[cc + 1];
                const float bx = ga.bias[cc], by = ga.bias[cc + 1];
                float v0 = ((float)acc1[mt][nt][0] + (float)acc2[mt][nt][0] * R) * (sa0 * sb0) + bx;
                float v1 = ((float)acc1[mt][nt][1] + (float)acc2[mt][nt][1] * R) * (sa0 * sb1) + by;
                float v2 = ((float)acc1[mt][nt][2] + (float)acc2[mt][nt][2] * R) * (sa1 * sb0) + bx;
                float v3 = ((float)acc1[mt][nt][3] + (float)acc2[mt][nt][3] * R) * (sa1 * sb1) + by;
                if (EPI == 0) {
                    *(float2*)(ga.C + (size_t)r0 * GK + cc)       = make_float2(v0, v1);
                    *(float2*)(ga.C + (size_t)(r0 + 8) * GK + cc) = make_float2(v2, v3);
                } else {
                    *(uint32_t*)(ga.Ch + (size_t)r0 * GK + cc)       = packh(v0, v1);
                    *(uint32_t*)(ga.Ch + (size_t)(r0 + 8) * GK + cc) = packh(v2, v3);
                }
            }
        }
    } else {
        // fused per-(row, 64-col head) two-level int8 quantization (Q/K)
        CP_WAIT0();
        __syncthreads();
        float* red = (float*)smem;      // 8 warps x 64 rows
        const int rbase = wid * 64;
#pragma unroll
        for (int mt = 0; mt < 4; mt++) {
            const int r0g = m0 + warp_m * 64 + mt * 16 + (lane >> 2);
            const float sa0 = sA[r0g], sa1 = sA[r0g + 8];
#pragma unroll
            for (int rr = 0; rr < 2; rr++) {
                const float sa = rr ? sa1 : sa0;
                float mx = 0.f;
#pragma unroll
                for (int nt = 0; nt < 4; nt++) {
                    const int cc = n0 + warp_n * 32 + nt * 8 + (lane & 3) * 2;
                    float v0 = ((float)acc1[mt][nt][rr*2]   + (float)acc2[mt][nt][rr*2]   * R)
                               * (sa * ga.sB[cc])     + ga.bias[cc];
                    float v1 = ((float)acc1[mt][nt][rr*2+1] + (float)acc2[mt][nt][rr*2+1] * R)
                               * (sa * ga.sB[cc + 1]) + ga.bias[cc + 1];
                    mx = fmaxf(mx, fmaxf(fabsf(v0), fabsf(v1)));
                }
                mx = fmaxf(mx, __shfl_xor_sync(~0u, mx, 1));
                mx = fmaxf(mx, __shfl_xor_sync(~0u, mx, 2));
                red[rbase + mt * 16 + rr * 8 + (lane >> 2)] = mx;
            }
        }
        __syncthreads();
        const int h = (n0 >> 6) + (warp_n >> 1);
#pragma unroll
        for (int mt = 0; mt < 4; mt++) {
            const int r0g = m0 + warp_m * 64 + mt * 16 + (lane >> 2);
            const float sa0 = sA[r0g], sa1 = sA[r0g + 8];
#pragma unroll
            for (int rr = 0; rr < 2; rr++) {
                const float sa = rr ? sa1 : sa0;
                const int idx = mt * 16 + rr * 8 + (lane >> 2);
                float m2 = fmaxf(red[rbase + idx], red[(rbase ^ 64) + idx]);
                m2 = fmaxf(m2, 1e-20f);
                const int grow = r0g + rr * 8;
                if ((lane & 3) == 0)
                    ga.SQ[(size_t)h * M_ + grow] = m2 * (1.f / 127.f);
                const float inv = 127.f / m2;
#pragma unroll
                for (int nt = 0; nt < 4; nt++) {
                    const int cc = n0 + warp_n * 32 + nt * 8 + (lane & 3) * 2;
                    float v0 = ((float)acc1[mt][nt][rr*2]   + (float)acc2[mt][nt][rr*2]   * R)
                               * (sa * ga.sB[cc])     + ga.bias[cc];
                    float v1 = ((float)acc1[mt][nt][rr*2+1] + (float)acc2[mt][nt][rr*2+1] * R)
                               * (sa * ga.sB[cc + 1]) + ga.bias[cc + 1];
                    float A0 = v0 * inv, A1v = v1 * inv;
                    float f0 = rintf(A0), f1 = rintf(A1v);
                    int i0 = (int)f0, i1 = (int)f1;
                    int r0v = (int)rintf((A0 - f0) * 254.f);
                    int r1v = (int)rintf((A1v - f1) * 254.f);
                    *(uint16_t*)(ga.Q1 + (size_t)grow * 2048 + cc) =
                        (uint16_t)((i0 & 0xff) | ((i1 & 0xff) << 8));
                    *(uint16_t*)(ga.Q2 + (size_t)grow * 2048 + cc) =
                        (uint16_t)((r0v & 0xff) | ((r1v & 0xff) << 8));
                }
            }
        }
    }
}

// ---------------------------------------------------------------------------
// Hybrid flash attention (causal): int8 two-level QK, fp16 P x fp16 V PV.
// exp in f16x2 (MUFU halved), row-sum l via ones-vector MMA, IMAD dequant.
// FQT=128 (16 rows/warp), 2 CTAs/SM.
// smem: 2 stages x (k1 4K | k2 4K | vh 8K) = 32K; k-scales at 32768 (+512).
// ---------------------------------------------------------------------------
#define FQT 128
#define FKT 64
#define STG_SZ 16384u
#define SCOFF 32768u
#define FA_SMEM 33280

__global__ __launch_bounds__(256, 2) void flash_hyb(
    const int8_t* __restrict__ q1g, const int8_t* __restrict__ q2g,
    const float* __restrict__ sqg,
    const int8_t* __restrict__ k1g, const int8_t* __restrict__ k2g,
    const float* __restrict__ skg,
    const __half* __restrict__ Vh,
    float* __restrict__ O)
{
    extern __shared__ char smem[];
    const uint32_t sb = smem_u32(smem);
    const int t = threadIdx.x, lane = t & 31, wid = t >> 5;
    const int qt = (int)gridDim.x - 1 - (int)blockIdx.x;   // heavy tiles first
    const int bh = blockIdx.y;
    const int b = bh >> 5, h = bh & 31;
    const int q0 = qt * FQT;
    const int qrow0 = b * S_ + q0;
    const int krow0 = b * S_;
    const int hoff = h * D_;
    const size_t vbase = ((size_t)b * S_) * E_ + hoff;
    const float* skh = skg + (size_t)h * M_ + b * S_;
    const float CEXP = SCALE_ * 1.4426950408889634f;
    const float CR = CEXP * (1.f / 254.f);
    const uint32_t HONES = 0x3C003C00u;   // fp16 {1, 1}

    // ---- stage Q (int8, both levels): 128 rows x 64B per level = 8K each ----
#pragma unroll
    for (int i = 0; i < 2; i++) {
        int idx = t + i * 256, r = idx >> 2, c = idx & 3;
        uint32_t so = (uint32_t)(r * 64 + ((c ^ ((r >> 1) & 3)) << 4));
        size_t g = (size_t)(qrow0 + r) * 2048 + hoff + c * 16;
        cp_async16(sb +         so, q1g + g);
        cp_async16(sb + 8192u + so, q2g + g);
    }
    CP_COMMIT(); CP_WAIT0();
    __syncthreads();

    uint32_t fq1[2][4], fq2[2][4];
#pragma unroll
    for (int kc = 0; kc < 2; kc++) {
        int row = wid * 16 + (lane & 15);
        uint32_t c = (uint32_t)(kc * 2 + (lane >> 4));
        uint32_t off = (uint32_t)(row * 64) + ((c ^ (uint32_t)((row >> 1) & 3)) << 4);
        ldm_x4(fq1[kc], sb + off);
        ldm_x4(fq2[kc], sb + 8192u + off);
    }
    float sqv[2];
#pragma unroll
    for (int rr = 0; rr < 2; rr++)
        sqv[rr] = sqg[(size_t)h * M_ + qrow0 + wid * 16 + (lane >> 2) + rr * 8];
    __syncthreads();   // Q area now reusable for KV stages

    const int jmax = 2 * (qt + 1);
    {   // KV tile 0 -> stage 0
        int r = t >> 2, c = t & 3;
        uint32_t so = (uint32_t)(r * 64 + ((c ^ ((r >> 1) & 3)) << 4));
        size_t gk = (size_t)(krow0 + r) * 2048 + hoff + c * 16;
        cp_async16(sb +         so, k1g + gk);
        cp_async16(sb + 4096u + so, k2g + gk);
        if (t < 16) cp_async16(sb + SCOFF + t * 16u, skh + t * 4);
    }
#pragma unroll
    for (int i = 0; i < 2; i++) {      // V fp16: 64 rows x 128B
        int idx = t + i * 256, r = idx >> 3, c = idx & 7;
        uint32_t so = (uint32_t)(r * 128 + ((c ^ (r & 7)) << 4));
        size_t g = vbase + (size_t)r * E_ + c * 8;
        cp_async16(sb + 8192u + so, Vh + g);
    }
    CP_COMMIT();

    float Oacc[8][4];
#pragma unroll
    for (int j = 0; j < 8; j++)
#pragma unroll
        for (int q = 0; q < 4; q++) Oacc[j][q] = 0.f;
    float lacc[4] = {0.f, 0.f, 0.f, 0.f};
    float m_i[2] = {-1e30f, -1e30f};

    for (int jt = 0; jt < jmax; jt++) {
        const int k0 = jt * FKT;
        __syncthreads();
        if (jt + 1 < jmax) {
            uint32_t st = (uint32_t)((jt + 1) & 1) * STG_SZ;
            {
                int r = t >> 2, c = t & 3;
                uint32_t so = (uint32_t)(r * 64 + ((c ^ ((r >> 1) & 3)) << 4));
                size_t gk = (size_t)(krow0 + k0 + FKT + r) * 2048 + hoff + c * 16;
                cp_async16(sb + st +         so, k1g + gk);
                cp_async16(sb + st + 4096u + so, k2g + gk);
                if (t < 16)
                    cp_async16(sb + SCOFF + (uint32_t)((jt + 1) & 1) * 256u + t * 16u,
                               skh + k0 + FKT + t * 4);
            }
#pragma unroll
            for (int i = 0; i < 2; i++) {
                int idx = t + i * 256, r = idx >> 3, c = idx & 7;
                uint32_t so = (uint32_t)(r * 128 + ((c ^ (r & 7)) << 4));
                size_t g = vbase + (size_t)(k0 + FKT + r) * E_ + c * 8;
                cp_async16(sb + st + 8192u + so, Vh + g);
            }
        }
        CP_COMMIT(); CP_WAIT1();
        __syncthreads();
        const uint32_t st = sb + (uint32_t)(jt & 1) * STG_SZ;
        const float* sks = (const float*)(smem + SCOFF + (jt & 1) * 256);

        // ---- S = Q K^T (int8 two-level), dequant to exponent domain ----
        float sacc[8][4];
#pragma unroll
        for (int kh = 0; kh < 2; kh++) {
            int i1[4][4], i2[4][4];
#pragma unroll
            for (int j = 0; j < 4; j++)
#pragma unroll
                for (int q = 0; q < 4; q++) { i1[j][q] = 0; i2[j][q] = 0; }
#pragma unroll
            for (int kc = 0; kc < 2; kc++) {
                uint32_t bk1[2][4], bk2[2][4];
#pragma unroll
                for (int np2 = 0; np2 < 2; np2++) {
                    int row = (kh * 2 + np2) * 16 + (lane & 7) + ((lane >> 4) & 1) * 8;
                    uint32_t c = (uint32_t)(kc * 2 + ((lane >> 3) & 1));
                    uint32_t off = (uint32_t)(row * 64) + ((c ^ (uint32_t)((row >> 1) & 3)) << 4);
                    ldm_x4(bk1[np2], st + off);
                    ldm_x4(bk2[np2], st + 4096u + off);
                }
#pragma unroll
                for (int np2 = 0; np2 < 2; np2++)
#pragma unroll
                    for (int nt2 = 0; nt2 < 2; nt2++) {
                        const int sl = np2 * 2 + nt2, hl = nt2 * 2;
                        mma_s8(i1[sl], fq1[kc], bk1[np2][hl], bk1[np2][hl+1]);
                        mma_s8(i2[sl], fq1[kc], bk2[np2][hl], bk2[np2][hl+1]);
                        mma_s8(i2[sl], fq2[kc], bk1[np2][hl], bk1[np2][hl+1]);
                    }
            }
#pragma unroll
            for (int sl = 0; sl < 4; sl++) {
                const int nt = kh * 4 + sl;
                const int c0 = nt * 8 + (lane & 3) * 2;
                const float kc0 = sks[c0] * CR, kc1 = sks[c0 + 1] * CR;
#pragma unroll
                for (int rr = 0; rr < 2; rr++) {
                    const float t0 = kc0 * sqv[rr], t1 = kc1 * sqv[rr];
                    sacc[nt][rr*2]   = t0 * (float)(i1[sl][rr*2]   * 254 + i2[sl][rr*2]);
                    sacc[nt][rr*2+1] = t1 * (float)(i1[sl][rr*2+1] * 254 + i2[sl][rr*2+1]);
                }
            }
        }

        // ---- causal mask (exponent domain) ----
        if (k0 + FKT - 1 > q0) {
#pragma unroll
            for (int nt = 0; nt < 8; nt++)
#pragma unroll
                for (int e = 0; e < 4; e++) {
                    int qrow = q0 + wid * 16 + (lane >> 2) + (e >> 1) * 8;
                    int kcol = k0 + nt * 8 + (lane & 3) * 2 + (e & 1);
                    if (kcol > qrow) sacc[nt][e] = -1e30f;
                }
        }

        // ---- online max + rescale ----
        float m_new[2], alpha[2];
#pragma unroll
        for (int rr = 0; rr < 2; rr++) {
            float mx = -1e30f;
#pragma unroll
            for (int nt = 0; nt < 8; nt++)
                mx = fmaxf(mx, fmaxf(sacc[nt][rr*2], sacc[nt][rr*2+1]));
            mx = fmaxf(mx, __shfl_xor_sync(0xffffffffu, mx, 1));
            mx = fmaxf(mx, __shfl_xor_sync(0xffffffffu, mx, 2));
            m_new[rr] = fmaxf(m_i[rr], mx);
            alpha[rr] = ex2(m_i[rr] - m_new[rr]);
            m_i[rr] = m_new[rr];
#pragma unroll
            for (int nd = 0; nd < 8; nd++) {
                Oacc[nd][rr*2]   *= alpha[rr];
                Oacc[nd][rr*2+1] *= alpha[rr];
            }
        }
        lacc[0] *= alpha[0]; lacc[1] *= alpha[0];
        lacc[2] *= alpha[1]; lacc[3] *= alpha[1];

        // ---- O += P V, l += P 1 (p computed via f16x2 ex2 on the fly) ----
#pragma unroll
        for (int kc = 0; kc < 4; kc++) {
            uint32_t ph[4];
            ph[0] = ex2h2(packh(sacc[2*kc][0]   - m_new[0], sacc[2*kc][1]   - m_new[0]));
            ph[1] = ex2h2(packh(sacc[2*kc][2]   - m_new[1], sacc[2*kc][3]   - m_new[1]));
            ph[2] = ex2h2(packh(sacc[2*kc+1][0] - m_new[0], sacc[2*kc+1][1] - m_new[0]));
            ph[3] = ex2h2(packh(sacc[2*kc+1][2] - m_new[1], sacc[2*kc+1][3] - m_new[1]));
            mma_h(lacc, ph, HONES, HONES);
#pragma unroll
            for (int ndp = 0; ndp < 4; ndp++) {
                int row = kc * 16 + (lane & 7) + ((lane >> 3) & 1) * 8;
                uint32_t c = (uint32_t)(2 * ndp) + (uint32_t)(lane >> 4);
                uint32_t off = (uint32_t)(row * 128) + ((c ^ (uint32_t)(row & 7)) << 4);
                uint32_t bvh[4];
                ldm_x4t(bvh, st + 8192u + off);
#pragma unroll
                for (int nt2 = 0; nt2 < 2; nt2++) {
                    const int nd = ndp * 2 + nt2;
                    mma_h(Oacc[nd], ph, bvh[nt2*2], bvh[nt2*2+1]);
                }
            }
        }
    }

    // ---- epilogue: normalize, fp32 store ----
#pragma unroll
    for (int rr = 0; rr < 2; rr++) {
        const int row = wid * 16 + (lane >> 2) + rr * 8;
        const float inv = 1.f / lacc[rr * 2];
        const size_t rb = (size_t)(qrow0 + row) * 2048 + hoff + (lane & 3) * 2;
#pragma unroll
        for (int nd = 0; nd < 8; nd++) {
            float v0 = Oacc[nd][rr*2]   * inv;
            float v1 = Oacc[nd][rr*2+1] * inv;
            *(float2*)(O + rb + nd * 8) = make_float2(v0, v1);
        }
    }
}

// ---------------------------------------------------------------------------
extern "C" void kernel_launch(void* const* d_in, const int* in_sizes, int n_in,
                              void* d_out, int out_size)
{
    const float* x  = (const float*)d_in[0];
    const float* Wq = (const float*)d_in[1];
    const float* bq = (const float*)d_in[2];
    const float* Wk = (const float*)d_in[3];
    const float* bk = (const float*)d_in[4];
    const float* Wv = (const float*)d_in[5];
    const float* bv = (const float*)d_in[6];
    const float* Wo = (const float*)d_in[7];
    const float* bo = (const float*)d_in[8];
    float* out = (float*)d_out;

    int8_t *x1, *x2, *a1, *a2;
    int8_t *wq1, *wq2, *wk1, *wk2, *wv1, *wv2, *wo1, *wo2;
    int8_t *q1, *q2, *k1, *k2;
    float *sx, *sa, *swq, *swk, *swv, *swo, *attn, *sq, *sk;
    __half *vh;
    cudaGetSymbolAddress((void**)&x1, g_x1);
    cudaGetSymbolAddress((void**)&x2, g_x2);
    cudaGetSymbolAddress((void**)&sx, g_sx);
    cudaGetSymbolAddress((void**)&a1, g_a1);
    cudaGetSymbolAddress((void**)&a2, g_a2);
    cudaGetSymbolAddress((void**)&sa, g_sa);
    cudaGetSymbolAddress((void**)&attn, g_attn);
    cudaGetSymbolAddress((void**)&wq1, g_wq1);
    cudaGetSymbolAddress((void**)&wq2, g_wq2);
    cudaGetSymbolAddress((void**)&swq, g_swq);
    cudaGetSymbolAddress((void**)&wk1, g_wk1);
    cudaGetSymbolAddress((void**)&wk2, g_wk2);
    cudaGetSymbolAddress((void**)&swk, g_swk);
    cudaGetSymbolAddress((void**)&wv1, g_wv1);
    cudaGetSymbolAddress((void**)&wv2, g_wv2);
    cudaGetSymbolAddress((void**)&swv, g_swv);
    cudaGetSymbolAddress((void**)&wo1, g_wo1);
    cudaGetSymbolAddress((void**)&wo2, g_wo2);
    cudaGetSymbolAddress((void**)&swo, g_swo);
    cudaGetSymbolAddress((void**)&q1, g_q1);
    cudaGetSymbolAddress((void**)&q2, g_q2);
    cudaGetSymbolAddress((void**)&k1, g_k1);
    cudaGetSymbolAddress((void**)&k2, g_k2);
    cudaGetSymbolAddress((void**)&sq, g_sq);
    cudaGetSymbolAddress((void**)&sk, g_sk);
    cudaGetSymbolAddress((void**)&vh, g_vh);

    cudaFuncSetAttribute(gemm_s8<0>,
                         cudaFuncAttributeMaxDynamicSharedMemorySize, GS8_SMEM);
    cudaFuncSetAttribute(gemm_s8<3>,
                         cudaFuncAttributeMaxDynamicSharedMemorySize, GS8_SMEM);
    cudaFuncSetAttribute(flash_hyb,
                         cudaFuncAttributeMaxDynamicSharedMemorySize, FA_SMEM);

    RQArgs rx{x,  x1,  x2,  sx,  M_};
    RQArgs rq{Wq, wq1, wq2, swq, E_};
    RQArgs rk{Wk, wk1, wk2, swk, E_};
    RQArgs rv{Wv, wv1, wv2, swv, E_};
    RQArgs ro{Wo, wo1, wo2, swo, E_};
    rowquant5<<<dim3(M_, 5), 256>>>(rx, rq, rk, rv, ro);

    GArgs aq{wq1, wq2, swq, bq, nullptr, nullptr, q1, q2, sq};
    GArgs ak{wk1, wk2, swk, bk, nullptr, nullptr, k1, k2, sk};
    GArgs av{wv1, wv2, swv, bv, nullptr, vh, nullptr, nullptr, nullptr};
    GArgs ao{wo1, wo2, swo, bo, out, nullptr, nullptr, nullptr, nullptr};

    dim3 gqkv(E_ / 128, M_ / 128, 3);
    gemm_s8<3><<<gqkv, 256, GS8_SMEM>>>(x1, x2, sx, aq, ak, av);

    dim3 ga(S_ / FQT, B_ * H_);     // (16, 64)
    flash_hyb<<<ga, 256, FA_SMEM>>>(q1, q2, sq, k1, k2, sk, vh, attn);

    rowquant<<<M_, 256>>>(attn, a1, a2, sa);

    dim3 go(E_ / 128, M_ / 128, 1);
    gemm_s8<0><<<go, 256, GS8_SMEM>>>(a1, a2, sa, ao, ao, ao);
}

// round 15
// speedup vs baseline: 1.3609x; 1.0098x over previous
#include <cuda_runtime.h>
#include <cuda_bf16.h>
#include <cuda_fp16.h>
#include <cstdint>
#include <math.h>

#define B_ 2
#define S_ 2048
#define E_ 2048
#define H_ 32
#define D_ 64
#define M_ (B_*S_)
#define SCALE_ 0.125f

// ---------------- scratch ----------------
static __device__ __align__(128) int8_t g_x1[(size_t)M_ * E_];
static __device__ __align__(128) int8_t g_x2[(size_t)M_ * E_];
static __device__ __align__(128) float  g_sx[M_];
static __device__ __align__(128) int8_t g_a1[(size_t)M_ * E_];
static __device__ __align__(128) int8_t g_a2[(size_t)M_ * E_];
static __device__ __align__(128) float  g_sa[M_];
static __device__ __align__(128) float  g_attn[(size_t)M_ * E_];

static __device__ __align__(128) int8_t g_wq1[(size_t)E_ * E_];
static __device__ __align__(128) int8_t g_wq2[(size_t)E_ * E_];
static __device__ __align__(128) float  g_swq[E_];
static __device__ __align__(128) int8_t g_wk1[(size_t)E_ * E_];
static __device__ __align__(128) int8_t g_wk2[(size_t)E_ * E_];
static __device__ __align__(128) float  g_swk[E_];
static __device__ __align__(128) int8_t g_wv1[(size_t)E_ * E_];
static __device__ __align__(128) int8_t g_wv2[(size_t)E_ * E_];
static __device__ __align__(128) float  g_swv[E_];
static __device__ __align__(128) int8_t g_wo1[(size_t)E_ * E_];
static __device__ __align__(128) int8_t g_wo2[(size_t)E_ * E_];
static __device__ __align__(128) float  g_swo[E_];

static __device__ __align__(128) int8_t g_q1[(size_t)M_ * E_];
static __device__ __align__(128) int8_t g_q2[(size_t)M_ * E_];
static __device__ __align__(128) int8_t g_k1[(size_t)M_ * E_];
static __device__ __align__(128) int8_t g_k2[(size_t)M_ * E_];
static __device__ __align__(128) float  g_sq[(size_t)H_ * M_];
static __device__ __align__(128) float  g_sk[(size_t)H_ * M_];

static __device__ __align__(128) __half g_vh[(size_t)M_ * E_];

// ---------------- helpers ----------------
__device__ __forceinline__ uint32_t smem_u32(const void* p) {
    uint32_t a;
    asm("{ .reg .u64 t; cvta.to.shared.u64 t, %1; cvt.u32.u64 %0, t; }"
        : "=r"(a) : "l"(p));
    return a;
}
__device__ __forceinline__ void cp_async16(uint32_t saddr, const void* gaddr) {
    asm volatile("cp.async.cg.shared.global [%0], [%1], 16;\n"
                 :: "r"(saddr), "l"(gaddr));
}
#define CP_COMMIT() asm volatile("cp.async.commit_group;\n" ::: "memory")
#define CP_WAIT0()  asm volatile("cp.async.wait_group 0;\n" ::: "memory")
#define CP_WAIT1()  asm volatile("cp.async.wait_group 1;\n" ::: "memory")
#define CP_WAIT2()  asm volatile("cp.async.wait_group 2;\n" ::: "memory")

__device__ __forceinline__ void ldm_x4(uint32_t* r, uint32_t addr) {
    asm volatile("ldmatrix.sync.aligned.m8n8.x4.shared.b16 {%0,%1,%2,%3}, [%4];"
                 : "=r"(r[0]), "=r"(r[1]), "=r"(r[2]), "=r"(r[3]) : "r"(addr));
}
__device__ __forceinline__ void ldm_x4t(uint32_t* r, uint32_t addr) {
    asm volatile("ldmatrix.sync.aligned.m8n8.x4.trans.shared.b16 {%0,%1,%2,%3}, [%4];"
                 : "=r"(r[0]), "=r"(r[1]), "=r"(r[2]), "=r"(r[3]) : "r"(addr));
}
__device__ __forceinline__ void mma_h(float* d, const uint32_t* a,
                                      uint32_t b0, uint32_t b1) {
    asm volatile(
        "mma.sync.aligned.m16n8k16.row.col.f32.f16.f16.f32 "
        "{%0,%1,%2,%3}, {%4,%5,%6,%7}, {%8,%9}, {%0,%1,%2,%3};"
        : "+f"(d[0]), "+f"(d[1]), "+f"(d[2]), "+f"(d[3])
        : "r"(a[0]), "r"(a[1]), "r"(a[2]), "r"(a[3]), "r"(b0), "r"(b1));
}
__device__ __forceinline__ void mma_s8(int* d, const uint32_t* a,
                                       uint32_t b0, uint32_t b1) {
    asm volatile(
        "mma.sync.aligned.m16n8k32.row.col.s32.s8.s8.s32 "
        "{%0,%1,%2,%3}, {%4,%5,%6,%7}, {%8,%9}, {%0,%1,%2,%3};"
        : "+r"(d[0]), "+r"(d[1]), "+r"(d[2]), "+r"(d[3])
        : "r"(a[0]), "r"(a[1]), "r"(a[2]), "r"(a[3]), "r"(b0), "r"(b1));
}
__device__ __forceinline__ uint32_t packh(float lo, float hi) {
    uint32_t d;
    asm("cvt.rn.f16x2.f32 %0, %1, %2;" : "=r"(d) : "f"(hi), "f"(lo));
    return d;
}
__device__ __forceinline__ uint32_t ex2h2(uint32_t x) {
    uint32_t y;
    asm("ex2.approx.f16x2 %0, %1;" : "=r"(y) : "r"(x));
    return y;
}
__device__ __forceinline__ float ex2(float x) {
    float y; asm("ex2.approx.f32 %0, %1;" : "=f"(y) : "f"(x)); return y;
}

// ---------------------------------------------------------------------------
// Row-wise two-level int8 quantization over 2048-col rows.
// ---------------------------------------------------------------------------
struct RQArgs { const float* src; int8_t* q1; int8_t* q2; float* s; int rows; };

__device__ __forceinline__ void rowquant_body(
    const float* __restrict__ x, int8_t* __restrict__ q1,
    int8_t* __restrict__ q2, float* __restrict__ s, int row, int t,
    float* wmax)
{
    const float* xr = x + (size_t)row * 2048 + t * 8;
    float4 v0 = ((const float4*)xr)[0];
    float4 v1 = ((const float4*)xr)[1];
    float vv[8] = {v0.x, v0.y, v0.z, v0.w, v1.x, v1.y, v1.z, v1.w};
    float m = 0.f;
#pragma unroll
    for (int j = 0; j < 8; j++) m = fmaxf(m, fabsf(vv[j]));
#pragma unroll
    for (int o = 16; o; o >>= 1) m = fmaxf(m, __shfl_xor_sync(~0u, m, o));
    if ((t & 31) == 0) wmax[t >> 5] = m;
    __syncthreads();
    float mm = wmax[0];
#pragma unroll
    for (int i = 1; i < 8; i++) mm = fmaxf(mm, wmax[i]);
    mm = fmaxf(mm, 1e-20f);
    if (t == 0) s[row] = mm * (1.f / 127.f);
    const float inv = 127.f / mm;

    uint32_t p1[2] = {0, 0}, p2[2] = {0, 0};
#pragma unroll
    for (int j = 0; j < 8; j++) {
        float xs = vv[j] * inv;
        float qf = rintf(xs);
        float rf = rintf((xs - qf) * 254.f);
        int iq = (int)qf, ir = (int)rf;
        p1[j >> 2] |= (uint32_t)(iq & 0xff) << ((j & 3) * 8);
        p2[j >> 2] |= (uint32_t)(ir & 0xff) << ((j & 3) * 8);
    }
    ((uint32_t*)q1)[row * 512 + t * 2]     = p1[0];
    ((uint32_t*)q1)[row * 512 + t * 2 + 1] = p1[1];
    ((uint32_t*)q2)[row * 512 + t * 2]     = p2[0];
    ((uint32_t*)q2)[row * 512 + t * 2 + 1] = p2[1];
}

__global__ __launch_bounds__(256) void rowquant(
    const float* __restrict__ x, int8_t* __restrict__ q1,
    int8_t* __restrict__ q2, float* __restrict__ s)
{
    __shared__ float wmax[8];
    rowquant_body(x, q1, q2, s, blockIdx.x, threadIdx.x, wmax);
}

__global__ __launch_bounds__(256) void rowquant5(
    RQArgs a0, RQArgs a1, RQArgs a2, RQArgs a3, RQArgs a4)
{
    __shared__ float wmax[8];
    RQArgs a = (blockIdx.y == 0) ? a0 : (blockIdx.y == 1) ? a1
             : (blockIdx.y == 2) ? a2 : (blockIdx.y == 3) ? a3 : a4;
    if ((int)blockIdx.x >= a.rows) return;
    rowquant_body(a.src, a.q1, a.q2, a.s, blockIdx.x, threadIdx.x, wmax);
}

// ---------------------------------------------------------------------------
// Two-level int8 GEMM.
// EPI 0: fp32 C + bias.
// EPI 3: merged QKV — z<2: fused int8 quant (Q/K); z==2: fp16 C (V).
// ---------------------------------------------------------------------------
#define GK 2048
#define NCH8 32
#define SSTG 32768
#define GS8_SMEM (3 * SSTG)

struct GArgs {
    const int8_t *B1, *B2;
    const float* sB;
    const float* bias;
    float* C;
    __half* Ch;
    int8_t *Q1, *Q2;
    float* SQ;
};

__device__ __forceinline__ void s8_load(
    const int8_t* __restrict__ A1, const int8_t* __restrict__ A2,
    const int8_t* __restrict__ B1, const int8_t* __restrict__ B2,
    int m0, int n0, int k0, uint32_t sb, int t)
{
#pragma unroll
    for (int i = 0; i < 2; i++) {
        int idx = t + i * 256, r = idx >> 2, c = idx & 3;
        uint32_t so = (uint32_t)(r * 64 + (((c ^ ((r >> 1) & 3))) << 4));
        size_t ga = (size_t)(m0 + r) * GK + k0 + c * 16;
        size_t gb = (size_t)(n0 + r) * GK + k0 + c * 16;
        cp_async16(sb +          so, A1 + ga);
        cp_async16(sb +  8192u + so, A2 + ga);
        cp_async16(sb + 16384u + so, B1 + gb);
        cp_async16(sb + 24576u + so, B2 + gb);
    }
}

template<int EPI>
__global__ __launch_bounds__(256, 1) void gemm_s8(
    const int8_t* __restrict__ A1, const int8_t* __restrict__ A2,
    const float* __restrict__ sA, GArgs a0, GArgs a1, GArgs a2)
{
    extern __shared__ char smem[];
    const uint32_t sbase = smem_u32(smem);
    const GArgs ga = (blockIdx.z == 0) ? a0 : (blockIdx.z == 1) ? a1 : a2;
    const int t = threadIdx.x, lane = t & 31, wid = t >> 5;
    const int warp_m = wid >> 2, warp_n = wid & 3;
    const int m0 = blockIdx.y * 128;
    const int n0 = blockIdx.x * 128;

    int a_row[4], b_row[2];
    uint32_t a_sw[4], b_sw[2];
#pragma unroll
    for (int mt = 0; mt < 4; mt++) {
        a_row[mt] = warp_m * 64 + mt * 16 + (lane & 15);
        a_sw[mt]  = (uint32_t)((a_row[mt] >> 1) & 3);
    }
#pragma unroll
    for (int pt = 0; pt < 2; pt++) {
        b_row[pt] = warp_n * 32 + pt * 16 + (lane & 7) + ((lane >> 4) & 1) * 8;
        b_sw[pt]  = (uint32_t)((b_row[pt] >> 1) & 3);
    }
    const uint32_t a_ch = (uint32_t)(lane >> 4);
    const uint32_t b_ch = (uint32_t)((lane >> 3) & 1);

    int acc1[4][4][4], acc2[4][4][4];
#pragma unroll
    for (int i = 0; i < 4; i++)
#pragma unroll
        for (int j = 0; j < 4; j++)
#pragma unroll
            for (int q = 0; q < 4; q++) { acc1[i][j][q] = 0; acc2[i][j][q] = 0; }

    s8_load(A1, A2, ga.B1, ga.B2, m0, n0, 0,   sbase,            t); CP_COMMIT();
    s8_load(A1, A2, ga.B1, ga.B2, m0, n0, 64,  sbase + SSTG,     t); CP_COMMIT();
    s8_load(A1, A2, ga.B1, ga.B2, m0, n0, 128, sbase + 2 * SSTG, t); CP_COMMIT();

    uint32_t stg = 0;
    for (int ch = 0; ch < NCH8; ch++) {
        CP_WAIT2();
        __syncthreads();
        const uint32_t sb = sbase + stg * SSTG;

#pragma unroll
        for (int s = 0; s < 2; s++) {
            uint32_t Af1[4][4], Af2[4][4];
            uint32_t Bf1[2][4], Bf2[2][4];
#pragma unroll
            for (int mt = 0; mt < 4; mt++) {
                uint32_t c = (uint32_t)(s * 2) + a_ch;
                uint32_t off = (uint32_t)(a_row[mt] * 64) + ((c ^ a_sw[mt]) << 4);
                ldm_x4(Af1[mt], sb + off);
                ldm_x4(Af2[mt], sb + 8192u + off);
            }
#pragma unroll
            for (int pt = 0; pt < 2; pt++) {
                uint32_t c = (uint32_t)(s * 2) + b_ch;
                uint32_t off = (uint32_t)(b_row[pt] * 64) + ((c ^ b_sw[pt]) << 4);
                ldm_x4(Bf1[pt], sb + 16384u + off);
                ldm_x4(Bf2[pt], sb + 24576u + off);
            }
#pragma unroll
            for (int mt = 0; mt < 4; mt++)
#pragma unroll
                for (int nt = 0; nt < 4; nt++) {
                    const int pt = nt >> 1, hl = (nt & 1) * 2;
                    mma_s8(acc1[mt][nt], Af1[mt], Bf1[pt][hl], Bf1[pt][hl+1]);
                    mma_s8(acc2[mt][nt], Af1[mt], Bf2[pt][hl], Bf2[pt][hl+1]);
                    mma_s8(acc2[mt][nt], Af2[mt], Bf1[pt][hl], Bf1[pt][hl+1]);
                }
        }
        __syncthreads();
        if (ch + 3 < NCH8)
            s8_load(A1, A2, ga.B1, ga.B2, m0, n0, (ch + 3) * 64,
                    sbase + stg * SSTG, t);
        CP_COMMIT();
        stg = (stg == 2) ? 0 : stg + 1;
    }

    const float R = 1.f / 254.f;
    if (EPI == 0 || (EPI == 3 && blockIdx.z == 2)) {
#pragma unroll
        for (int mt = 0; mt < 4; mt++) {
            const int r0 = m0 + warp_m * 64 + mt * 16 + (lane >> 2);
            const float sa0 = sA[r0], sa1 = sA[r0 + 8];
#pragma unroll
            for (int nt = 0; nt < 4; nt++) {
                const int cc = n0 + warp_n * 32 + nt * 8 + (lane & 3) * 2;
                const float sb0 = ga.sB[cc], sb1 = ga.sB[cc + 1];
                const float bx = ga.bias[cc], by = ga.bias[cc + 1];
                float v0 = ((float)acc1[mt][nt][0] + (float)acc2[mt][nt][0] * R) * (sa0 * sb0) + bx;
                float v1 = ((float)acc1[mt][nt][1] + (float)acc2[mt][nt][1] * R) * (sa0 * sb1) + by;
                float v2 = ((float)acc1[mt][nt][2] + (float)acc2[mt][nt][2] * R) * (sa1 * sb0) + bx;
                float v3 = ((float)acc1[mt][nt][3] + (float)acc2[mt][nt][3] * R) * (sa1 * sb1) + by;
                if (EPI == 0) {
                    *(float2*)(ga.C + (size_t)r0 * GK + cc)       = make_float2(v0, v1);
                    *(float2*)(ga.C + (size_t)(r0 + 8) * GK + cc) = make_float2(v2, v3);
                } else {
                    *(uint32_t*)(ga.Ch + (size_t)r0 * GK + cc)       = packh(v0, v1);
                    *(uint32_t*)(ga.Ch + (size_t)(r0 + 8) * GK + cc) = packh(v2, v3);
                }
            }
        }
    } else {
        // fused per-(row, 64-col head) two-level int8 quantization (Q/K)
        CP_WAIT0();
        __syncthreads();
        float* red = (float*)smem;      // 8 warps x 64 rows
        const int rbase = wid * 64;
#pragma unroll
        for (int mt = 0; mt < 4; mt++) {
            const int r0g = m0 + warp_m * 64 + mt * 16 + (lane >> 2);
            const float sa0 = sA[r0g], sa1 = sA[r0g + 8];
#pragma unroll
            for (int rr = 0; rr < 2; rr++) {
                const float sa = rr ? sa1 : sa0;
                float mx = 0.f;
#pragma unroll
                for (int nt = 0; nt < 4; nt++) {
                    const int cc = n0 + warp_n * 32 + nt * 8 + (lane & 3) * 2;
                    float v0 = ((float)acc1[mt][nt][rr*2]   + (float)acc2[mt][nt][rr*2]   * R)
                               * (sa * ga.sB[cc])     + ga.bias[cc];
                    float v1 = ((float)acc1[mt][nt][rr*2+1] + (float)acc2[mt][nt][rr*2+1] * R)
                               * (sa * ga.sB[cc + 1]) + ga.bias[cc + 1];
                    mx = fmaxf(mx, fmaxf(fabsf(v0), fabsf(v1)));
                }
                mx = fmaxf(mx, __shfl_xor_sync(~0u, mx, 1));
                mx = fmaxf(mx, __shfl_xor_sync(~0u, mx, 2));
                red[rbase + mt * 16 + rr * 8 + (lane >> 2)] = mx;
            }
        }
        __syncthreads();
        const int h = (n0 >> 6) + (warp_n >> 1);
#pragma unroll
        for (int mt = 0; mt < 4; mt++) {
            const int r0g = m0 + warp_m * 64 + mt * 16 + (lane >> 2);
            const float sa0 = sA[r0g], sa1 = sA[r0g + 8];
#pragma unroll
            for (int rr = 0; rr < 2; rr++) {
                const float sa = rr ? sa1 : sa0;
                const int idx = mt * 16 + rr * 8 + (lane >> 2);
                float m2 = fmaxf(red[rbase + idx], red[(rbase ^ 64) + idx]);
                m2 = fmaxf(m2, 1e-20f);
                const int grow = r0g + rr * 8;
                if ((lane & 3) == 0)
                    ga.SQ[(size_t)h * M_ + grow] = m2 * (1.f / 127.f);
                const float inv = 127.f / m2;
#pragma unroll
                for (int nt = 0; nt < 4; nt++) {
                    const int cc = n0 + warp_n * 32 + nt * 8 + (lane & 3) * 2;
                    float v0 = ((float)acc1[mt][nt][rr*2]   + (float)acc2[mt][nt][rr*2]   * R)
                               * (sa * ga.sB[cc])     + ga.bias[cc];
                    float v1 = ((float)acc1[mt][nt][rr*2+1] + (float)acc2[mt][nt][rr*2+1] * R)
                               * (sa * ga.sB[cc + 1]) + ga.bias[cc + 1];
                    float A0 = v0 * inv, A1v = v1 * inv;
                    float f0 = rintf(A0), f1 = rintf(A1v);
                    int i0 = (int)f0, i1 = (int)f1;
                    int r0v = (int)rintf((A0 - f0) * 254.f);
                    int r1v = (int)rintf((A1v - f1) * 254.f);
                    *(uint16_t*)(ga.Q1 + (size_t)grow * 2048 + cc) =
                        (uint16_t)((i0 & 0xff) | ((i1 & 0xff) << 8));
                    *(uint16_t*)(ga.Q2 + (size_t)grow * 2048 + cc) =
                        (uint16_t)((r0v & 0xff) | ((r1v & 0xff) << 8));
                }
            }
        }
    }
}

// ---------------------------------------------------------------------------
// Hybrid flash attention (causal): int8 two-level QK, fp16 P x fp16 V PV.
// All ldmatrix smem offsets precomputed; prefetch pointers advanced
// incrementally (no per-iteration address arithmetic).
// ---------------------------------------------------------------------------
#define FQT 128
#define FKT 64
#define STG_SZ 16384u
#define SCOFF 32768u
#define FA_SMEM 33280

__global__ __launch_bounds__(256, 2) void flash_hyb(
    const int8_t* __restrict__ q1g, const int8_t* __restrict__ q2g,
    const float* __restrict__ sqg,
    const int8_t* __restrict__ k1g, const int8_t* __restrict__ k2g,
    const float* __restrict__ skg,
    const __half* __restrict__ Vh,
    float* __restrict__ O)
{
    extern __shared__ char smem[];
    const uint32_t sb = smem_u32(smem);
    const int t = threadIdx.x, lane = t & 31, wid = t >> 5;
    const int qt = (int)gridDim.x - 1 - (int)blockIdx.x;   // heavy tiles first
    const int bh = blockIdx.y;
    const int b = bh >> 5, h = bh & 31;
    const int q0 = qt * FQT;
    const int qrow0 = b * S_ + q0;
    const int krow0 = b * S_;
    const int hoff = h * D_;
    const size_t vbase = ((size_t)b * S_) * E_ + hoff;
    const float* skh = skg + (size_t)h * M_ + b * S_;
    const float CEXP = SCALE_ * 1.4426950408889634f;
    const float CR = CEXP * (1.f / 254.f);
    const uint32_t HONES = 0x3C003C00u;   // fp16 {1, 1}

    // ---- stage Q (int8, both levels): 128 rows x 64B per level = 8K each ----
#pragma unroll
    for (int i = 0; i < 2; i++) {
        int idx = t + i * 256, r = idx >> 2, c = idx & 3;
        uint32_t so = (uint32_t)(r * 64 + ((c ^ ((r >> 1) & 3)) << 4));
        size_t g = (size_t)(qrow0 + r) * 2048 + hoff + c * 16;
        cp_async16(sb +         so, q1g + g);
        cp_async16(sb + 8192u + so, q2g + g);
    }
    CP_COMMIT(); CP_WAIT0();
    __syncthreads();

    uint32_t fq1[2][4], fq2[2][4];
#pragma unroll
    for (int kc = 0; kc < 2; kc++) {
        int row = wid * 16 + (lane & 15);
        uint32_t c = (uint32_t)(kc * 2 + (lane >> 4));
        uint32_t off = (uint32_t)(row * 64) + ((c ^ (uint32_t)((row >> 1) & 3)) << 4);
        ldm_x4(fq1[kc], sb + off);
        ldm_x4(fq2[kc], sb + 8192u + off);
    }
    float sqv[2];
#pragma unroll
    for (int rr = 0; rr < 2; rr++)
        sqv[rr] = sqg[(size_t)h * M_ + qrow0 + wid * 16 + (lane >> 2) + rr * 8];
    __syncthreads();   // Q area now reusable for KV stages

    // ---- precomputed ldmatrix smem offsets (stage-relative) ----
    uint32_t koff[2][2][2];   // [kc][kh][np2]
#pragma unroll
    for (int kc = 0; kc < 2; kc++)
#pragma unroll
        for (int kh = 0; kh < 2; kh++)
#pragma unroll
            for (int np2 = 0; np2 < 2; np2++) {
                int row = (kh * 2 + np2) * 16 + (lane & 7) + ((lane >> 4) & 1) * 8;
                uint32_t c = (uint32_t)(kc * 2 + ((lane >> 3) & 1));
                koff[kc][kh][np2] = (uint32_t)(row * 64)
                                  + ((c ^ (uint32_t)((row >> 1) & 3)) << 4);
            }
    uint32_t voff[4][4];      // [kc][ndp], includes +8192 V base
#pragma unroll
    for (int kc = 0; kc < 4; kc++)
#pragma unroll
        for (int ndp = 0; ndp < 4; ndp++) {
            int row = kc * 16 + (lane & 7) + ((lane >> 3) & 1) * 8;
            uint32_t c = (uint32_t)(2 * ndp) + (uint32_t)(lane >> 4);
            voff[kc][ndp] = 8192u + (uint32_t)(row * 128)
                          + ((c ^ (uint32_t)(row & 7)) << 4);
        }

    // ---- prefetch pointers (advance incrementally) ----
    const int rk_ = t >> 2, ck_ = t & 3;
    const uint32_t so_k = (uint32_t)(rk_ * 64 + ((ck_ ^ ((rk_ >> 1) & 3)) << 4));
    const int rv0 = t >> 3, cv_ = t & 7;
    const int rv1 = (t + 256) >> 3;
    const uint32_t so_v0 = (uint32_t)(rv0 * 128 + ((cv_ ^ (rv0 & 7)) << 4));
    const uint32_t so_v1 = (uint32_t)(rv1 * 128 + ((cv_ ^ (rv1 & 7)) << 4));
    const size_t gk_base = (size_t)(krow0 + rk_) * 2048 + hoff + ck_ * 16;
    const int8_t* gk1p = k1g + gk_base + (size_t)FKT * 2048;
    const int8_t* gk2p = k2g + gk_base + (size_t)FKT * 2048;
    const __half* gv0p = Vh + vbase + (size_t)(FKT + rv0) * E_ + cv_ * 8;
    const __half* gv1p = Vh + vbase + (size_t)(FKT + rv1) * E_ + cv_ * 8;
    const float* skp = skh + FKT + t * 4;
    const int mrow_base = q0 + wid * 16 + (lane >> 2);   // causal row base

    const int jmax = 2 * (qt + 1);
    {   // KV tile 0 -> stage 0
        cp_async16(sb +         so_k, k1g + gk_base);
        cp_async16(sb + 4096u + so_k, k2g + gk_base);
        if (t < 16) cp_async16(sb + SCOFF + t * 16u, skh + t * 4);
        cp_async16(sb + 8192u + so_v0, Vh + vbase + (size_t)rv0 * E_ + cv_ * 8);
        cp_async16(sb + 8192u + so_v1, Vh + vbase + (size_t)rv1 * E_ + cv_ * 8);
    }
    CP_COMMIT();

    float Oacc[8][4];
#pragma unroll
    for (int j = 0; j < 8; j++)
#pragma unroll
        for (int q = 0; q < 4; q++) Oacc[j][q] = 0.f;
    float lacc[4] = {0.f, 0.f, 0.f, 0.f};
    float m_i[2] = {-1e30f, -1e30f};

    for (int jt = 0; jt < jmax; jt++) {
        const int k0 = jt * FKT;
        __syncthreads();
        if (jt + 1 < jmax) {
            uint32_t st = (uint32_t)((jt + 1) & 1) * STG_SZ;
            cp_async16(sb + st +         so_k, gk1p);
            cp_async16(sb + st + 4096u + so_k, gk2p);
            if (t < 16)
                cp_async16(sb + SCOFF + (uint32_t)((jt + 1) & 1) * 256u + t * 16u, skp);
            cp_async16(sb + st + 8192u + so_v0, gv0p);
            cp_async16(sb + st + 8192u + so_v1, gv1p);
        }
        gk1p += FKT * 2048; gk2p += FKT * 2048;
        gv0p += (size_t)FKT * E_; gv1p += (size_t)FKT * E_;
        skp += FKT;
        CP_COMMIT(); CP_WAIT1();
        __syncthreads();
        const uint32_t st = sb + (uint32_t)(jt & 1) * STG_SZ;
        const float* sks = (const float*)(smem + SCOFF + (jt & 1) * 256);

        // ---- S = Q K^T (int8 two-level), dequant to exponent domain ----
        float sacc[8][4];
#pragma unroll
        for (int kh = 0; kh < 2; kh++) {
            int i1[4][4], i2[4][4];
#pragma unroll
            for (int j = 0; j < 4; j++)
#pragma unroll
                for (int q = 0; q < 4; q++) { i1[j][q] = 0; i2[j][q] = 0; }
#pragma unroll
            for (int kc = 0; kc < 2; kc++) {
                uint32_t bk1[2][4], bk2[2][4];
#pragma unroll
                for (int np2 = 0; np2 < 2; np2++) {
                    const uint32_t off = koff[kc][kh][np2];
                    ldm_x4(bk1[np2], st + off);
                    ldm_x4(bk2[np2], st + 4096u + off);
                }
#pragma unroll
                for (int np2 = 0; np2 < 2; np2++)
#pragma unroll
                    for (int nt2 = 0; nt2 < 2; nt2++) {
                        const int sl = np2 * 2 + nt2, hl = nt2 * 2;
                        mma_s8(i1[sl], fq1[kc], bk1[np2][hl], bk1[np2][hl+1]);
                        mma_s8(i2[sl], fq1[kc], bk2[np2][hl], bk2[np2][hl+1]);
                        mma_s8(i2[sl], fq2[kc], bk1[np2][hl], bk1[np2][hl+1]);
                    }
            }
#pragma unroll
            for (int sl = 0; sl < 4; sl++) {
                const int nt = kh * 4 + sl;
                const int c0 = nt * 8 + (lane & 3) * 2;
                const float kc0 = sks[c0] * CR, kc1 = sks[c0 + 1] * CR;
#pragma unroll
                for (int rr = 0; rr < 2; rr++) {
                    const float t0 = kc0 * sqv[rr], t1 = kc1 * sqv[rr];
                    sacc[nt][rr*2]   = t0 * (float)(i1[sl][rr*2]   * 254 + i2[sl][rr*2]);
                    sacc[nt][rr*2+1] = t1 * (float)(i1[sl][rr*2+1] * 254 + i2[sl][rr*2+1]);
                }
            }
        }

        // ---- causal mask (exponent domain) ----
        if (k0 + FKT - 1 > q0) {
#pragma unroll
            for (int nt = 0; nt < 8; nt++)
#pragma unroll
                for (int e = 0; e < 4; e++) {
                    int qrow = mrow_base + (e >> 1) * 8;
                    int kcol = k0 + nt * 8 + (lane & 3) * 2 + (e & 1);
                    if (kcol > qrow) sacc[nt][e] = -1e30f;
                }
        }

        // ---- online max + rescale ----
        float m_new[2], alpha[2];
#pragma unroll
        for (int rr = 0; rr < 2; rr++) {
            float mx = -1e30f;
#pragma unroll
            for (int nt = 0; nt < 8; nt++)
                mx = fmaxf(mx, fmaxf(sacc[nt][rr*2], sacc[nt][rr*2+1]));
            mx = fmaxf(mx, __shfl_xor_sync(0xffffffffu, mx, 1));
            mx = fmaxf(mx, __shfl_xor_sync(0xffffffffu, mx, 2));
            m_new[rr] = fmaxf(m_i[rr], mx);
            alpha[rr] = ex2(m_i[rr] - m_new[rr]);
            m_i[rr] = m_new[rr];
#pragma unroll
            for (int nd = 0; nd < 8; nd++) {
                Oacc[nd][rr*2]   *= alpha[rr];
                Oacc[nd][rr*2+1] *= alpha[rr];
            }
        }
        lacc[0] *= alpha[0]; lacc[1] *= alpha[0];
        lacc[2] *= alpha[1]; lacc[3] *= alpha[1];

        // ---- O += P V, l += P 1 (p via f16x2 ex2) ----
#pragma unroll
        for (int kc = 0; kc < 4; kc++) {
            uint32_t ph[4];
            ph[0] = ex2h2(packh(sacc[2*kc][0]   - m_new[0], sacc[2*kc][1]   - m_new[0]));
            ph[1] = ex2h2(packh(sacc[2*kc][2]   - m_new[1], sacc[2*kc][3]   - m_new[1]));
            ph[2] = ex2h2(packh(sacc[2*kc+1][0] - m_new[0], sacc[2*kc+1][1] - m_new[0]));
            ph[3] = ex2h2(packh(sacc[2*kc+1][2] - m_new[1], sacc[2*kc+1][3] - m_new[1]));
            mma_h(lacc, ph, HONES, HONES);
#pragma unroll
            for (int ndp = 0; ndp < 4; ndp++) {
                uint32_t bvh[4];
                ldm_x4t(bvh, st + voff[kc][ndp]);
#pragma unroll
                for (int nt2 = 0; nt2 < 2; nt2++) {
                    const int nd = ndp * 2 + nt2;
                    mma_h(Oacc[nd], ph, bvh[nt2*2], bvh[nt2*2+1]);
                }
            }
        }
    }

    // ---- epilogue: normalize, fp32 store ----
#pragma unroll
    for (int rr = 0; rr < 2; rr++) {
        const int row = wid * 16 + (lane >> 2) + rr * 8;
        const float inv = 1.f / lacc[rr * 2];
        const size_t rb = (size_t)(qrow0 + row) * 2048 + hoff + (lane & 3) * 2;
#pragma unroll
        for (int nd = 0; nd < 8; nd++) {
            float v0 = Oacc[nd][rr*2]   * inv;
            float v1 = Oacc[nd][rr*2+1] * inv;
            *(float2*)(O + rb + nd * 8) = make_float2(v0, v1);
        }
    }
}

// ---------------------------------------------------------------------------
extern "C" void kernel_launch(void* const* d_in, const int* in_sizes, int n_in,
                              void* d_out, int out_size)
{
    const float* x  = (const float*)d_in[0];
    const float* Wq = (const float*)d_in[1];
    const float* bq = (const float*)d_in[2];
    const float* Wk = (const float*)d_in[3];
    const float* bk = (const float*)d_in[4];
    const float* Wv = (const float*)d_in[5];
    const float* bv = (const float*)d_in[6];
    const float* Wo = (const float*)d_in[7];
    const float* bo = (const float*)d_in[8];
    float* out = (float*)d_out;

    int8_t *x1, *x2, *a1, *a2;
    int8_t *wq1, *wq2, *wk1, *wk2, *wv1, *wv2, *wo1, *wo2;
    int8_t *q1, *q2, *k1, *k2;
    float *sx, *sa, *swq, *swk, *swv, *swo, *attn, *sq, *sk;
    __half *vh;
    cudaGetSymbolAddress((void**)&x1, g_x1);
    cudaGetSymbolAddress((void**)&x2, g_x2);
    cudaGetSymbolAddress((void**)&sx, g_sx);
    cudaGetSymbolAddress((void**)&a1, g_a1);
    cudaGetSymbolAddress((void**)&a2, g_a2);
    cudaGetSymbolAddress((void**)&sa, g_sa);
    cudaGetSymbolAddress((void**)&attn, g_attn);
    cudaGetSymbolAddress((void**)&wq1, g_wq1);
    cudaGetSymbolAddress((void**)&wq2, g_wq2);
    cudaGetSymbolAddress((void**)&swq, g_swq);
    cudaGetSymbolAddress((void**)&wk1, g_wk1);
    cudaGetSymbolAddress((void**)&wk2, g_wk2);
    cudaGetSymbolAddress((void**)&swk, g_swk);
    cudaGetSymbolAddress((void**)&wv1, g_wv1);
    cudaGetSymbolAddress((void**)&wv2, g_wv2);
    cudaGetSymbolAddress((void**)&swv, g_swv);
    cudaGetSymbolAddress((void**)&wo1, g_wo1);
    cudaGetSymbolAddress((void**)&wo2, g_wo2);
    cudaGetSymbolAddress((void**)&swo, g_swo);
    cudaGetSymbolAddress((void**)&q1, g_q1);
    cudaGetSymbolAddress((void**)&q2, g_q2);
    cudaGetSymbolAddress((void**)&k1, g_k1);
    cudaGetSymbolAddress((void**)&k2, g_k2);
    cudaGetSymbolAddress((void**)&sq, g_sq);
    cudaGetSymbolAddress((void**)&sk, g_sk);
    cudaGetSymbolAddress((void**)&vh, g_vh);

    cudaFuncSetAttribute(gemm_s8<0>,
                         cudaFuncAttributeMaxDynamicSharedMemorySize, GS8_SMEM);
    cudaFuncSetAttribute(gemm_s8<3>,
                         cudaFuncAttributeMaxDynamicSharedMemorySize, GS8_SMEM);
    cudaFuncSetAttribute(flash_hyb,
                         cudaFuncAttributeMaxDynamicSharedMemorySize, FA_SMEM);

    RQArgs rx{x,  x1,  x2,  sx,  M_};
    RQArgs rq{Wq, wq1, wq2, swq, E_};
    RQArgs rk{Wk, wk1, wk2, swk, E_};
    RQArgs rv{Wv, wv1, wv2, swv, E_};
    RQArgs ro{Wo, wo1, wo2, swo, E_};
    rowquant5<<<dim3(M_, 5), 256>>>(rx, rq, rk, rv, ro);

    GArgs aq{wq1, wq2, swq, bq, nullptr, nullptr, q1, q2, sq};
    GArgs ak{wk1, wk2, swk, bk, nullptr, nullptr, k1, k2, sk};
    GArgs av{wv1, wv2, swv, bv, nullptr, vh, nullptr, nullptr, nullptr};
    GArgs ao{wo1, wo2, swo, bo, out, nullptr, nullptr, nullptr, nullptr};

    dim3 gqkv(E_ / 128, M_ / 128, 3);
    gemm_s8<3><<<gqkv, 256, GS8_SMEM>>>(x1, x2, sx, aq, ak, av);

    dim3 ga(S_ / FQT, B_ * H_);     // (16, 64)
    flash_hyb<<<ga, 256, FA_SMEM>>>(q1, q2, sq, k1, k2, sk, vh, attn);

    rowquant<<<M_, 256>>>(attn, a1, a2, sa);

    dim3 go(E_ / 128, M_ / 128, 1);
    gemm_s8<0><<<go, 256, GS8_SMEM>>>(a1, a2, sa, ao, ao, ao);
}